// round 1
// baseline (speedup 1.0000x reference)
#include <cuda_runtime.h>

#define NT 512
constexpr int CHN = 4;
constexpr float LRATE = 0.01f;
constexpr float DYSCALE = 2.0f / 2097152.0f;   // 2 / (B * 128*128)

// ---- per-sample scratch offsets (floats) ----
constexpr int OFF_U0=0,      OFF_P0=65536,  OFF_U1=81920,  OFF_P1=98304,
              OFF_U2=102400, OFF_P2=106496, OFF_U3=107520, OFF_P3=108544,
              OFF_U4=108800, OFF_P4=109056, OFF_U5=109120, OFF_F =109184,
              OFF_ZU=109248, OFF_Z =109280, OFF_DU=109312, OFF_DD=109376,
              OFF_V0=109440, OFF_Q0=109696, OFF_V1=109952, OFF_Q1=110976,
              OFF_V2=112000, OFF_Q2=116096, OFF_V3=120192, OFF_Q3=136576,
              OFF_V4=152960, OFF_Q4=218496, OFF_DY=284032, OFF_GA=300416,
              OFF_GB=365952;
constexpr int SSC = 431488;                       // floats per sample
constexpr int IX0=0, IX1=16384, IX2=20480, IX3=21504, IX4=21760, SIDX=21824;

__device__ float          g_scratch[128ull * SSC];      // ~221 MB
__device__ unsigned char  g_idxbuf[128 * SIDX];

// ---- smem param layout (floats) ----
constexpr int PW0=0, PEB=36, PEW=60, PLEW=780, PLEB=2828, PLDW=2860, PLDB=4908,
              PDW=4972, PDB=5692, PWO=5712, PBO=5748, NPARAM=5749;

__device__ __forceinline__ float sigm(float u){ return 1.0f/(1.0f + __expf(-u)); }
__device__ __forceinline__ float swish_f(float u){ return u * sigm(u); }
__device__ __forceinline__ float swish_d(float u){ float s = sigm(u); return s + u*s*(1.0f-s); }

// ---- forward conv 3x3 SAME ----
template<int R,int CIN,int COUT>
__device__ void conv3x3(const float* __restrict__ in, const float* __restrict__ w,
                        const float* __restrict__ b, float* __restrict__ out)
{
    for (int t = threadIdx.x; t < COUT*R*R; t += NT) {
        int o = t/(R*R); int p = t - o*R*R; int y = p/R, x = p - y*R;
        float acc = b[o];
        #pragma unroll
        for (int c = 0; c < CIN; ++c) {
            const float* wb = w + (o*CIN + c)*9;
            const float* ib = in + c*R*R;
            #pragma unroll
            for (int ky = 0; ky < 3; ++ky) {
                int yy = y + ky - 1; if ((unsigned)yy >= (unsigned)R) continue;
                #pragma unroll
                for (int kx = 0; kx < 3; ++kx) {
                    int xc = x + kx - 1; if ((unsigned)xc >= (unsigned)R) continue;
                    acc += wb[ky*3+kx] * ib[yy*R + xc];
                }
            }
        }
        out[t] = acc;
    }
}

// ---- forward conv 3x3 with 2x nearest-upsample fused on the input ----
template<int R,int CIN,int COUT>
__device__ void conv3x3_up(const float* __restrict__ src, const float* __restrict__ w,
                           const float* __restrict__ b, float* __restrict__ out)
{
    constexpr int H = R/2;
    for (int t = threadIdx.x; t < COUT*R*R; t += NT) {
        int o = t/(R*R); int p = t - o*R*R; int y = p/R, x = p - y*R;
        float acc = b[o];
        #pragma unroll
        for (int c = 0; c < CIN; ++c) {
            const float* wb = w + (o*CIN + c)*9;
            const float* sb = src + c*H*H;
            #pragma unroll
            for (int ky = 0; ky < 3; ++ky) {
                int yy = y + ky - 1; if ((unsigned)yy >= (unsigned)R) continue;
                const float* row = sb + (yy>>1)*H;
                #pragma unroll
                for (int kx = 0; kx < 3; ++kx) {
                    int xc = x + kx - 1; if ((unsigned)xc >= (unsigned)R) continue;
                    acc += wb[ky*3+kx] * row[xc>>1];
                }
            }
        }
        out[t] = acc;
    }
}

// ---- maxpool 2x2 of swish(u), storing argmax ----
template<int R>
__device__ void pool_swish(const float* __restrict__ u, float* __restrict__ p,
                           unsigned char* __restrict__ idx)
{
    constexpr int Ro = R/2;
    for (int t = threadIdx.x; t < CHN*Ro*Ro; t += NT) {
        int c = t/(Ro*Ro); int q = t - c*Ro*Ro; int y = q/Ro, x = q - y*Ro;
        const float* ub = u + c*R*R + (2*y)*R + 2*x;
        float v0 = swish_f(ub[0]),   v1 = swish_f(ub[1]);
        float v2 = swish_f(ub[R]),   v3 = swish_f(ub[R+1]);
        float m = v0; int id = 0;
        if (v1 > m) { m = v1; id = 1; }
        if (v2 > m) { m = v2; id = 2; }
        if (v3 > m) { m = v3; id = 3; }
        p[t] = m; idx[t] = (unsigned char)id;
    }
}

__device__ void swish_arr(const float* __restrict__ u, float* __restrict__ q, int n)
{
    for (int t = threadIdx.x; t < n; t += NT) q[t] = swish_f(u[t]);
}

// ---- backward: input-grad of conv (optionally fused * swish'(upre)) ----
template<int R,int CIN,int COUT,bool FUSE>
__device__ void dgrad3x3(const float* __restrict__ dout, const float* __restrict__ w,
                         const float* __restrict__ upre, float* __restrict__ din)
{
    for (int t = threadIdx.x; t < CIN*R*R; t += NT) {
        int c = t/(R*R); int p = t - c*R*R; int y = p/R, x = p - y*R;
        float acc = 0.f;
        #pragma unroll
        for (int o = 0; o < COUT; ++o) {
            const float* wb = w + (o*CIN + c)*9;
            const float* db = dout + o*R*R;
            #pragma unroll
            for (int ky = 0; ky < 3; ++ky) {
                int yy = y + 1 - ky; if ((unsigned)yy >= (unsigned)R) continue;
                #pragma unroll
                for (int kx = 0; kx < 3; ++kx) {
                    int xc = x + 1 - kx; if ((unsigned)xc >= (unsigned)R) continue;
                    acc += wb[ky*3+kx] * db[yy*R + xc];
                }
            }
        }
        din[t] = FUSE ? acc * swish_d(upre[t]) : acc;
    }
}

// ---- backward: input-grad of conv_up, fused with up-backward (2x2 sum) and swish' ----
template<int R,int CIN,int COUT>
__device__ void dgrad_up_pool(const float* __restrict__ dout, const float* __restrict__ w,
                              const float* __restrict__ upre, float* __restrict__ din)
{
    constexpr int H = R/2;
    for (int t = threadIdx.x; t < CIN*H*H; t += NT) {
        int c = t/(H*H); int q = t - c*H*H; int u = q/H, v = q - u*H;
        float acc = 0.f;
        #pragma unroll
        for (int sy = 0; sy < 2; ++sy) {
            #pragma unroll
            for (int sx = 0; sx < 2; ++sx) {
                int y = 2*u + sy, x = 2*v + sx;
                #pragma unroll
                for (int o = 0; o < COUT; ++o) {
                    const float* wb = w + (o*CIN + c)*9;
                    const float* db = dout + o*R*R;
                    #pragma unroll
                    for (int ky = 0; ky < 3; ++ky) {
                        int yy = y + 1 - ky; if ((unsigned)yy >= (unsigned)R) continue;
                        #pragma unroll
                        for (int kx = 0; kx < 3; ++kx) {
                            int xc = x + 1 - kx; if ((unsigned)xc >= (unsigned)R) continue;
                            acc += wb[ky*3+kx] * db[yy*R + xc];
                        }
                    }
                }
            }
        }
        din[t] = acc * swish_d(upre[t]);
    }
}

// ---- backward: maxpool scatter fused with swish' ----
template<int R>   // R = output resolution of du; dp is at R/2
__device__ void pool_bwd(const float* __restrict__ dp, const unsigned char* __restrict__ idx,
                         const float* __restrict__ u, float* __restrict__ du)
{
    constexpr int H = R/2;
    for (int t = threadIdx.x; t < CHN*R*R; t += NT) {
        int c = t/(R*R); int q = t - c*R*R; int y = q/R, x = q - y*R;
        int cell = c*H*H + (y>>1)*H + (x>>1);
        int id = ((y&1)<<1) | (x&1);
        float g = (idx[cell] == (unsigned char)id) ? dp[cell] : 0.f;
        du[t] = g * swish_d(u[t]);
    }
}

// ---- backward: weight/bias grad of conv; updates smem params in place ----
template<int R,int CIN,int COUT,bool UP>
__device__ void wgrad3x3(const float* __restrict__ dout, const float* __restrict__ in,
                         float* wDst, float* bDst, float* sRed)
{
    constexpr int NW = COUT*CIN*9;
    constexpr int H  = R/2;
    for (int i = threadIdx.x; i < NW+COUT; i += NT) sRed[i] = 0.f;
    __syncthreads();

    const int o = threadIdx.x % COUT;
    float acc[CIN*9];
    #pragma unroll
    for (int i = 0; i < CIN*9; ++i) acc[i] = 0.f;
    float accb = 0.f;

    for (int p = threadIdx.x / COUT; p < R*R; p += NT/COUT) {
        int y = p/R, x = p - y*R;
        float g = dout[o*R*R + p];
        accb += g;
        #pragma unroll
        for (int c = 0; c < CIN; ++c) {
            const float* ib = in + (UP ? c*H*H : c*R*R);
            #pragma unroll
            for (int ky = 0; ky < 3; ++ky) {
                int yy = y + ky - 1; if ((unsigned)yy >= (unsigned)R) continue;
                #pragma unroll
                for (int kx = 0; kx < 3; ++kx) {
                    int xc = x + kx - 1; if ((unsigned)xc >= (unsigned)R) continue;
                    float v = UP ? ib[(yy>>1)*H + (xc>>1)] : ib[yy*R + xc];
                    acc[c*9 + ky*3 + kx] += g * v;
                }
            }
        }
    }
    unsigned lane = threadIdx.x & 31;
    #pragma unroll
    for (int off = 16; off >= COUT; off >>= 1) {
        #pragma unroll
        for (int i = 0; i < CIN*9; ++i) acc[i] += __shfl_xor_sync(0xffffffffu, acc[i], off);
        accb += __shfl_xor_sync(0xffffffffu, accb, off);
    }
    if (lane < (unsigned)COUT) {
        #pragma unroll
        for (int i = 0; i < CIN*9; ++i) atomicAdd(&sRed[o*CIN*9 + i], acc[i]);
        atomicAdd(&sRed[NW + o], accb);
    }
    __syncthreads();
    for (int i = threadIdx.x; i < NW; i += NT) wDst[i] -= LRATE * sRed[i];
    if (threadIdx.x < COUT) bDst[threadIdx.x] -= LRATE * sRed[NW + threadIdx.x];
}

// ---- full forward pass (used twice: shared params, then per-sample updated params) ----
__device__ __noinline__ void forward_pass(const float* __restrict__ x, const float* sP,
                                          float* S, unsigned char* I,
                                          float* __restrict__ ydst, bool makeDy)
{
    conv3x3<128,1,4>(x, sP+PW0, sP+PEB, S+OFF_U0);                         __syncthreads();
    pool_swish<128>(S+OFF_U0, S+OFF_P0, I+IX0);                            __syncthreads();
    conv3x3<64,4,4>(S+OFF_P0, sP+PEW,     sP+PEB+4,  S+OFF_U1);            __syncthreads();
    pool_swish<64>(S+OFF_U1, S+OFF_P1, I+IX1);                             __syncthreads();
    conv3x3<32,4,4>(S+OFF_P1, sP+PEW+144, sP+PEB+8,  S+OFF_U2);            __syncthreads();
    pool_swish<32>(S+OFF_U2, S+OFF_P2, I+IX2);                             __syncthreads();
    conv3x3<16,4,4>(S+OFF_P2, sP+PEW+288, sP+PEB+12, S+OFF_U3);            __syncthreads();
    pool_swish<16>(S+OFF_U3, S+OFF_P3, I+IX3);                             __syncthreads();
    conv3x3<8,4,4> (S+OFF_P3, sP+PEW+432, sP+PEB+16, S+OFF_U4);            __syncthreads();
    pool_swish<8>(S+OFF_U4, S+OFF_P4, I+IX4);                              __syncthreads();
    conv3x3<4,4,4> (S+OFF_P4, sP+PEW+576, sP+PEB+20, S+OFF_U5);            __syncthreads();
    swish_arr(S+OFF_U5, S+OFF_F, 64);                                      __syncthreads();

    if (threadIdx.x < 32) {
        float acc = sP[PLEB + threadIdx.x];
        for (int j = 0; j < 64; ++j) acc += sP[PLEW + threadIdx.x*64 + j] * S[OFF_F + j];
        S[OFF_ZU + threadIdx.x] = acc;
        S[OFF_Z  + threadIdx.x] = swish_f(acc);
    }
    __syncthreads();
    if (threadIdx.x < 64) {
        float acc = sP[PLDB + threadIdx.x];
        for (int j = 0; j < 32; ++j) acc += sP[PLDW + threadIdx.x*32 + j] * S[OFF_Z + j];
        S[OFF_DU + threadIdx.x] = acc;
        S[OFF_DD + threadIdx.x] = swish_f(acc);
    }
    __syncthreads();

    conv3x3_up<8,4,4>  (S+OFF_DD, sP+PDW,     sP+PDB,    S+OFF_V0);        __syncthreads();
    swish_arr(S+OFF_V0, S+OFF_Q0, 256);                                    __syncthreads();
    conv3x3_up<16,4,4> (S+OFF_Q0, sP+PDW+144, sP+PDB+4,  S+OFF_V1);        __syncthreads();
    swish_arr(S+OFF_V1, S+OFF_Q1, 1024);                                   __syncthreads();
    conv3x3_up<32,4,4> (S+OFF_Q1, sP+PDW+288, sP+PDB+8,  S+OFF_V2);        __syncthreads();
    swish_arr(S+OFF_V2, S+OFF_Q2, 4096);                                   __syncthreads();
    conv3x3_up<64,4,4> (S+OFF_Q2, sP+PDW+432, sP+PDB+12, S+OFF_V3);        __syncthreads();
    swish_arr(S+OFF_V3, S+OFF_Q3, 16384);                                  __syncthreads();
    conv3x3_up<128,4,4>(S+OFF_Q3, sP+PDW+576, sP+PDB+16, S+OFF_V4);        __syncthreads();
    swish_arr(S+OFF_V4, S+OFF_Q4, 65536);                                  __syncthreads();

    // final 4->1 conv, optionally producing dy = scale*(y - x)
    {
        const float* w = sP + PWO;
        float b0 = sP[PBO];
        for (int t = threadIdx.x; t < 16384; t += NT) {
            int y = t >> 7, xx = t & 127;
            float acc = b0;
            #pragma unroll
            for (int c = 0; c < 4; ++c) {
                const float* wb = w + c*9;
                const float* ib = S + OFF_Q4 + c*16384;
                #pragma unroll
                for (int ky = 0; ky < 3; ++ky) {
                    int yy = y + ky - 1; if ((unsigned)yy >= 128u) continue;
                    #pragma unroll
                    for (int kx = 0; kx < 3; ++kx) {
                        int xc = xx + kx - 1; if ((unsigned)xc >= 128u) continue;
                        acc += wb[ky*3+kx] * ib[yy*128 + xc];
                    }
                }
            }
            if (makeDy) ydst[t] = (acc - x[t]) * DYSCALE;
            else        ydst[t] = acc;
        }
    }
    __syncthreads();
}

__global__ __launch_bounds__(NT)
void maml_kernel(const float* __restrict__ x_all,
                 const float* __restrict__ enc_w0,   const float* __restrict__ enc_w,
                 const float* __restrict__ enc_b,    const float* __restrict__ enc_lin_w,
                 const float* __restrict__ enc_lin_b,const float* __restrict__ dec_lin_w,
                 const float* __restrict__ dec_lin_b,const float* __restrict__ dec_w,
                 const float* __restrict__ dec_b,    const float* __restrict__ dec_w_out,
                 const float* __restrict__ dec_b_out,float* __restrict__ out)
{
    __shared__ float sP[NPARAM];
    __shared__ float sRed[160];
    const int s = blockIdx.x;
    float* S = g_scratch + (size_t)s * SSC;
    unsigned char* I = g_idxbuf + s * SIDX;
    const float* x = x_all + (size_t)s * 16384;

    // load shared params into smem
    for (int i = threadIdx.x; i < 36;   i += NT) sP[PW0 +i] = enc_w0[i];
    for (int i = threadIdx.x; i < 24;   i += NT) sP[PEB +i] = enc_b[i];
    for (int i = threadIdx.x; i < 720;  i += NT) sP[PEW +i] = enc_w[i];
    for (int i = threadIdx.x; i < 2048; i += NT) sP[PLEW+i] = enc_lin_w[i];
    for (int i = threadIdx.x; i < 32;   i += NT) sP[PLEB+i] = enc_lin_b[i];
    for (int i = threadIdx.x; i < 2048; i += NT) sP[PLDW+i] = dec_lin_w[i];
    for (int i = threadIdx.x; i < 64;   i += NT) sP[PLDB+i] = dec_lin_b[i];
    for (int i = threadIdx.x; i < 720;  i += NT) sP[PDW +i] = dec_w[i];
    for (int i = threadIdx.x; i < 20;   i += NT) sP[PDB +i] = dec_b[i];
    for (int i = threadIdx.x; i < 36;   i += NT) sP[PWO +i] = dec_w_out[i];
    if (threadIdx.x == 0) sP[PBO] = dec_b_out[0];
    __syncthreads();

    // ===== forward #1 (shared params), producing dy in scratch =====
    forward_pass(x, sP, S, I, S + OFF_DY, true);

    // ===== backward, updating smem params in place =====
    float* GA = S + OFF_GA;
    float* GB = S + OFF_GB;

    // final conv
    dgrad3x3<128,4,1,true>(S+OFF_DY, sP+PWO, S+OFF_V4, GA);                 __syncthreads();
    wgrad3x3<128,4,1,false>(S+OFF_DY, S+OFF_Q4, sP+PWO, sP+PBO, sRed);      __syncthreads();
    // decoder j=4..0
    dgrad_up_pool<128,4,4>(GA, sP+PDW+576, S+OFF_V3, GB);                   __syncthreads();
    wgrad3x3<128,4,4,true>(GA, S+OFF_Q3, sP+PDW+576, sP+PDB+16, sRed);      __syncthreads();
    dgrad_up_pool<64,4,4>(GB, sP+PDW+432, S+OFF_V2, GA);                    __syncthreads();
    wgrad3x3<64,4,4,true>(GB, S+OFF_Q2, sP+PDW+432, sP+PDB+12, sRed);       __syncthreads();
    dgrad_up_pool<32,4,4>(GA, sP+PDW+288, S+OFF_V1, GB);                    __syncthreads();
    wgrad3x3<32,4,4,true>(GA, S+OFF_Q1, sP+PDW+288, sP+PDB+8, sRed);        __syncthreads();
    dgrad_up_pool<16,4,4>(GB, sP+PDW+144, S+OFF_V0, GA);                    __syncthreads();
    wgrad3x3<16,4,4,true>(GB, S+OFF_Q0, sP+PDW+144, sP+PDB+4, sRed);        __syncthreads();
    dgrad_up_pool<8,4,4>(GA, sP+PDW, S+OFF_DU, GB);                         __syncthreads();  // GB = ddu[64]
    wgrad3x3<8,4,4,true>(GA, S+OFF_DD, sP+PDW, sP+PDB, sRed);               __syncthreads();

    // dec_lin backward (ddu in GB)
    if (threadIdx.x < 32) {
        float acc = 0.f;
        for (int i = 0; i < 64; ++i) acc += sP[PLDW + i*32 + threadIdx.x] * GB[i];
        GA[threadIdx.x] = acc;                       // dz
    }
    __syncthreads();
    for (int t = threadIdx.x; t < 2048; t += NT) {
        int i = t >> 5, j = t & 31;
        sP[PLDW + t] -= LRATE * GB[i] * S[OFF_Z + j];
    }
    if (threadIdx.x < 64) sP[PLDB + threadIdx.x] -= LRATE * GB[threadIdx.x];
    __syncthreads();
    if (threadIdx.x < 32) GB[threadIdx.x] = GA[threadIdx.x] * swish_d(S[OFF_ZU + threadIdx.x]); // dzu
    __syncthreads();
    if (threadIdx.x < 64) {
        float acc = 0.f;
        for (int i = 0; i < 32; ++i) acc += sP[PLEW + i*64 + threadIdx.x] * GB[i];
        GA[threadIdx.x] = acc;                       // df
    }
    __syncthreads();
    for (int t = threadIdx.x; t < 2048; t += NT) {
        int i = t >> 6, j = t & 63;
        sP[PLEW + t] -= LRATE * GB[i] * S[OFF_F + j];
    }
    if (threadIdx.x < 32) sP[PLEB + threadIdx.x] -= LRATE * GB[threadIdx.x];
    __syncthreads();
    if (threadIdx.x < 64) GB[threadIdx.x] = GA[threadIdx.x] * swish_d(S[OFF_U5 + threadIdx.x]); // du5
    __syncthreads();

    // encoder k=5..1
    dgrad3x3<4,4,4,false>(GB, sP+PEW+576, nullptr, GA);                     __syncthreads();
    wgrad3x3<4,4,4,false>(GB, S+OFF_P4, sP+PEW+576, sP+PEB+20, sRed);       __syncthreads();
    pool_bwd<8>(GA, I+IX4, S+OFF_U4, GB);                                   __syncthreads();
    dgrad3x3<8,4,4,false>(GB, sP+PEW+432, nullptr, GA);                     __syncthreads();
    wgrad3x3<8,4,4,false>(GB, S+OFF_P3, sP+PEW+432, sP+PEB+16, sRed);       __syncthreads();
    pool_bwd<16>(GA, I+IX3, S+OFF_U3, GB);                                  __syncthreads();
    dgrad3x3<16,4,4,false>(GB, sP+PEW+288, nullptr, GA);                    __syncthreads();
    wgrad3x3<16,4,4,false>(GB, S+OFF_P2, sP+PEW+288, sP+PEB+12, sRed);      __syncthreads();
    pool_bwd<32>(GA, I+IX2, S+OFF_U2, GB);                                  __syncthreads();
    dgrad3x3<32,4,4,false>(GB, sP+PEW+144, nullptr, GA);                    __syncthreads();
    wgrad3x3<32,4,4,false>(GB, S+OFF_P1, sP+PEW+144, sP+PEB+8, sRed);       __syncthreads();
    pool_bwd<64>(GA, I+IX1, S+OFF_U1, GB);                                  __syncthreads();
    dgrad3x3<64,4,4,false>(GB, sP+PEW, nullptr, GA);                        __syncthreads();
    wgrad3x3<64,4,4,false>(GB, S+OFF_P0, sP+PEW, sP+PEB+4, sRed);           __syncthreads();
    pool_bwd<128>(GA, I+IX0, S+OFF_U0, GB);                                 __syncthreads();
    // k=0 (input conv): only wgrad needed
    wgrad3x3<128,1,4,false>(GB, x, sP+PW0, sP+PEB, sRed);                   __syncthreads();

    // ===== forward #2 with updated per-sample params, write final output =====
    forward_pass(x, sP, S, I, out + (size_t)s * 16384, false);
}

extern "C" void kernel_launch(void* const* d_in, const int* in_sizes, int n_in,
                              void* d_out, int out_size)
{
    (void)in_sizes; (void)n_in; (void)out_size;
    maml_kernel<<<128, NT>>>(
        (const float*)d_in[0],  (const float*)d_in[1],  (const float*)d_in[2],
        (const float*)d_in[3],  (const float*)d_in[4],  (const float*)d_in[5],
        (const float*)d_in[6],  (const float*)d_in[7],  (const float*)d_in[8],
        (const float*)d_in[9],  (const float*)d_in[10], (const float*)d_in[11],
        (float*)d_out);
}

// round 2
// speedup vs baseline: 1.3755x; 1.3755x over previous
#include <cuda_runtime.h>

#define NT 512
constexpr float LRATE = 0.01f;
constexpr float DYSCALE = 2.0f / 2097152.0f;   // 2 / (B * 128*128)

// ---- per-sample scratch offsets (floats) ----
constexpr int OFF_U0=0,      OFF_P0=65536,  OFF_U1=81920,  OFF_P1=98304,
              OFF_U2=102400, OFF_P2=106496, OFF_U3=107520, OFF_P3=108544,
              OFF_U4=108800, OFF_P4=109056, OFF_U5=109120, OFF_F =109184,
              OFF_ZU=109248, OFF_Z =109280, OFF_DU=109312, OFF_DD=109376,
              OFF_V0=109440, OFF_Q0=109696, OFF_V1=109952, OFF_Q1=110976,
              OFF_V2=112000, OFF_Q2=116096, OFF_V3=120192, OFF_Q3=136576,
              OFF_V4=152960, OFF_Q4=218496, OFF_DY=284032, OFF_GA=300416,
              OFF_GB=365952;
constexpr int SSC = 431488;                       // floats per sample
constexpr int IX0=0, IX1=16384, IX2=20480, IX3=21504, IX4=21760, SIDX=21824;

__device__ float          g_scratch[128ull * SSC];      // ~221 MB
__device__ unsigned char  g_idxbuf[128 * SIDX];

// ---- smem param layout (floats) ----
constexpr int PW0=0, PEB=36, PEW=60, PLEW=780, PLEB=2828, PLDW=2860, PLDB=4908,
              PDW=4972, PDB=5692, PWO=5712, PBO=5748, NPARAM=5749;

__device__ __forceinline__ float sigm(float u){ return 1.0f/(1.0f + __expf(-u)); }
__device__ __forceinline__ float swish_f(float u){ return u * sigm(u); }
__device__ __forceinline__ float swish_d(float u){ float s = sigm(u); return s + u*s*(1.0f-s); }

// ============================================================================
// Forward conv 3x3 SAME, row-per-thread, 4-wide vectorized.
// UPIN: input is at half resolution, nearest-upsampled 2x (weights parity-folded).
// MODE 0: write pre only. 1: write pre + swish(pre). 2: write (pre - xref)*DYSCALE.
// ============================================================================
template<int R,int CIN,int COUT,bool UPIN,int MODE>
__device__ __noinline__ void convfwd(const float* __restrict__ in, const float* __restrict__ w,
                                     const float* __restrict__ b, float* __restrict__ outPre,
                                     float* __restrict__ outAct, const float* __restrict__ xref)
{
    constexpr int NX = R/4, H = R/2, ROWS = COUT*R, TPR = NT/ROWS;
    const int tid  = threadIdx.x;
    const int r    = tid / TPR;
    const int lane = tid - r*TPR;
    const int o = r / R, y = r - o*R;
    const float bb = b[o];

    if constexpr (!UPIN) {
        float wr[CIN*9];
        #pragma unroll
        for (int i = 0; i < CIN*9; ++i) wr[i] = w[o*CIN*9 + i];
        const float* rp[3]; bool rv[3];
        #pragma unroll
        for (int ky = 0; ky < 3; ++ky) {
            int yy = y + ky - 1;
            rv[ky] = ((unsigned)yy < (unsigned)R);
            rp[ky] = in + yy*R;
        }
        for (int xv = lane; xv < NX; xv += TPR) {
            int x0 = xv*4;
            float a0=bb,a1=bb,a2=bb,a3=bb;
            #pragma unroll
            for (int c = 0; c < CIN; ++c) {
                #pragma unroll
                for (int ky = 0; ky < 3; ++ky) {
                    if (!rv[ky]) continue;
                    const float* row = rp[ky] + c*R*R;
                    float4 v = *reinterpret_cast<const float4*>(row + x0);
                    float m1 = (x0 > 0)     ? row[x0-1] : 0.f;
                    float p4 = (x0+4 < R)   ? row[x0+4] : 0.f;
                    float w0=wr[c*9+ky*3], w1=wr[c*9+ky*3+1], w2=wr[c*9+ky*3+2];
                    a0 += w0*m1  + w1*v.x + w2*v.y;
                    a1 += w0*v.x + w1*v.y + w2*v.z;
                    a2 += w0*v.y + w1*v.z + w2*v.w;
                    a3 += w0*v.z + w1*v.w + w2*p4;
                }
            }
            int base = o*R*R + y*R + x0;
            if constexpr (MODE == 2) {
                float4 xr = *reinterpret_cast<const float4*>(xref + y*R + x0);
                *reinterpret_cast<float4*>(outPre + base) =
                    make_float4((a0-xr.x)*DYSCALE,(a1-xr.y)*DYSCALE,(a2-xr.z)*DYSCALE,(a3-xr.w)*DYSCALE);
            } else {
                *reinterpret_cast<float4*>(outPre + base) = make_float4(a0,a1,a2,a3);
                if constexpr (MODE == 1)
                    *reinterpret_cast<float4*>(outAct + base) =
                        make_float4(swish_f(a0),swish_f(a1),swish_f(a2),swish_f(a3));
            }
        }
    } else {
        // Upsampled input: 2 src rows per output row, folded weights (u0,u2,u01,u12).
        const bool parity = (y & 1);
        int ra, rb; bool va, vb;
        if (!parity) { ra = (y>>1)-1; va = (y>0);   rb = y>>1;     vb = true; }
        else         { ra = y>>1;     va = true;    rb = (y>>1)+1; vb = (y < R-1); }
        float fu[CIN][8];
        #pragma unroll
        for (int c = 0; c < CIN; ++c) {
            const float* wb = w + (o*CIN + c)*9;
            float A0,A1,A2,B0,B1,B2;
            if (!parity) { A0=wb[0];A1=wb[1];A2=wb[2]; B0=wb[3]+wb[6];B1=wb[4]+wb[7];B2=wb[5]+wb[8]; }
            else         { A0=wb[0]+wb[3];A1=wb[1]+wb[4];A2=wb[2]+wb[5]; B0=wb[6];B1=wb[7];B2=wb[8]; }
            fu[c][0]=A0; fu[c][1]=A2; fu[c][2]=A0+A1; fu[c][3]=A1+A2;
            fu[c][4]=B0; fu[c][5]=B2; fu[c][6]=B0+B1; fu[c][7]=B1+B2;
        }
        for (int xv = lane; xv < NX; xv += TPR) {
            int x0 = xv*4, hx = x0>>1;
            float a0=bb,a1=bb,a2=bb,a3=bb;
            #pragma unroll
            for (int c = 0; c < CIN; ++c) {
                const float* sb = in + c*H*H;
                #pragma unroll
                for (int rr = 0; rr < 2; ++rr) {
                    bool vld = rr ? vb : va;
                    if (!vld) continue;
                    const float* srow = sb + (rr ? rb : ra)*H;
                    float2 s01 = *reinterpret_cast<const float2*>(srow + hx);
                    float sm = (x0 > 0)   ? srow[hx-1] : 0.f;
                    float s2 = (x0+4 < R) ? srow[hx+2] : 0.f;
                    float u0=fu[c][rr*4+0], u2=fu[c][rr*4+1], u01=fu[c][rr*4+2], u12=fu[c][rr*4+3];
                    a0 += u0*sm    + u12*s01.x;
                    a1 += u01*s01.x + u2*s01.y;
                    a2 += u0*s01.x + u12*s01.y;
                    a3 += u01*s01.y + u2*s2;
                }
            }
            int base = o*R*R + y*R + x0;
            *reinterpret_cast<float4*>(outPre + base) = make_float4(a0,a1,a2,a3);
            *reinterpret_cast<float4*>(outAct + base) =
                make_float4(swish_f(a0),swish_f(a1),swish_f(a2),swish_f(a3));
        }
    }
}

// ============================================================================
// Backward input-grad of plain conv (flipped kernel), row-per-thread, x4 vec.
// FUSE: multiply by swish'(upre).
// ============================================================================
template<int R,int CIN,int COUT,bool FUSE>
__device__ __noinline__ void dgradv(const float* __restrict__ dout, const float* __restrict__ w,
                                    const float* __restrict__ upre, float* __restrict__ din)
{
    constexpr int NX = R/4, ROWS = CIN*R, TPR = NT/ROWS;
    const int tid = threadIdx.x;
    const int r = tid / TPR, lane = tid - r*TPR;
    const int c = r / R, y = r - c*R;
    float wf[COUT*9];
    #pragma unroll
    for (int o = 0; o < COUT; ++o)
        #pragma unroll
        for (int k = 0; k < 9; ++k) wf[o*9+k] = w[(o*CIN + c)*9 + 8 - k];
    const float* rp[3]; bool rv[3];
    #pragma unroll
    for (int ky = 0; ky < 3; ++ky) {
        int yy = y + ky - 1;
        rv[ky] = ((unsigned)yy < (unsigned)R);
        rp[ky] = dout + yy*R;
    }
    for (int xv = lane; xv < NX; xv += TPR) {
        int x0 = xv*4;
        float a0=0,a1=0,a2=0,a3=0;
        #pragma unroll
        for (int o = 0; o < COUT; ++o) {
            #pragma unroll
            for (int ky = 0; ky < 3; ++ky) {
                if (!rv[ky]) continue;
                const float* row = rp[ky] + o*R*R;
                float4 v = *reinterpret_cast<const float4*>(row + x0);
                float m1 = (x0 > 0)   ? row[x0-1] : 0.f;
                float p4 = (x0+4 < R) ? row[x0+4] : 0.f;
                float w0=wf[o*9+ky*3], w1=wf[o*9+ky*3+1], w2=wf[o*9+ky*3+2];
                a0 += w0*m1  + w1*v.x + w2*v.y;
                a1 += w0*v.x + w1*v.y + w2*v.z;
                a2 += w0*v.y + w1*v.z + w2*v.w;
                a3 += w0*v.z + w1*v.w + w2*p4;
            }
        }
        int base = c*R*R + y*R + x0;
        if constexpr (FUSE) {
            float4 u4 = *reinterpret_cast<const float4*>(upre + base);
            a0 *= swish_d(u4.x); a1 *= swish_d(u4.y); a2 *= swish_d(u4.z); a3 *= swish_d(u4.w);
        }
        *reinterpret_cast<float4*>(din + base) = make_float4(a0,a1,a2,a3);
    }
}

// ============================================================================
// Backward of (upsample -> conv): din at H-res via effective 4x4 kernel
// wE = flip(w) convolved with 2x2 box; fused swish'(upre). Row-per-thread, x4.
// ============================================================================
template<int R,int CIN,int COUT>
__device__ __noinline__ void dupv(const float* __restrict__ dout, const float* __restrict__ w,
                                  const float* __restrict__ upre, float* __restrict__ din)
{
    constexpr int H = R/2, NXH = H/4, ROWS = CIN*H, TPR = NT/ROWS;
    const int tid = threadIdx.x;
    const int r = tid / TPR, lane = tid - r*TPR;
    const int c = r / H, u = r - c*H;
    float wE[COUT*16];
    #pragma unroll
    for (int o = 0; o < COUT; ++o) {
        const float* wb = w + (o*CIN + c)*9;
        #pragma unroll
        for (int i = 0; i < 4; ++i)
            #pragma unroll
            for (int j = 0; j < 4; ++j) {
                float s = 0.f;
                #pragma unroll
                for (int sy = 0; sy < 2; ++sy) {
                    int a = sy + 2 - i; if (a < 0 || a > 2) continue;
                    #pragma unroll
                    for (int sx = 0; sx < 2; ++sx) {
                        int bcol = sx + 2 - j; if (bcol < 0 || bcol > 2) continue;
                        s += wb[a*3 + bcol];
                    }
                }
                wE[o*16 + i*4 + j] = s;
            }
    }
    const int r0 = 2*u - 1;
    bool rvld[4];
    #pragma unroll
    for (int i = 0; i < 4; ++i) rvld[i] = ((unsigned)(r0+i) < (unsigned)R);
    for (int xv = lane; xv < NXH; xv += TPR) {
        int v0 = xv*4;
        float a0=0,a1=0,a2=0,a3=0;
        #pragma unroll
        for (int o = 0; o < COUT; ++o) {
            const float* db = dout + o*R*R;
            #pragma unroll
            for (int i = 0; i < 4; ++i) {
                if (!rvld[i]) continue;
                const float* row = db + (r0+i)*R;
                float4 q0 = *reinterpret_cast<const float4*>(row + 2*v0);
                float4 q1 = *reinterpret_cast<const float4*>(row + 2*v0 + 4);
                float d0 = (v0 > 0)      ? row[2*v0-1] : 0.f;
                float d9 = (2*v0+8 < R)  ? row[2*v0+8] : 0.f;
                float e0=wE[o*16+i*4], e1=wE[o*16+i*4+1], e2=wE[o*16+i*4+2], e3=wE[o*16+i*4+3];
                a0 += e0*d0   + e1*q0.x + e2*q0.y + e3*q0.z;
                a1 += e0*q0.y + e1*q0.z + e2*q0.w + e3*q1.x;
                a2 += e0*q0.w + e1*q1.x + e2*q1.y + e3*q1.z;
                a3 += e0*q1.y + e1*q1.z + e2*q1.w + e3*d9;
            }
        }
        int base = c*H*H + u*H + v0;
        float4 u4 = *reinterpret_cast<const float4*>(upre + base);
        *reinterpret_cast<float4*>(din + base) =
            make_float4(a0*swish_d(u4.x), a1*swish_d(u4.y), a2*swish_d(u4.z), a3*swish_d(u4.w));
    }
}

// ============================================================================
// maxpool 2x2 of swish(u), x4 vectorized, argmax as bytes
// ============================================================================
template<int R>
__device__ void pool_swishv(const float* __restrict__ u, float* __restrict__ p,
                            unsigned char* __restrict__ idx)
{
    constexpr int Ro = R/2, NXo = Ro/4;
    for (int t = threadIdx.x; t < 4*Ro*NXo; t += NT) {
        int cy = t / NXo; int xv = t - cy*NXo;
        int c = cy / Ro, y = cy - c*Ro;
        int x0 = xv*4;
        const float* r0 = u + c*R*R + (2*y)*R + 2*x0;
        const float* r1 = r0 + R;
        float4 A0 = *reinterpret_cast<const float4*>(r0);
        float4 A1 = *reinterpret_cast<const float4*>(r0+4);
        float4 B0 = *reinterpret_cast<const float4*>(r1);
        float4 B1 = *reinterpret_cast<const float4*>(r1+4);
        float av[8] = {A0.x,A0.y,A0.z,A0.w,A1.x,A1.y,A1.z,A1.w};
        float bv[8] = {B0.x,B0.y,B0.z,B0.w,B1.x,B1.y,B1.z,B1.w};
        float pm[4]; unsigned char im[4];
        #pragma unroll
        for (int i = 0; i < 4; ++i) {
            float v0 = swish_f(av[2*i]),   v1 = swish_f(av[2*i+1]);
            float v2 = swish_f(bv[2*i]),   v3 = swish_f(bv[2*i+1]);
            float m = v0; int id = 0;
            if (v1 > m) { m = v1; id = 1; }
            if (v2 > m) { m = v2; id = 2; }
            if (v3 > m) { m = v3; id = 3; }
            pm[i] = m; im[i] = (unsigned char)id;
        }
        int ob = c*Ro*Ro + y*Ro + x0;
        *reinterpret_cast<float4*>(p + ob) = make_float4(pm[0],pm[1],pm[2],pm[3]);
        *reinterpret_cast<uchar4*>(idx + ob) = make_uchar4(im[0],im[1],im[2],im[3]);
    }
}

// ---- maxpool backward scatter fused with swish', x4 vectorized ----
template<int R>
__device__ void pool_bwdv(const float* __restrict__ dp, const unsigned char* __restrict__ idx,
                          const float* __restrict__ u, float* __restrict__ du)
{
    constexpr int H = R/2, NX = R/4;
    for (int t = threadIdx.x; t < 4*R*NX; t += NT) {
        int ry = t / NX; int xv = t - ry*NX;
        int c = ry / R, y = ry - c*R;
        int x0 = xv*4, hx = x0>>1;
        int cellb = c*H*H + (y>>1)*H + hx;
        float2 d2 = *reinterpret_cast<const float2*>(dp + cellb);
        unsigned char i0 = idx[cellb], i1 = idx[cellb+1];
        int idb = (y & 1) << 1;
        float4 u4 = *reinterpret_cast<const float4*>(u + c*R*R + y*R + x0);
        float g0 = (i0 == (unsigned char)(idb))   ? d2.x : 0.f;
        float g1 = (i0 == (unsigned char)(idb+1)) ? d2.x : 0.f;
        float g2 = (i1 == (unsigned char)(idb))   ? d2.y : 0.f;
        float g3 = (i1 == (unsigned char)(idb+1)) ? d2.y : 0.f;
        *reinterpret_cast<float4*>(du + c*R*R + y*R + x0) =
            make_float4(g0*swish_d(u4.x), g1*swish_d(u4.y), g2*swish_d(u4.z), g3*swish_d(u4.w));
    }
}

// ============================================================================
// Weight/bias grad, x4 vectorized pixel loop, warp shfl reduce, smem atomics;
// updates smem params in place.
// ============================================================================
template<int R,int CIN,int COUT,bool UP>
__device__ __noinline__ void wgradv(const float* __restrict__ dout, const float* __restrict__ in,
                                    float* wDst, float* bDst, float* sRed)
{
    constexpr int NW = COUT*CIN*9, H = R/2, NX = R/4;
    for (int i = threadIdx.x; i < NW+COUT; i += NT) sRed[i] = 0.f;
    __syncthreads();

    const int o = threadIdx.x % COUT;
    float acc[CIN*9];
    #pragma unroll
    for (int i = 0; i < CIN*9; ++i) acc[i] = 0.f;
    float accb = 0.f;

    for (int pv = threadIdx.x / COUT; pv < R*NX; pv += NT/COUT) {
        int y = pv / NX; int x0 = (pv - y*NX)*4;
        float4 g = *reinterpret_cast<const float4*>(dout + o*R*R + y*R + x0);
        accb += g.x + g.y + g.z + g.w;
        float g01 = g.x + g.y, g12 = g.y + g.z, g23 = g.z + g.w;
        #pragma unroll
        for (int ky = 0; ky < 3; ++ky) {
            int yy = y + ky - 1;
            if ((unsigned)yy >= (unsigned)R) continue;
            #pragma unroll
            for (int c = 0; c < CIN; ++c) {
                if constexpr (UP) {
                    const float* srow = in + c*H*H + (yy>>1)*H;
                    int hx = x0>>1;
                    float2 s01 = *reinterpret_cast<const float2*>(srow + hx);
                    float sm = (x0 > 0)   ? srow[hx-1] : 0.f;
                    float s2 = (x0+4 < R) ? srow[hx+2] : 0.f;
                    acc[c*9+ky*3+0] += g.x*sm    + g12*s01.x + g.w*s01.y;
                    acc[c*9+ky*3+1] += g01*s01.x + g23*s01.y;
                    acc[c*9+ky*3+2] += g.x*s01.x + g12*s01.y + g.w*s2;
                } else {
                    const float* row = in + c*R*R + yy*R;
                    float4 v = *reinterpret_cast<const float4*>(row + x0);
                    float m1 = (x0 > 0)   ? row[x0-1] : 0.f;
                    float p4 = (x0+4 < R) ? row[x0+4] : 0.f;
                    acc[c*9+ky*3+0] += g.x*m1  + g.y*v.x + g.z*v.y + g.w*v.z;
                    acc[c*9+ky*3+1] += g.x*v.x + g.y*v.y + g.z*v.z + g.w*v.w;
                    acc[c*9+ky*3+2] += g.x*v.y + g.y*v.z + g.z*v.w + g.w*p4;
                }
            }
        }
    }
    unsigned lane = threadIdx.x & 31;
    #pragma unroll
    for (int off = 16; off >= COUT; off >>= 1) {
        #pragma unroll
        for (int i = 0; i < CIN*9; ++i) acc[i] += __shfl_xor_sync(0xffffffffu, acc[i], off);
        accb += __shfl_xor_sync(0xffffffffu, accb, off);
    }
    if (lane < (unsigned)COUT) {
        #pragma unroll
        for (int i = 0; i < CIN*9; ++i) atomicAdd(&sRed[o*CIN*9 + i], acc[i]);
        atomicAdd(&sRed[NW + o], accb);
    }
    __syncthreads();
    for (int i = threadIdx.x; i < NW; i += NT) wDst[i] -= LRATE * sRed[i];
    if (threadIdx.x < COUT) bDst[threadIdx.x] -= LRATE * sRed[NW + threadIdx.x];
}

// ---- full forward pass ----
__device__ __noinline__ void forward_pass(const float* __restrict__ x, const float* sP,
                                          float* S, unsigned char* I,
                                          float* __restrict__ ydst, bool makeDy)
{
    convfwd<128,1,4,false,0>(x, sP+PW0, sP+PEB, S+OFF_U0, nullptr, nullptr);        __syncthreads();
    pool_swishv<128>(S+OFF_U0, S+OFF_P0, I+IX0);                                    __syncthreads();
    convfwd<64,4,4,false,0>(S+OFF_P0, sP+PEW,     sP+PEB+4,  S+OFF_U1, nullptr, nullptr); __syncthreads();
    pool_swishv<64>(S+OFF_U1, S+OFF_P1, I+IX1);                                     __syncthreads();
    convfwd<32,4,4,false,0>(S+OFF_P1, sP+PEW+144, sP+PEB+8,  S+OFF_U2, nullptr, nullptr); __syncthreads();
    pool_swishv<32>(S+OFF_U2, S+OFF_P2, I+IX2);                                     __syncthreads();
    convfwd<16,4,4,false,0>(S+OFF_P2, sP+PEW+288, sP+PEB+12, S+OFF_U3, nullptr, nullptr); __syncthreads();
    pool_swishv<16>(S+OFF_U3, S+OFF_P3, I+IX3);                                     __syncthreads();
    convfwd<8,4,4,false,0> (S+OFF_P3, sP+PEW+432, sP+PEB+16, S+OFF_U4, nullptr, nullptr); __syncthreads();
    pool_swishv<8>(S+OFF_U4, S+OFF_P4, I+IX4);                                      __syncthreads();
    convfwd<4,4,4,false,1> (S+OFF_P4, sP+PEW+576, sP+PEB+20, S+OFF_U5, S+OFF_F, nullptr); __syncthreads();

    if (threadIdx.x < 32) {
        float acc = sP[PLEB + threadIdx.x];
        for (int j = 0; j < 64; ++j) acc += sP[PLEW + threadIdx.x*64 + j] * S[OFF_F + j];
        S[OFF_ZU + threadIdx.x] = acc;
        S[OFF_Z  + threadIdx.x] = swish_f(acc);
    }
    __syncthreads();
    if (threadIdx.x < 64) {
        float acc = sP[PLDB + threadIdx.x];
        for (int j = 0; j < 32; ++j) acc += sP[PLDW + threadIdx.x*32 + j] * S[OFF_Z + j];
        S[OFF_DU + threadIdx.x] = acc;
        S[OFF_DD + threadIdx.x] = swish_f(acc);
    }
    __syncthreads();

    convfwd<8,4,4,true,1>  (S+OFF_DD, sP+PDW,     sP+PDB,    S+OFF_V0, S+OFF_Q0, nullptr); __syncthreads();
    convfwd<16,4,4,true,1> (S+OFF_Q0, sP+PDW+144, sP+PDB+4,  S+OFF_V1, S+OFF_Q1, nullptr); __syncthreads();
    convfwd<32,4,4,true,1> (S+OFF_Q1, sP+PDW+288, sP+PDB+8,  S+OFF_V2, S+OFF_Q2, nullptr); __syncthreads();
    convfwd<64,4,4,true,1> (S+OFF_Q2, sP+PDW+432, sP+PDB+12, S+OFF_V3, S+OFF_Q3, nullptr); __syncthreads();
    convfwd<128,4,4,true,1>(S+OFF_Q3, sP+PDW+576, sP+PDB+16, S+OFF_V4, S+OFF_Q4, nullptr); __syncthreads();

    if (makeDy) convfwd<128,4,1,false,2>(S+OFF_Q4, sP+PWO, sP+PBO, ydst, nullptr, x);
    else        convfwd<128,4,1,false,0>(S+OFF_Q4, sP+PWO, sP+PBO, ydst, nullptr, nullptr);
    __syncthreads();
}

__global__ __launch_bounds__(NT)
void maml_kernel(const float* __restrict__ x_all,
                 const float* __restrict__ enc_w0,   const float* __restrict__ enc_w,
                 const float* __restrict__ enc_b,    const float* __restrict__ enc_lin_w,
                 const float* __restrict__ enc_lin_b,const float* __restrict__ dec_lin_w,
                 const float* __restrict__ dec_lin_b,const float* __restrict__ dec_w,
                 const float* __restrict__ dec_b,    const float* __restrict__ dec_w_out,
                 const float* __restrict__ dec_b_out,float* __restrict__ out)
{
    __shared__ float sP[NPARAM];
    __shared__ float sRed[160];
    const int s = blockIdx.x;
    float* S = g_scratch + (size_t)s * SSC;
    unsigned char* I = g_idxbuf + s * SIDX;
    const float* x = x_all + (size_t)s * 16384;

    for (int i = threadIdx.x; i < 36;   i += NT) sP[PW0 +i] = enc_w0[i];
    for (int i = threadIdx.x; i < 24;   i += NT) sP[PEB +i] = enc_b[i];
    for (int i = threadIdx.x; i < 720;  i += NT) sP[PEW +i] = enc_w[i];
    for (int i = threadIdx.x; i < 2048; i += NT) sP[PLEW+i] = enc_lin_w[i];
    for (int i = threadIdx.x; i < 32;   i += NT) sP[PLEB+i] = enc_lin_b[i];
    for (int i = threadIdx.x; i < 2048; i += NT) sP[PLDW+i] = dec_lin_w[i];
    for (int i = threadIdx.x; i < 64;   i += NT) sP[PLDB+i] = dec_lin_b[i];
    for (int i = threadIdx.x; i < 720;  i += NT) sP[PDW +i] = dec_w[i];
    for (int i = threadIdx.x; i < 20;   i += NT) sP[PDB +i] = dec_b[i];
    for (int i = threadIdx.x; i < 36;   i += NT) sP[PWO +i] = dec_w_out[i];
    if (threadIdx.x == 0) sP[PBO] = dec_b_out[0];
    __syncthreads();

    // ===== forward #1 (shared params), producing dy in scratch =====
    forward_pass(x, sP, S, I, S + OFF_DY, true);

    // ===== backward, updating smem params in place =====
    float* GA = S + OFF_GA;
    float* GB = S + OFF_GB;

    dgradv<128,4,1,true>(S+OFF_DY, sP+PWO, S+OFF_V4, GA);                   __syncthreads();
    wgradv<128,4,1,false>(S+OFF_DY, S+OFF_Q4, sP+PWO, sP+PBO, sRed);        __syncthreads();

    dupv<128,4,4>(GA, sP+PDW+576, S+OFF_V3, GB);                            __syncthreads();
    wgradv<128,4,4,true>(GA, S+OFF_Q3, sP+PDW+576, sP+PDB+16, sRed);        __syncthreads();
    dupv<64,4,4>(GB, sP+PDW+432, S+OFF_V2, GA);                             __syncthreads();
    wgradv<64,4,4,true>(GB, S+OFF_Q2, sP+PDW+432, sP+PDB+12, sRed);         __syncthreads();
    dupv<32,4,4>(GA, sP+PDW+288, S+OFF_V1, GB);                             __syncthreads();
    wgradv<32,4,4,true>(GA, S+OFF_Q1, sP+PDW+288, sP+PDB+8, sRed);          __syncthreads();
    dupv<16,4,4>(GB, sP+PDW+144, S+OFF_V0, GA);                             __syncthreads();
    wgradv<16,4,4,true>(GB, S+OFF_Q0, sP+PDW+144, sP+PDB+4, sRed);          __syncthreads();
    dupv<8,4,4>(GA, sP+PDW, S+OFF_DU, GB);                                  __syncthreads();  // GB = ddu[64]
    wgradv<8,4,4,true>(GA, S+OFF_DD, sP+PDW, sP+PDB, sRed);                 __syncthreads();

    if (threadIdx.x < 32) {
        float acc = 0.f;
        for (int i = 0; i < 64; ++i) acc += sP[PLDW + i*32 + threadIdx.x] * GB[i];
        GA[threadIdx.x] = acc;                       // dz
    }
    __syncthreads();
    for (int t = threadIdx.x; t < 2048; t += NT) {
        int i = t >> 5, j = t & 31;
        sP[PLDW + t] -= LRATE * GB[i] * S[OFF_Z + j];
    }
    if (threadIdx.x < 64) sP[PLDB + threadIdx.x] -= LRATE * GB[threadIdx.x];
    __syncthreads();
    if (threadIdx.x < 32) GB[threadIdx.x] = GA[threadIdx.x] * swish_d(S[OFF_ZU + threadIdx.x]); // dzu
    __syncthreads();
    if (threadIdx.x < 64) {
        float acc = 0.f;
        for (int i = 0; i < 32; ++i) acc += sP[PLEW + i*64 + threadIdx.x] * GB[i];
        GA[threadIdx.x] = acc;                       // df
    }
    __syncthreads();
    for (int t = threadIdx.x; t < 2048; t += NT) {
        int i = t >> 6, j = t & 63;
        sP[PLEW + t] -= LRATE * GB[i] * S[OFF_F + j];
    }
    if (threadIdx.x < 32) sP[PLEB + threadIdx.x] -= LRATE * GB[threadIdx.x];
    __syncthreads();
    if (threadIdx.x < 64) GB[threadIdx.x] = GA[threadIdx.x] * swish_d(S[OFF_U5 + threadIdx.x]); // du5
    __syncthreads();

    dgradv<4,4,4,false>(GB, sP+PEW+576, nullptr, GA);                       __syncthreads();
    wgradv<4,4,4,false>(GB, S+OFF_P4, sP+PEW+576, sP+PEB+20, sRed);         __syncthreads();
    pool_bwdv<8>(GA, I+IX4, S+OFF_U4, GB);                                  __syncthreads();
    dgradv<8,4,4,false>(GB, sP+PEW+432, nullptr, GA);                       __syncthreads();
    wgradv<8,4,4,false>(GB, S+OFF_P3, sP+PEW+432, sP+PEB+16, sRed);         __syncthreads();
    pool_bwdv<16>(GA, I+IX3, S+OFF_U3, GB);                                 __syncthreads();
    dgradv<16,4,4,false>(GB, sP+PEW+288, nullptr, GA);                      __syncthreads();
    wgradv<16,4,4,false>(GB, S+OFF_P2, sP+PEW+288, sP+PEB+12, sRed);        __syncthreads();
    pool_bwdv<32>(GA, I+IX2, S+OFF_U2, GB);                                 __syncthreads();
    dgradv<32,4,4,false>(GB, sP+PEW+144, nullptr, GA);                      __syncthreads();
    wgradv<32,4,4,false>(GB, S+OFF_P1, sP+PEW+144, sP+PEB+8, sRed);         __syncthreads();
    pool_bwdv<64>(GA, I+IX1, S+OFF_U1, GB);                                 __syncthreads();
    dgradv<64,4,4,false>(GB, sP+PEW, nullptr, GA);                          __syncthreads();
    wgradv<64,4,4,false>(GB, S+OFF_P0, sP+PEW, sP+PEB+4, sRed);             __syncthreads();
    pool_bwdv<128>(GA, I+IX0, S+OFF_U0, GB);                                __syncthreads();
    wgradv<128,1,4,false>(GB, x, sP+PW0, sP+PEB, sRed);                     __syncthreads();

    // ===== forward #2 with updated per-sample params =====
    forward_pass(x, sP, S, I, out + (size_t)s * 16384, false);
}

extern "C" void kernel_launch(void* const* d_in, const int* in_sizes, int n_in,
                              void* d_out, int out_size)
{
    (void)in_sizes; (void)n_in; (void)out_size;
    maml_kernel<<<128, NT>>>(
        (const float*)d_in[0],  (const float*)d_in[1],  (const float*)d_in[2],
        (const float*)d_in[3],  (const float*)d_in[4],  (const float*)d_in[5],
        (const float*)d_in[6],  (const float*)d_in[7],  (const float*)d_in[8],
        (const float*)d_in[9],  (const float*)d_in[10], (const float*)d_in[11],
        (float*)d_out);
}

// round 3
// speedup vs baseline: 3.5612x; 2.5891x over previous
#include <cuda_runtime.h>

#define NT 512
constexpr float LRATE = 0.01f;
constexpr float DYSCALE = 2.0f / 2097152.0f;   // 2 / (B * 128*128)

// ---- per-sample scratch offsets (floats); 4-ch tensors stored NHWC ----
constexpr int OFF_U0=0,      OFF_P0=65536,  OFF_U1=81920,  OFF_P1=98304,
              OFF_U2=102400, OFF_P2=106496, OFF_U3=107520, OFF_P3=108544,
              OFF_U4=108800, OFF_P4=109056, OFF_U5=109120, OFF_F =109184,
              OFF_ZU=109248, OFF_Z =109280, OFF_DU=109312, OFF_DD=109376,
              OFF_V0=109440, OFF_Q0=109696, OFF_V1=109952, OFF_Q1=110976,
              OFF_V2=112000, OFF_Q2=116096, OFF_V3=120192, OFF_Q3=136576,
              OFF_V4=152960, OFF_Q4=218496, OFF_DY=284032, OFF_GA=300416,
              OFF_GB=365952;
constexpr int SSC = 431488;
constexpr int IX0=0, IX1=16384, IX2=20480, IX3=21504, IX4=21760, SIDX=21824;

__device__ float          g_scratch[128ull * SSC];
__device__ unsigned char  g_idxbuf[128 * SIDX];

// ---- smem param layout (floats) ----
constexpr int PW0=0, PEB=36, PEW=60, PLEW=780, PLEB=2828, PLDW=2860, PLDB=4908,
              PDW=4972, PDB=5692, PWO=5712, PBO=5748, NPARAM=5749;

__device__ __forceinline__ float tanhap(float x){ float y; asm("tanh.approx.f32 %0, %1;" : "=f"(y) : "f"(x)); return y; }
__device__ __forceinline__ float sigm(float u){ return fmaf(tanhap(0.5f*u), 0.5f, 0.5f); }
__device__ __forceinline__ float swish_f(float u){ return u * sigm(u); }
__device__ __forceinline__ float swish_d(float u){ float s = sigm(u); return s * fmaf(u, 1.0f - s, 1.0f); }

__device__ __forceinline__ float4 ldz4(const float* p, bool v){
    return v ? *reinterpret_cast<const float4*>(p) : make_float4(0.f,0.f,0.f,0.f);
}
__device__ __forceinline__ float dot4a(float a, const float* w, float4 p){
    return fmaf(w[0],p.x, fmaf(w[1],p.y, fmaf(w[2],p.z, fmaf(w[3],p.w, a))));
}
__device__ __forceinline__ void axpy4(float4& a, float s, const float* w){
    a.x = fmaf(s,w[0],a.x); a.y = fmaf(s,w[1],a.y); a.z = fmaf(s,w[2],a.z); a.w = fmaf(s,w[3],a.w);
}
__device__ __forceinline__ void accum4(float* accK, float g, float4 p){  // stride 9 over c
    accK[0]  = fmaf(g,p.x,accK[0]);  accK[9]  = fmaf(g,p.y,accK[9]);
    accK[18] = fmaf(g,p.z,accK[18]); accK[27] = fmaf(g,p.w,accK[27]);
}
__device__ __forceinline__ int nh(int i){ return ((i & 15) << 2) + (i >> 4); }  // chw(4x4) -> nhwc

// ============================================================================
// conv0: 1->4, planar in, NHWC out (pre only)
// ============================================================================
template<int R>
__device__ __noinline__ void conv0(const float* __restrict__ in, const float* __restrict__ w,
                                   const float* __restrict__ b, float* __restrict__ outPre)
{
    constexpr int NX = R/4;
    float wr[36];
    #pragma unroll
    for (int k = 0; k < 9; ++k)
        #pragma unroll
        for (int o = 0; o < 4; ++o) wr[k*4+o] = w[o*9+k];
    const float4 bb = make_float4(b[0],b[1],b[2],b[3]);
    for (int t = threadIdx.x; t < R*NX; t += NT) {
        int xv = t % NX, y = t / NX, x0 = xv*4;
        float4 a[4] = {bb,bb,bb,bb};
        #pragma unroll
        for (int ky = 0; ky < 3; ++ky) {
            int yy = y + ky - 1; if ((unsigned)yy >= (unsigned)R) continue;
            const float* row = in + yy*R;
            float4 v = *reinterpret_cast<const float4*>(row + x0);
            float s[6];
            s[0] = (x0 > 0)   ? row[x0-1] : 0.f;
            s[1]=v.x; s[2]=v.y; s[3]=v.z; s[4]=v.w;
            s[5] = (x0+4 < R) ? row[x0+4] : 0.f;
            #pragma unroll
            for (int j = 0; j < 4; ++j)
                #pragma unroll
                for (int kx = 0; kx < 3; ++kx)
                    axpy4(a[j], s[j+kx], &wr[(ky*3+kx)*4]);
        }
        int base = (y*R + x0)*4;
        #pragma unroll
        for (int j = 0; j < 4; ++j)
            *reinterpret_cast<float4*>(outPre + base + j*4) = a[j];
    }
}

// ============================================================================
// conv4: 4->4 NHWC. MODE 0: pre only. MODE 1: pre + swish act.
// ============================================================================
template<int R,int MODE>
__device__ __noinline__ void conv4(const float* __restrict__ in, const float* __restrict__ w,
                                   const float* __restrict__ b, float* __restrict__ outPre,
                                   float* __restrict__ outAct)
{
    constexpr int NX = R/4;
    const int o = threadIdx.x & 3;
    float wr[36];
    #pragma unroll
    for (int k = 0; k < 9; ++k)
        #pragma unroll
        for (int c = 0; c < 4; ++c) wr[k*4+c] = w[(o*4+c)*9+k];
    const float bb = b[o];
    for (int t = threadIdx.x; t < 4*R*NX; t += NT) {
        int r2 = t >> 2;
        int xv = r2 % NX, y = r2 / NX, x0 = xv*4;
        float a[4] = {bb,bb,bb,bb};
        #pragma unroll
        for (int ky = 0; ky < 3; ++ky) {
            int yy = y + ky - 1; if ((unsigned)yy >= (unsigned)R) continue;
            const float* row = in + yy*R*4;
            float4 p[6];
            #pragma unroll
            for (int k = 0; k < 6; ++k) {
                int xx = x0 - 1 + k;
                p[k] = ldz4(row + xx*4, (unsigned)xx < (unsigned)R);
            }
            #pragma unroll
            for (int j = 0; j < 4; ++j)
                #pragma unroll
                for (int kx = 0; kx < 3; ++kx)
                    a[j] = dot4a(a[j], &wr[(ky*3+kx)*4], p[j+kx]);
        }
        int base = (y*R + x0)*4 + o;
        #pragma unroll
        for (int j = 0; j < 4; ++j) {
            outPre[base + j*4] = a[j];
            if constexpr (MODE == 1) outAct[base + j*4] = swish_f(a[j]);
        }
    }
}

// ============================================================================
// convup: 4->4 NHWC with fused 2x nearest upsample on input; writes pre + act.
// Thread group of 8: (o, row-parity) fixed per thread.
// ============================================================================
template<int R>
__device__ __noinline__ void convup(const float* __restrict__ in, const float* __restrict__ w,
                                    const float* __restrict__ b, float* __restrict__ outPre,
                                    float* __restrict__ outAct)
{
    constexpr int NX = R/4, H = R/2;
    const int o = threadIdx.x & 3;
    const int parity = (threadIdx.x >> 2) & 1;
    float FU[32];   // [rr][q][c], q: 0=u0 1=u2 2=u01 3=u12
    #pragma unroll
    for (int c = 0; c < 4; ++c) {
        const float* wb = w + (o*4 + c)*9;
        float A0,A1,A2,B0,B1,B2;
        if (!parity) { A0=wb[0];A1=wb[1];A2=wb[2]; B0=wb[3]+wb[6];B1=wb[4]+wb[7];B2=wb[5]+wb[8]; }
        else         { A0=wb[0]+wb[3];A1=wb[1]+wb[4];A2=wb[2]+wb[5]; B0=wb[6];B1=wb[7];B2=wb[8]; }
        FU[0*4+c]=A0;  FU[1*4+c]=A2;  FU[2*4+c]=A0+A1; FU[3*4+c]=A1+A2;
        FU[16+0*4+c]=B0; FU[16+1*4+c]=B2; FU[16+2*4+c]=B0+B1; FU[16+3*4+c]=B1+B2;
    }
    const float bb = b[o];
    for (int t = threadIdx.x; t < 8*H*NX; t += NT) {
        int q = t >> 3;
        int xv = q % NX, yh = q / NX;
        int y = 2*yh + parity, x0 = xv*4, hx = x0>>1;
        int ra, rb; bool va, vb;
        if (!parity) { ra = yh-1; va = (yh>0); rb = yh; vb = true; }
        else         { ra = yh; va = true; rb = yh+1; vb = (yh+1 < H); }
        float a[4] = {bb,bb,bb,bb};
        #pragma unroll
        for (int rr = 0; rr < 2; ++rr) {
            bool vld = rr ? vb : va;
            if (!vld) continue;
            const float* srow = in + (rr ? rb : ra)*H*4;
            float4 s0 = ldz4(srow + (hx-1)*4, hx > 0);
            float4 s1 = *reinterpret_cast<const float4*>(srow + hx*4);
            float4 s2 = *reinterpret_cast<const float4*>(srow + (hx+1)*4);
            float4 s3 = ldz4(srow + (hx+2)*4, hx+2 < H);
            const float* F = FU + rr*16;
            a[0] = dot4a(dot4a(a[0], F+0*4, s0), F+3*4, s1);
            a[1] = dot4a(dot4a(a[1], F+2*4, s1), F+1*4, s2);
            a[2] = dot4a(dot4a(a[2], F+0*4, s1), F+3*4, s2);
            a[3] = dot4a(dot4a(a[3], F+2*4, s2), F+1*4, s3);
        }
        int base = (y*R + x0)*4 + o;
        #pragma unroll
        for (int j = 0; j < 4; ++j) {
            outPre[base + j*4] = a[j];
            outAct[base + j*4] = swish_f(a[j]);
        }
    }
}

// ============================================================================
// convfin: 4->1, NHWC in, planar out. MODE 0: y. MODE 2: (y - xref)*DYSCALE.
// ============================================================================
template<int R,int MODE>
__device__ __noinline__ void convfin(const float* __restrict__ in, const float* __restrict__ w,
                                     float b0, float* __restrict__ outp,
                                     const float* __restrict__ xref)
{
    constexpr int NX = R/4;
    float wr[36];
    #pragma unroll
    for (int k = 0; k < 9; ++k)
        #pragma unroll
        for (int c = 0; c < 4; ++c) wr[k*4+c] = w[c*9+k];
    for (int t = threadIdx.x; t < R*NX; t += NT) {
        int xv = t % NX, y = t / NX, x0 = xv*4;
        float a[4] = {b0,b0,b0,b0};
        #pragma unroll
        for (int ky = 0; ky < 3; ++ky) {
            int yy = y + ky - 1; if ((unsigned)yy >= (unsigned)R) continue;
            const float* row = in + yy*R*4;
            float4 p[6];
            #pragma unroll
            for (int k = 0; k < 6; ++k) {
                int xx = x0 - 1 + k;
                p[k] = ldz4(row + xx*4, (unsigned)xx < (unsigned)R);
            }
            #pragma unroll
            for (int j = 0; j < 4; ++j)
                #pragma unroll
                for (int kx = 0; kx < 3; ++kx)
                    a[j] = dot4a(a[j], &wr[(ky*3+kx)*4], p[j+kx]);
        }
        float4 ov;
        if constexpr (MODE == 2) {
            float4 xr = *reinterpret_cast<const float4*>(xref + y*R + x0);
            ov = make_float4((a[0]-xr.x)*DYSCALE,(a[1]-xr.y)*DYSCALE,(a[2]-xr.z)*DYSCALE,(a[3]-xr.w)*DYSCALE);
        } else {
            ov = make_float4(a[0],a[1],a[2],a[3]);
        }
        *reinterpret_cast<float4*>(outp + y*R + x0) = ov;
    }
}

// ============================================================================
// pool 2x2 of swish(u), NHWC; argmax uchar4 per output pixel
// ============================================================================
template<int R>
__device__ __noinline__ void pool_swishv(const float* __restrict__ u, float* __restrict__ p,
                                         unsigned char* __restrict__ idx)
{
    constexpr int Ro = R/2;
    for (int t = threadIdx.x; t < Ro*Ro; t += NT) {
        int x = t % Ro, y = t / Ro;
        int base = ((2*y)*R + 2*x)*4;
        float4 A = *reinterpret_cast<const float4*>(u + base);
        float4 B = *reinterpret_cast<const float4*>(u + base + 4);
        float4 C = *reinterpret_cast<const float4*>(u + base + R*4);
        float4 D = *reinterpret_cast<const float4*>(u + base + R*4 + 4);
        float va[4]={A.x,A.y,A.z,A.w}, vb[4]={B.x,B.y,B.z,B.w};
        float vc[4]={C.x,C.y,C.z,C.w}, vd[4]={D.x,D.y,D.z,D.w};
        float pm[4]; unsigned char im[4];
        #pragma unroll
        for (int c = 0; c < 4; ++c) {
            float v0 = swish_f(va[c]), v1 = swish_f(vb[c]);
            float v2 = swish_f(vc[c]), v3 = swish_f(vd[c]);
            float m = v0; int id = 0;
            if (v1 > m) { m = v1; id = 1; }
            if (v2 > m) { m = v2; id = 2; }
            if (v3 > m) { m = v3; id = 3; }
            pm[c] = m; im[c] = (unsigned char)id;
        }
        int ob = (y*Ro + x)*4;
        *reinterpret_cast<float4*>(p + ob) = make_float4(pm[0],pm[1],pm[2],pm[3]);
        *reinterpret_cast<uchar4*>(idx + ob) = make_uchar4(im[0],im[1],im[2],im[3]);
    }
}

// ---- pool backward scatter fused with swish', NHWC ----
template<int R>
__device__ __noinline__ void pool_bwdv(const float* __restrict__ dp, const unsigned char* __restrict__ idx,
                                       const float* __restrict__ u, float* __restrict__ du)
{
    constexpr int H = R/2;
    for (int t = threadIdx.x; t < R*H; t += NT) {
        int xh = t % H, y = t / H;
        int cell = ((y>>1)*H + xh)*4;
        float4 d4 = *reinterpret_cast<const float4*>(dp + cell);
        uchar4 i4 = *reinterpret_cast<const uchar4*>(idx + cell);
        float dv[4]={d4.x,d4.y,d4.z,d4.w};
        unsigned char iv[4]={i4.x,i4.y,i4.z,i4.w};
        int sb = (y & 1) << 1;
        #pragma unroll
        for (int s = 0; s < 2; ++s) {
            int x = 2*xh + s;
            float4 u4 = *reinterpret_cast<const float4*>(u + (y*R + x)*4);
            float uv[4]={u4.x,u4.y,u4.z,u4.w};
            float ov[4];
            #pragma unroll
            for (int c = 0; c < 4; ++c) {
                float g = (iv[c] == (unsigned char)(sb+s)) ? dv[c] : 0.f;
                ov[c] = g * swish_d(uv[c]);
            }
            *reinterpret_cast<float4*>(du + (y*R + x)*4) = make_float4(ov[0],ov[1],ov[2],ov[3]);
        }
    }
}

// ============================================================================
// dgrad of final conv: planar dout -> NHWC din, fused swish'(V4)
// ============================================================================
template<int R>
__device__ __noinline__ void dgrad_fin(const float* __restrict__ dout, const float* __restrict__ w,
                                       const float* __restrict__ upre, float* __restrict__ din)
{
    constexpr int NX = R/4;
    float wf[36];
    #pragma unroll
    for (int k = 0; k < 9; ++k)
        #pragma unroll
        for (int c = 0; c < 4; ++c) wf[k*4+c] = w[c*9 + 8-k];
    for (int t = threadIdx.x; t < R*NX; t += NT) {
        int xv = t % NX, y = t / NX, x0 = xv*4;
        float4 a[4] = {};
        #pragma unroll
        for (int ky = 0; ky < 3; ++ky) {
            int yy = y + ky - 1; if ((unsigned)yy >= (unsigned)R) continue;
            const float* row = dout + yy*R;
            float4 v = *reinterpret_cast<const float4*>(row + x0);
            float s[6];
            s[0] = (x0 > 0)   ? row[x0-1] : 0.f;
            s[1]=v.x; s[2]=v.y; s[3]=v.z; s[4]=v.w;
            s[5] = (x0+4 < R) ? row[x0+4] : 0.f;
            #pragma unroll
            for (int j = 0; j < 4; ++j)
                #pragma unroll
                for (int kx = 0; kx < 3; ++kx)
                    axpy4(a[j], s[j+kx], &wf[(ky*3+kx)*4]);
        }
        int base = (y*R + x0)*4;
        #pragma unroll
        for (int j = 0; j < 4; ++j) {
            float4 u4 = *reinterpret_cast<const float4*>(upre + base + j*4);
            a[j].x *= swish_d(u4.x); a[j].y *= swish_d(u4.y);
            a[j].z *= swish_d(u4.z); a[j].w *= swish_d(u4.w);
            *reinterpret_cast<float4*>(din + base + j*4) = a[j];
        }
    }
}

// ============================================================================
// dgrad 4->4 NHWC (encoder; no fuse)
// ============================================================================
template<int R>
__device__ __noinline__ void dgrad4(const float* __restrict__ dout, const float* __restrict__ w,
                                    float* __restrict__ din)
{
    constexpr int NX = R/4;
    const int c = threadIdx.x & 3;
    float wf[36];
    #pragma unroll
    for (int k = 0; k < 9; ++k)
        #pragma unroll
        for (int o = 0; o < 4; ++o) wf[k*4+o] = w[(o*4+c)*9 + 8-k];
    for (int t = threadIdx.x; t < 4*R*NX; t += NT) {
        int r2 = t >> 2;
        int xv = r2 % NX, y = r2 / NX, x0 = xv*4;
        float a[4] = {};
        #pragma unroll
        for (int ky = 0; ky < 3; ++ky) {
            int yy = y + ky - 1; if ((unsigned)yy >= (unsigned)R) continue;
            const float* row = dout + yy*R*4;
            float4 p[6];
            #pragma unroll
            for (int k = 0; k < 6; ++k) {
                int xx = x0 - 1 + k;
                p[k] = ldz4(row + xx*4, (unsigned)xx < (unsigned)R);
            }
            #pragma unroll
            for (int j = 0; j < 4; ++j)
                #pragma unroll
                for (int kx = 0; kx < 3; ++kx)
                    a[j] = dot4a(a[j], &wf[(ky*3+kx)*4], p[j+kx]);
        }
        int base = (y*R + x0)*4 + c;
        #pragma unroll
        for (int j = 0; j < 4; ++j) din[base + j*4] = a[j];
    }
}

// ============================================================================
// backward of (up -> conv): NHWC dout at R -> NHWC din at H, effective 4x4
// kernel wE = flip(w) * box2x2; fused swish'(upre).
// ============================================================================
template<int R>
__device__ __noinline__ void dupv(const float* __restrict__ dout, const float* __restrict__ w,
                                  const float* __restrict__ upre, float* __restrict__ din)
{
    constexpr int H = R/2, NXH = H/4;
    const int c = threadIdx.x & 3;
    float wE[64];   // [i*4+kk][o]
    #pragma unroll
    for (int o = 0; o < 4; ++o) {
        const float* wb = w + (o*4 + c)*9;
        #pragma unroll
        for (int i = 0; i < 4; ++i)
            #pragma unroll
            for (int j = 0; j < 4; ++j) {
                float s = 0.f;
                #pragma unroll
                for (int sy = 0; sy < 2; ++sy) {
                    int a = sy + 2 - i; if (a < 0 || a > 2) continue;
                    #pragma unroll
                    for (int sx = 0; sx < 2; ++sx) {
                        int bc = sx + 2 - j; if (bc < 0 || bc > 2) continue;
                        s += wb[a*3 + bc];
                    }
                }
                wE[(i*4+j)*4 + o] = s;
            }
    }
    for (int t = threadIdx.x; t < 4*H*NXH; t += NT) {
        int r2 = t >> 2;
        int vv = r2 % NXH, u = r2 / NXH, v0 = vv*4;
        int r0 = 2*u - 1;
        float a[4] = {};
        #pragma unroll
        for (int i = 0; i < 4; ++i) {
            int rr = r0 + i; if ((unsigned)rr >= (unsigned)R) continue;
            const float* row = dout + rr*R*4;
            float4 q[10];
            #pragma unroll
            for (int m = 0; m < 10; ++m) {
                int px = 2*v0 - 1 + m;
                q[m] = ldz4(row + px*4, (unsigned)px < (unsigned)R);
            }
            #pragma unroll
            for (int j = 0; j < 4; ++j)
                #pragma unroll
                for (int kk = 0; kk < 4; ++kk)
                    a[j] = dot4a(a[j], &wE[(i*4+kk)*4], q[2*j+kk]);
        }
        int base = (u*H + v0)*4 + c;
        #pragma unroll
        for (int j = 0; j < 4; ++j) {
            float up = upre[base + j*4];
            din[base + j*4] = a[j] * swish_d(up);
        }
    }
}

// ============================================================================
// wgrad 4->4 (NHWC dout; in NHWC at R or, UP, at H); in-place smem update
// ============================================================================
template<int R,bool UP>
__device__ __noinline__ void wgrad4(const float* __restrict__ dout, const float* __restrict__ in,
                                    float* wDst, float* bDst, float* sRed)
{
    constexpr int NX = R/4, H = R/2;
    for (int i = threadIdx.x; i < 148; i += NT) sRed[i] = 0.f;
    __syncthreads();
    const int o = threadIdx.x & 3;
    float acc[36]; float accb = 0.f;
    #pragma unroll
    for (int i = 0; i < 36; ++i) acc[i] = 0.f;

    for (int pv = threadIdx.x >> 2; pv < R*NX; pv += NT >> 2) {
        int y = pv / NX, x0 = (pv % NX)*4;
        const float* db = dout + (y*R + x0)*4 + o;
        float g0 = db[0], g1 = db[4], g2 = db[8], g3 = db[12];
        accb += g0+g1+g2+g3;
        float g01 = g0+g1, g12 = g1+g2, g23 = g2+g3;
        #pragma unroll
        for (int ky = 0; ky < 3; ++ky) {
            int yy = y + ky - 1; if ((unsigned)yy >= (unsigned)R) continue;
            if constexpr (UP) {
                const float* srow = in + (yy>>1)*H*4;
                int hx = x0 >> 1;
                float4 s0 = ldz4(srow + (hx-1)*4, hx > 0);
                float4 s1 = *reinterpret_cast<const float4*>(srow + hx*4);
                float4 s2 = *reinterpret_cast<const float4*>(srow + (hx+1)*4);
                float4 s3 = ldz4(srow + (hx+2)*4, hx+2 < H);
                accum4(&acc[ky*3+0], g0, s0); accum4(&acc[ky*3+0], g12, s1); accum4(&acc[ky*3+0], g3, s2);
                accum4(&acc[ky*3+1], g01, s1); accum4(&acc[ky*3+1], g23, s2);
                accum4(&acc[ky*3+2], g0, s1); accum4(&acc[ky*3+2], g12, s2); accum4(&acc[ky*3+2], g3, s3);
            } else {
                const float* row = in + yy*R*4;
                float4 p[6];
                #pragma unroll
                for (int k = 0; k < 6; ++k) {
                    int xx = x0 - 1 + k;
                    p[k] = ldz4(row + xx*4, (unsigned)xx < (unsigned)R);
                }
                float g[4] = {g0,g1,g2,g3};
                #pragma unroll
                for (int kx = 0; kx < 3; ++kx)
                    #pragma unroll
                    for (int j = 0; j < 4; ++j)
                        accum4(&acc[ky*3+kx], g[j], p[j+kx]);
            }
        }
    }
    unsigned lane = threadIdx.x & 31;
    #pragma unroll
    for (int off = 16; off >= 4; off >>= 1) {
        #pragma unroll
        for (int i = 0; i < 36; ++i) acc[i] += __shfl_xor_sync(0xffffffffu, acc[i], off);
        accb += __shfl_xor_sync(0xffffffffu, accb, off);
    }
    if (lane < 4) {
        #pragma unroll
        for (int i = 0; i < 36; ++i) atomicAdd(&sRed[o*36 + i], acc[i]);
        atomicAdd(&sRed[144 + o], accb);
    }
    __syncthreads();
    for (int i = threadIdx.x; i < 144; i += NT) wDst[i] -= LRATE * sRed[i];
    if (threadIdx.x < 4) bDst[threadIdx.x] -= LRATE * sRed[144 + threadIdx.x];
}

// ---- wgrad of final conv (planar dout, NHWC in, COUT=1) ----
template<int R>
__device__ __noinline__ void wgrad_fin(const float* __restrict__ dout, const float* __restrict__ in,
                                       float* wDst, float* bDst, float* sRed)
{
    constexpr int NX = R/4;
    for (int i = threadIdx.x; i < 37; i += NT) sRed[i] = 0.f;
    __syncthreads();
    float acc[36]; float accb = 0.f;
    #pragma unroll
    for (int i = 0; i < 36; ++i) acc[i] = 0.f;
    for (int pv = threadIdx.x; pv < R*NX; pv += NT) {
        int y = pv / NX, x0 = (pv % NX)*4;
        float4 g = *reinterpret_cast<const float4*>(dout + y*R + x0);
        float gv[4] = {g.x,g.y,g.z,g.w};
        accb += g.x+g.y+g.z+g.w;
        #pragma unroll
        for (int ky = 0; ky < 3; ++ky) {
            int yy = y + ky - 1; if ((unsigned)yy >= (unsigned)R) continue;
            const float* row = in + yy*R*4;
            float4 p[6];
            #pragma unroll
            for (int k = 0; k < 6; ++k) {
                int xx = x0 - 1 + k;
                p[k] = ldz4(row + xx*4, (unsigned)xx < (unsigned)R);
            }
            #pragma unroll
            for (int kx = 0; kx < 3; ++kx)
                #pragma unroll
                for (int j = 0; j < 4; ++j)
                    accum4(&acc[ky*3+kx], gv[j], p[j+kx]);
        }
    }
    unsigned lane = threadIdx.x & 31;
    #pragma unroll
    for (int off = 16; off >= 1; off >>= 1) {
        #pragma unroll
        for (int i = 0; i < 36; ++i) acc[i] += __shfl_xor_sync(0xffffffffu, acc[i], off);
        accb += __shfl_xor_sync(0xffffffffu, accb, off);
    }
    if (lane == 0) {
        #pragma unroll
        for (int i = 0; i < 36; ++i) atomicAdd(&sRed[i], acc[i]);
        atomicAdd(&sRed[36], accb);
    }
    __syncthreads();
    for (int i = threadIdx.x; i < 36; i += NT) wDst[i] -= LRATE * sRed[i];
    if (threadIdx.x == 0) bDst[0] -= LRATE * sRed[36];
}

// ---- wgrad of first conv (NHWC dout, planar in, CIN=1) ----
template<int R>
__device__ __noinline__ void wgrad_first(const float* __restrict__ dout, const float* __restrict__ in,
                                         float* wDst, float* bDst, float* sRed)
{
    constexpr int NX = R/4;
    for (int i = threadIdx.x; i < 40; i += NT) sRed[i] = 0.f;
    __syncthreads();
    const int o = threadIdx.x & 3;
    float acc[9]; float accb = 0.f;
    #pragma unroll
    for (int i = 0; i < 9; ++i) acc[i] = 0.f;
    for (int pv = threadIdx.x >> 2; pv < R*NX; pv += NT >> 2) {
        int y = pv / NX, x0 = (pv % NX)*4;
        const float* db = dout + (y*R + x0)*4 + o;
        float g[4] = {db[0], db[4], db[8], db[12]};
        accb += g[0]+g[1]+g[2]+g[3];
        #pragma unroll
        for (int ky = 0; ky < 3; ++ky) {
            int yy = y + ky - 1; if ((unsigned)yy >= (unsigned)R) continue;
            const float* row = in + yy*R;
            float4 v = *reinterpret_cast<const float4*>(row + x0);
            float s[6];
            s[0] = (x0 > 0)   ? row[x0-1] : 0.f;
            s[1]=v.x; s[2]=v.y; s[3]=v.z; s[4]=v.w;
            s[5] = (x0+4 < R) ? row[x0+4] : 0.f;
            #pragma unroll
            for (int kx = 0; kx < 3; ++kx) {
                float t = 0.f;
                #pragma unroll
                for (int j = 0; j < 4; ++j) t = fmaf(g[j], s[j+kx], t);
                acc[ky*3+kx] += t;
            }
        }
    }
    unsigned lane = threadIdx.x & 31;
    #pragma unroll
    for (int off = 16; off >= 4; off >>= 1) {
        #pragma unroll
        for (int i = 0; i < 9; ++i) acc[i] += __shfl_xor_sync(0xffffffffu, acc[i], off);
        accb += __shfl_xor_sync(0xffffffffu, accb, off);
    }
    if (lane < 4) {
        #pragma unroll
        for (int i = 0; i < 9; ++i) atomicAdd(&sRed[o*9 + i], acc[i]);
        atomicAdd(&sRed[36 + o], accb);
    }
    __syncthreads();
    for (int i = threadIdx.x; i < 36; i += NT) wDst[i] -= LRATE * sRed[i];
    if (threadIdx.x < 4) bDst[threadIdx.x] -= LRATE * sRed[36 + threadIdx.x];
}

// ---- full forward pass ----
__device__ __noinline__ void forward_pass(const float* __restrict__ x, const float* sP,
                                          float* S, unsigned char* I,
                                          float* __restrict__ ydst, bool makeDy)
{
    conv0<128>(x, sP+PW0, sP+PEB, S+OFF_U0);                                __syncthreads();
    pool_swishv<128>(S+OFF_U0, S+OFF_P0, I+IX0);                            __syncthreads();
    conv4<64,0>(S+OFF_P0, sP+PEW,     sP+PEB+4,  S+OFF_U1, nullptr);        __syncthreads();
    pool_swishv<64>(S+OFF_U1, S+OFF_P1, I+IX1);                             __syncthreads();
    conv4<32,0>(S+OFF_P1, sP+PEW+144, sP+PEB+8,  S+OFF_U2, nullptr);        __syncthreads();
    pool_swishv<32>(S+OFF_U2, S+OFF_P2, I+IX2);                             __syncthreads();
    conv4<16,0>(S+OFF_P2, sP+PEW+288, sP+PEB+12, S+OFF_U3, nullptr);        __syncthreads();
    pool_swishv<16>(S+OFF_U3, S+OFF_P3, I+IX3);                             __syncthreads();
    conv4<8,0> (S+OFF_P3, sP+PEW+432, sP+PEB+16, S+OFF_U4, nullptr);        __syncthreads();
    pool_swishv<8>(S+OFF_U4, S+OFF_P4, I+IX4);                              __syncthreads();
    conv4<4,1> (S+OFF_P4, sP+PEW+576, sP+PEB+20, S+OFF_U5, S+OFF_F);        __syncthreads();

    if (threadIdx.x < 32) {
        float acc = sP[PLEB + threadIdx.x];
        for (int j = 0; j < 64; ++j) acc += sP[PLEW + threadIdx.x*64 + j] * S[OFF_F + nh(j)];
        S[OFF_ZU + threadIdx.x] = acc;
        S[OFF_Z  + threadIdx.x] = swish_f(acc);
    }
    __syncthreads();
    if (threadIdx.x < 64) {
        float acc = sP[PLDB + threadIdx.x];
        for (int j = 0; j < 32; ++j) acc += sP[PLDW + threadIdx.x*32 + j] * S[OFF_Z + j];
        S[OFF_DU + nh(threadIdx.x)] = acc;
        S[OFF_DD + nh(threadIdx.x)] = swish_f(acc);
    }
    __syncthreads();

    convup<8>  (S+OFF_DD, sP+PDW,     sP+PDB,    S+OFF_V0, S+OFF_Q0);       __syncthreads();
    convup<16> (S+OFF_Q0, sP+PDW+144, sP+PDB+4,  S+OFF_V1, S+OFF_Q1);       __syncthreads();
    convup<32> (S+OFF_Q1, sP+PDW+288, sP+PDB+8,  S+OFF_V2, S+OFF_Q2);       __syncthreads();
    convup<64> (S+OFF_Q2, sP+PDW+432, sP+PDB+12, S+OFF_V3, S+OFF_Q3);       __syncthreads();
    convup<128>(S+OFF_Q3, sP+PDW+576, sP+PDB+16, S+OFF_V4, S+OFF_Q4);       __syncthreads();

    if (makeDy) convfin<128,2>(S+OFF_Q4, sP+PWO, sP[PBO], ydst, x);
    else        convfin<128,0>(S+OFF_Q4, sP+PWO, sP[PBO], ydst, nullptr);
    __syncthreads();
}

__global__ __launch_bounds__(NT, 1)
void maml_kernel(const float* __restrict__ x_all,
                 const float* __restrict__ enc_w0,   const float* __restrict__ enc_w,
                 const float* __restrict__ enc_b,    const float* __restrict__ enc_lin_w,
                 const float* __restrict__ enc_lin_b,const float* __restrict__ dec_lin_w,
                 const float* __restrict__ dec_lin_b,const float* __restrict__ dec_w,
                 const float* __restrict__ dec_b,    const float* __restrict__ dec_w_out,
                 const float* __restrict__ dec_b_out,float* __restrict__ out)
{
    __shared__ float sP[NPARAM];
    __shared__ float sRed[160];
    const int s = blockIdx.x;
    float* S = g_scratch + (size_t)s * SSC;
    unsigned char* I = g_idxbuf + s * SIDX;
    const float* x = x_all + (size_t)s * 16384;

    for (int i = threadIdx.x; i < 36;   i += NT) sP[PW0 +i] = enc_w0[i];
    for (int i = threadIdx.x; i < 24;   i += NT) sP[PEB +i] = enc_b[i];
    for (int i = threadIdx.x; i < 720;  i += NT) sP[PEW +i] = enc_w[i];
    for (int i = threadIdx.x; i < 2048; i += NT) sP[PLEW+i] = enc_lin_w[i];
    for (int i = threadIdx.x; i < 32;   i += NT) sP[PLEB+i] = enc_lin_b[i];
    for (int i = threadIdx.x; i < 2048; i += NT) sP[PLDW+i] = dec_lin_w[i];
    for (int i = threadIdx.x; i < 64;   i += NT) sP[PLDB+i] = dec_lin_b[i];
    for (int i = threadIdx.x; i < 720;  i += NT) sP[PDW +i] = dec_w[i];
    for (int i = threadIdx.x; i < 20;   i += NT) sP[PDB +i] = dec_b[i];
    for (int i = threadIdx.x; i < 36;   i += NT) sP[PWO +i] = dec_w_out[i];
    if (threadIdx.x == 0) sP[PBO] = dec_b_out[0];
    __syncthreads();

    // ===== forward #1 =====
    forward_pass(x, sP, S, I, S + OFF_DY, true);

    float* GA = S + OFF_GA;
    float* GB = S + OFF_GB;

    // ===== backward =====
    dgrad_fin<128>(S+OFF_DY, sP+PWO, S+OFF_V4, GA);                         __syncthreads();
    wgrad_fin<128>(S+OFF_DY, S+OFF_Q4, sP+PWO, sP+PBO, sRed);               __syncthreads();

    dupv<128>(GA, sP+PDW+576, S+OFF_V3, GB);                                __syncthreads();
    wgrad4<128,true>(GA, S+OFF_Q3, sP+PDW+576, sP+PDB+16, sRed);            __syncthreads();
    dupv<64>(GB, sP+PDW+432, S+OFF_V2, GA);                                 __syncthreads();
    wgrad4<64,true>(GB, S+OFF_Q2, sP+PDW+432, sP+PDB+12, sRed);             __syncthreads();
    dupv<32>(GA, sP+PDW+288, S+OFF_V1, GB);                                 __syncthreads();
    wgrad4<32,true>(GA, S+OFF_Q1, sP+PDW+288, sP+PDB+8, sRed);              __syncthreads();
    dupv<16>(GB, sP+PDW+144, S+OFF_V0, GA);                                 __syncthreads();
    wgrad4<16,true>(GB, S+OFF_Q0, sP+PDW+144, sP+PDB+4, sRed);              __syncthreads();
    dupv<8>(GA, sP+PDW, S+OFF_DU, GB);                                      __syncthreads();  // GB = ddu (NHWC, 64)
    wgrad4<8,true>(GA, S+OFF_DD, sP+PDW, sP+PDB, sRed);                     __syncthreads();

    // dec_lin backward (ddu NHWC in GB)
    if (threadIdx.x < 32) {
        float acc = 0.f;
        for (int i = 0; i < 64; ++i) acc += sP[PLDW + i*32 + threadIdx.x] * GB[nh(i)];
        GA[threadIdx.x] = acc;                       // dz (plain)
    }
    __syncthreads();
    for (int t = threadIdx.x; t < 2048; t += NT) {
        int i = t >> 5, j = t & 31;
        sP[PLDW + t] -= LRATE * GB[nh(i)] * S[OFF_Z + j];
    }
    if (threadIdx.x < 64) sP[PLDB + threadIdx.x] -= LRATE * GB[nh(threadIdx.x)];
    __syncthreads();
    if (threadIdx.x < 32) GB[threadIdx.x] = GA[threadIdx.x] * swish_d(S[OFF_ZU + threadIdx.x]); // dzu (plain)
    __syncthreads();
    if (threadIdx.x < 64) {
        float acc = 0.f;
        for (int i = 0; i < 32; ++i) acc += sP[PLEW + i*64 + threadIdx.x] * GB[i];
        int ni = nh(threadIdx.x);
        GA[ni] = acc * swish_d(S[OFF_U5 + ni]);      // du5 (NHWC)
    }
    __syncthreads();
    for (int t = threadIdx.x; t < 2048; t += NT) {
        int i = t >> 6, j = t & 63;
        sP[PLEW + t] -= LRATE * GB[i] * S[OFF_F + nh(j)];
    }
    if (threadIdx.x < 32) sP[PLEB + threadIdx.x] -= LRATE * GB[threadIdx.x];
    __syncthreads();

    // encoder backward (du5 in GA)
    dgrad4<4>(GA, sP+PEW+576, GB);                                          __syncthreads();
    wgrad4<4,false>(GA, S+OFF_P4, sP+PEW+576, sP+PEB+20, sRed);             __syncthreads();
    pool_bwdv<8>(GB, I+IX4, S+OFF_U4, GA);                                  __syncthreads();
    dgrad4<8>(GA, sP+PEW+432, GB);                                          __syncthreads();
    wgrad4<8,false>(GA, S+OFF_P3, sP+PEW+432, sP+PEB+16, sRed);             __syncthreads();
    pool_bwdv<16>(GB, I+IX3, S+OFF_U3, GA);                                 __syncthreads();
    dgrad4<16>(GA, sP+PEW+288, GB);                                         __syncthreads();
    wgrad4<16,false>(GA, S+OFF_P2, sP+PEW+288, sP+PEB+12, sRed);            __syncthreads();
    pool_bwdv<32>(GB, I+IX2, S+OFF_U2, GA);                                 __syncthreads();
    dgrad4<32>(GA, sP+PEW+144, GB);                                         __syncthreads();
    wgrad4<32,false>(GA, S+OFF_P1, sP+PEW+144, sP+PEB+8, sRed);             __syncthreads();
    pool_bwdv<64>(GB, I+IX1, S+OFF_U1, GA);                                 __syncthreads();
    dgrad4<64>(GA, sP+PEW, GB);                                             __syncthreads();
    wgrad4<64,false>(GA, S+OFF_P0, sP+PEW, sP+PEB+4, sRed);                 __syncthreads();
    pool_bwdv<128>(GB, I+IX0, S+OFF_U0, GA);                                __syncthreads();
    wgrad_first<128>(GA, x, sP+PW0, sP+PEB, sRed);                          __syncthreads();

    // ===== forward #2 with updated per-sample params =====
    forward_pass(x, sP, S, I, out + (size_t)s * 16384, false);
}

extern "C" void kernel_launch(void* const* d_in, const int* in_sizes, int n_in,
                              void* d_out, int out_size)
{
    (void)in_sizes; (void)n_in; (void)out_size;
    maml_kernel<<<128, NT>>>(
        (const float*)d_in[0],  (const float*)d_in[1],  (const float*)d_in[2],
        (const float*)d_in[3],  (const float*)d_in[4],  (const float*)d_in[5],
        (const float*)d_in[6],  (const float*)d_in[7],  (const float*)d_in[8],
        (const float*)d_in[9],  (const float*)d_in[10], (const float*)d_in[11],
        (float*)d_out);
}

// round 5
// speedup vs baseline: 3.7121x; 1.0424x over previous
// Resubmission of R4 kernel (prior bench aborted: GB300 container infra failure).
#include <cuda_runtime.h>

#define NT 512
constexpr float LRATE = 0.01f;
constexpr float DYSCALE = 2.0f / 2097152.0f;   // 2 / (B * 128*128)

// ---- per-sample scratch offsets (floats); 4-ch tensors stored NHWC ----
constexpr int OFF_U0=0,      OFF_P0=65536,  OFF_U1=81920,  OFF_P1=98304,
              OFF_U2=102400, OFF_P2=106496, OFF_U3=107520, OFF_P3=108544,
              OFF_U4=108800, OFF_P4=109056, OFF_U5=109120, OFF_F =109184,
              OFF_ZU=109248, OFF_Z =109280, OFF_DU=109312, OFF_DD=109376,
              OFF_V0=109440, OFF_Q0=109696, OFF_V1=109952, OFF_Q1=110976,
              OFF_V2=112000, OFF_Q2=116096, OFF_V3=120192, OFF_Q3=136576,
              OFF_V4=152960, OFF_Q4=218496, OFF_DY=284032, OFF_GA=300416,
              OFF_GB=365952;
constexpr int SSC = 431488;
constexpr int IX0=0, IX1=16384, IX2=20480, IX3=21504, IX4=21760, SIDX=21824;

__device__ float          g_scratch[128ull * SSC];
__device__ unsigned char  g_idxbuf[128 * SIDX];

// ---- smem param layout (floats) ----
constexpr int PW0=0, PEB=36, PEW=60, PLEW=780, PLEB=2828, PLDW=2860, PLDB=4908,
              PDW=4972, PDB=5692, PWO=5712, PBO=5748, NPARAM=5749;

__device__ __forceinline__ float tanhap(float x){ float y; asm("tanh.approx.f32 %0, %1;" : "=f"(y) : "f"(x)); return y; }
__device__ __forceinline__ float sigm(float u){ return fmaf(tanhap(0.5f*u), 0.5f, 0.5f); }
__device__ __forceinline__ float swish_f(float u){ return u * sigm(u); }
__device__ __forceinline__ float swish_d(float u){ float s = sigm(u); return s * fmaf(u, 1.0f - s, 1.0f); }

__device__ __forceinline__ float4 ldz4(const float* p, bool v){
    return v ? *reinterpret_cast<const float4*>(p) : make_float4(0.f,0.f,0.f,0.f);
}
__device__ __forceinline__ float dot4a(float a, const float* w, float4 p){
    return fmaf(w[0],p.x, fmaf(w[1],p.y, fmaf(w[2],p.z, fmaf(w[3],p.w, a))));
}
__device__ __forceinline__ void axpy4(float4& a, float s, const float* w){
    a.x = fmaf(s,w[0],a.x); a.y = fmaf(s,w[1],a.y); a.z = fmaf(s,w[2],a.z); a.w = fmaf(s,w[3],a.w);
}
__device__ __forceinline__ void accum4(float* accK, float g, float4 p){  // stride 9 over c
    accK[0]  = fmaf(g,p.x,accK[0]);  accK[9]  = fmaf(g,p.y,accK[9]);
    accK[18] = fmaf(g,p.z,accK[18]); accK[27] = fmaf(g,p.w,accK[27]);
}
__device__ __forceinline__ int nh(int i){ return ((i & 15) << 2) + (i >> 4); }  // chw(4x4) -> nhwc

// ============================================================================
// conv0: 1->4, planar in, NHWC out (pre only). 2-row blocked.
// ============================================================================
template<int R>
__device__ __noinline__ void conv0(const float* __restrict__ in, const float* __restrict__ w,
                                   const float* __restrict__ b, float* __restrict__ outPre)
{
    constexpr int NX = R/4;
    float wr[36];
    #pragma unroll
    for (int k = 0; k < 9; ++k)
        #pragma unroll
        for (int o = 0; o < 4; ++o) wr[k*4+o] = w[o*9+k];
    const float4 bb = make_float4(b[0],b[1],b[2],b[3]);
    for (int t = threadIdx.x; t < (R/2)*NX; t += NT) {
        int xv = t % NX, yp = t / NX, x0 = xv*4, y0 = 2*yp;
        float4 a0[4] = {bb,bb,bb,bb};
        float4 a1[4] = {bb,bb,bb,bb};
        #pragma unroll
        for (int iy = 0; iy < 4; ++iy) {
            int yy = y0 - 1 + iy; if ((unsigned)yy >= (unsigned)R) continue;
            const float* row = in + yy*R;
            float4 v = *reinterpret_cast<const float4*>(row + x0);
            float s[6];
            s[0] = (x0 > 0)   ? row[x0-1] : 0.f;
            s[1]=v.x; s[2]=v.y; s[3]=v.z; s[4]=v.w;
            s[5] = (x0+4 < R) ? row[x0+4] : 0.f;
            if (iy <= 2) {
                #pragma unroll
                for (int j = 0; j < 4; ++j)
                    #pragma unroll
                    for (int kx = 0; kx < 3; ++kx)
                        axpy4(a0[j], s[j+kx], &wr[(iy*3+kx)*4]);
            }
            if (iy >= 1) {
                #pragma unroll
                for (int j = 0; j < 4; ++j)
                    #pragma unroll
                    for (int kx = 0; kx < 3; ++kx)
                        axpy4(a1[j], s[j+kx], &wr[((iy-1)*3+kx)*4]);
            }
        }
        int base0 = (y0*R + x0)*4, base1 = base0 + R*4;
        #pragma unroll
        for (int j = 0; j < 4; ++j) {
            *reinterpret_cast<float4*>(outPre + base0 + j*4) = a0[j];
            *reinterpret_cast<float4*>(outPre + base1 + j*4) = a1[j];
        }
    }
}

// ============================================================================
// conv4: 4->4 NHWC, 2-row blocked. MODE 0: pre only. MODE 1: act (+pre if ST).
// ============================================================================
template<int R,int MODE,bool ST>
__device__ __noinline__ void conv4(const float* __restrict__ in, const float* __restrict__ w,
                                   const float* __restrict__ b, float* __restrict__ outPre,
                                   float* __restrict__ outAct)
{
    constexpr int NX = R/4;
    const int o = threadIdx.x & 3;
    float wr[36];
    #pragma unroll
    for (int k = 0; k < 9; ++k)
        #pragma unroll
        for (int c = 0; c < 4; ++c) wr[k*4+c] = w[(o*4+c)*9+k];
    const float bb = b[o];
    for (int t = threadIdx.x; t < 4*(R/2)*NX; t += NT) {
        int r2 = t >> 2;
        int xv = r2 % NX, yp = r2 / NX, x0 = xv*4, y0 = 2*yp;
        float a0[4] = {bb,bb,bb,bb};
        float a1[4] = {bb,bb,bb,bb};
        #pragma unroll
        for (int iy = 0; iy < 4; ++iy) {
            int yy = y0 - 1 + iy; if ((unsigned)yy >= (unsigned)R) continue;
            const float* row = in + yy*R*4;
            float4 p[6];
            #pragma unroll
            for (int k = 0; k < 6; ++k) {
                int xx = x0 - 1 + k;
                p[k] = ldz4(row + xx*4, (unsigned)xx < (unsigned)R);
            }
            if (iy <= 2) {
                #pragma unroll
                for (int j = 0; j < 4; ++j)
                    #pragma unroll
                    for (int kx = 0; kx < 3; ++kx)
                        a0[j] = dot4a(a0[j], &wr[(iy*3+kx)*4], p[j+kx]);
            }
            if (iy >= 1) {
                #pragma unroll
                for (int j = 0; j < 4; ++j)
                    #pragma unroll
                    for (int kx = 0; kx < 3; ++kx)
                        a1[j] = dot4a(a1[j], &wr[((iy-1)*3+kx)*4], p[j+kx]);
            }
        }
        int base0 = (y0*R + x0)*4 + o, base1 = base0 + R*4;
        #pragma unroll
        for (int j = 0; j < 4; ++j) {
            if (MODE == 0 || ST) { outPre[base0 + j*4] = a0[j]; outPre[base1 + j*4] = a1[j]; }
            if constexpr (MODE == 1) {
                outAct[base0 + j*4] = swish_f(a0[j]);
                outAct[base1 + j*4] = swish_f(a1[j]);
            }
        }
    }
}

// ============================================================================
// convup: 4->4 NHWC, fused 2x nearest upsample; act always, pre if ST.
// Thread fixed (o, parity); 2 output rows (same parity) per item.
// ============================================================================
template<int R,bool ST>
__device__ __noinline__ void convup(const float* __restrict__ in, const float* __restrict__ w,
                                    const float* __restrict__ b, float* __restrict__ outPre,
                                    float* __restrict__ outAct)
{
    constexpr int NX = R/4, H = R/2;
    const int o = threadIdx.x & 3;
    const int parity = (threadIdx.x >> 2) & 1;
    float FU[32];   // [set][q][c], set 0 = A(top), 1 = B(bottom); q: u0,u2,u01,u12
    #pragma unroll
    for (int c = 0; c < 4; ++c) {
        const float* wb = w + (o*4 + c)*9;
        float A0,A1,A2,B0,B1,B2;
        if (!parity) { A0=wb[0];A1=wb[1];A2=wb[2]; B0=wb[3]+wb[6];B1=wb[4]+wb[7];B2=wb[5]+wb[8]; }
        else         { A0=wb[0]+wb[3];A1=wb[1]+wb[4];A2=wb[2]+wb[5]; B0=wb[6];B1=wb[7];B2=wb[8]; }
        FU[0*4+c]=A0;  FU[1*4+c]=A2;  FU[2*4+c]=A0+A1; FU[3*4+c]=A1+A2;
        FU[16+0*4+c]=B0; FU[16+1*4+c]=B2; FU[16+2*4+c]=B0+B1; FU[16+3*4+c]=B1+B2;
    }
    const float bb = b[o];
    constexpr int ITEMS = 8*(H/2)*NX;
    for (int t = threadIdx.x; t < ITEMS; t += NT) {
        int q = t >> 3;
        int xv = q % NX, yhp = q / NX;
        int yh0 = 2*yhp, x0 = xv*4, hx = x0>>1;
        float a0[4] = {bb,bb,bb,bb};
        float a1[4] = {bb,bb,bb,bb};
        #pragma unroll
        for (int rr = 0; rr < 3; ++rr) {
            int srow_i = yh0 - 1 + parity + rr;
            if ((unsigned)srow_i >= (unsigned)H) continue;
            const float* srow = in + srow_i*H*4;
            float4 s0 = ldz4(srow + (hx-1)*4, hx > 0);
            float4 s1 = *reinterpret_cast<const float4*>(srow + hx*4);
            float4 s2 = *reinterpret_cast<const float4*>(srow + (hx+1)*4);
            float4 s3 = ldz4(srow + (hx+2)*4, hx+2 < H);
            if (rr <= 1) {  // out0: A from rr=0, B from rr=1
                const float* F = FU + rr*16;
                a0[0] = dot4a(dot4a(a0[0], F+0*4, s0), F+3*4, s1);
                a0[1] = dot4a(dot4a(a0[1], F+2*4, s1), F+1*4, s2);
                a0[2] = dot4a(dot4a(a0[2], F+0*4, s1), F+3*4, s2);
                a0[3] = dot4a(dot4a(a0[3], F+2*4, s2), F+1*4, s3);
            }
            if (rr >= 1) {  // out1: A from rr=1, B from rr=2
                const float* F = FU + (rr-1)*16;
                a1[0] = dot4a(dot4a(a1[0], F+0*4, s0), F+3*4, s1);
                a1[1] = dot4a(dot4a(a1[1], F+2*4, s1), F+1*4, s2);
                a1[2] = dot4a(dot4a(a1[2], F+0*4, s1), F+3*4, s2);
                a1[3] = dot4a(dot4a(a1[3], F+2*4, s2), F+1*4, s3);
            }
        }
        int y0 = 2*yh0 + parity;
        int base0 = (y0*R + x0)*4 + o, base1 = base0 + 2*R*4;
        #pragma unroll
        for (int j = 0; j < 4; ++j) {
            if (ST) { outPre[base0 + j*4] = a0[j]; outPre[base1 + j*4] = a1[j]; }
            outAct[base0 + j*4] = swish_f(a0[j]);
            outAct[base1 + j*4] = swish_f(a1[j]);
        }
    }
}

// ============================================================================
// convfin: 4->1, NHWC in, planar out, 2-row blocked. MODE 0: y. 2: dy.
// ============================================================================
template<int R,int MODE>
__device__ __noinline__ void convfin(const float* __restrict__ in, const float* __restrict__ w,
                                     float b0, float* __restrict__ outp,
                                     const float* __restrict__ xref)
{
    constexpr int NX = R/4;
    float wr[36];
    #pragma unroll
    for (int k = 0; k < 9; ++k)
        #pragma unroll
        for (int c = 0; c < 4; ++c) wr[k*4+c] = w[c*9+k];
    for (int t = threadIdx.x; t < (R/2)*NX; t += NT) {
        int xv = t % NX, yp = t / NX, x0 = xv*4, y0 = 2*yp;
        float a0[4] = {b0,b0,b0,b0};
        float a1[4] = {b0,b0,b0,b0};
        #pragma unroll
        for (int iy = 0; iy < 4; ++iy) {
            int yy = y0 - 1 + iy; if ((unsigned)yy >= (unsigned)R) continue;
            const float* row = in + yy*R*4;
            float4 p[6];
            #pragma unroll
            for (int k = 0; k < 6; ++k) {
                int xx = x0 - 1 + k;
                p[k] = ldz4(row + xx*4, (unsigned)xx < (unsigned)R);
            }
            if (iy <= 2) {
                #pragma unroll
                for (int j = 0; j < 4; ++j)
                    #pragma unroll
                    for (int kx = 0; kx < 3; ++kx)
                        a0[j] = dot4a(a0[j], &wr[(iy*3+kx)*4], p[j+kx]);
            }
            if (iy >= 1) {
                #pragma unroll
                for (int j = 0; j < 4; ++j)
                    #pragma unroll
                    for (int kx = 0; kx < 3; ++kx)
                        a1[j] = dot4a(a1[j], &wr[((iy-1)*3+kx)*4], p[j+kx]);
            }
        }
        #pragma unroll
        for (int rr = 0; rr < 2; ++rr) {
            float* a = rr ? a1 : a0;
            int y = y0 + rr;
            float4 ov;
            if constexpr (MODE == 2) {
                float4 xr = *reinterpret_cast<const float4*>(xref + y*R + x0);
                ov = make_float4((a[0]-xr.x)*DYSCALE,(a[1]-xr.y)*DYSCALE,(a[2]-xr.z)*DYSCALE,(a[3]-xr.w)*DYSCALE);
            } else {
                ov = make_float4(a[0],a[1],a[2],a[3]);
            }
            *reinterpret_cast<float4*>(outp + y*R + x0) = ov;
        }
    }
}

// ============================================================================
// pool 2x2 of swish(u), NHWC; argmax stored only if ST
// ============================================================================
template<int R,bool ST>
__device__ __noinline__ void pool_swishv(const float* __restrict__ u, float* __restrict__ p,
                                         unsigned char* __restrict__ idx)
{
    constexpr int Ro = R/2;
    for (int t = threadIdx.x; t < Ro*Ro; t += NT) {
        int x = t % Ro, y = t / Ro;
        int base = ((2*y)*R + 2*x)*4;
        float4 A = *reinterpret_cast<const float4*>(u + base);
        float4 B = *reinterpret_cast<const float4*>(u + base + 4);
        float4 C = *reinterpret_cast<const float4*>(u + base + R*4);
        float4 D = *reinterpret_cast<const float4*>(u + base + R*4 + 4);
        float va[4]={A.x,A.y,A.z,A.w}, vb[4]={B.x,B.y,B.z,B.w};
        float vc[4]={C.x,C.y,C.z,C.w}, vd[4]={D.x,D.y,D.z,D.w};
        float pm[4]; unsigned char im[4];
        #pragma unroll
        for (int c = 0; c < 4; ++c) {
            float v0 = swish_f(va[c]), v1 = swish_f(vb[c]);
            float v2 = swish_f(vc[c]), v3 = swish_f(vd[c]);
            float m = v0; int id = 0;
            if (v1 > m) { m = v1; id = 1; }
            if (v2 > m) { m = v2; id = 2; }
            if (v3 > m) { m = v3; id = 3; }
            pm[c] = m; im[c] = (unsigned char)id;
        }
        int ob = (y*Ro + x)*4;
        *reinterpret_cast<float4*>(p + ob) = make_float4(pm[0],pm[1],pm[2],pm[3]);
        if (ST) *reinterpret_cast<uchar4*>(idx + ob) = make_uchar4(im[0],im[1],im[2],im[3]);
    }
}

// ---- pool backward scatter fused with swish', NHWC ----
template<int R>
__device__ __noinline__ void pool_bwdv(const float* __restrict__ dp, const unsigned char* __restrict__ idx,
                                       const float* __restrict__ u, float* __restrict__ du)
{
    constexpr int H = R/2;
    for (int t = threadIdx.x; t < R*H; t += NT) {
        int xh = t % H, y = t / H;
        int cell = ((y>>1)*H + xh)*4;
        float4 d4 = *reinterpret_cast<const float4*>(dp + cell);
        uchar4 i4 = *reinterpret_cast<const uchar4*>(idx + cell);
        float dv[4]={d4.x,d4.y,d4.z,d4.w};
        unsigned char iv[4]={i4.x,i4.y,i4.z,i4.w};
        int sb = (y & 1) << 1;
        #pragma unroll
        for (int s = 0; s < 2; ++s) {
            int x = 2*xh + s;
            float4 u4 = *reinterpret_cast<const float4*>(u + (y*R + x)*4);
            float uv[4]={u4.x,u4.y,u4.z,u4.w};
            float ov[4];
            #pragma unroll
            for (int c = 0; c < 4; ++c) {
                float g = (iv[c] == (unsigned char)(sb+s)) ? dv[c] : 0.f;
                ov[c] = g * swish_d(uv[c]);
            }
            *reinterpret_cast<float4*>(du + (y*R + x)*4) = make_float4(ov[0],ov[1],ov[2],ov[3]);
        }
    }
}

// ============================================================================
// dgrad of final conv: planar dout -> NHWC din, fused swish'(V4). 2-row blocked.
// ============================================================================
template<int R>
__device__ __noinline__ void dgrad_fin(const float* __restrict__ dout, const float* __restrict__ w,
                                       const float* __restrict__ upre, float* __restrict__ din)
{
    constexpr int NX = R/4;
    float wf[36];
    #pragma unroll
    for (int k = 0; k < 9; ++k)
        #pragma unroll
        for (int c = 0; c < 4; ++c) wf[k*4+c] = w[c*9 + 8-k];
    for (int t = threadIdx.x; t < (R/2)*NX; t += NT) {
        int xv = t % NX, yp = t / NX, x0 = xv*4, y0 = 2*yp;
        float4 a0[4] = {};
        float4 a1[4] = {};
        #pragma unroll
        for (int iy = 0; iy < 4; ++iy) {
            int yy = y0 - 1 + iy; if ((unsigned)yy >= (unsigned)R) continue;
            const float* row = dout + yy*R;
            float4 v = *reinterpret_cast<const float4*>(row + x0);
            float s[6];
            s[0] = (x0 > 0)   ? row[x0-1] : 0.f;
            s[1]=v.x; s[2]=v.y; s[3]=v.z; s[4]=v.w;
            s[5] = (x0+4 < R) ? row[x0+4] : 0.f;
            if (iy <= 2) {
                #pragma unroll
                for (int j = 0; j < 4; ++j)
                    #pragma unroll
                    for (int kx = 0; kx < 3; ++kx)
                        axpy4(a0[j], s[j+kx], &wf[(iy*3+kx)*4]);
            }
            if (iy >= 1) {
                #pragma unroll
                for (int j = 0; j < 4; ++j)
                    #pragma unroll
                    for (int kx = 0; kx < 3; ++kx)
                        axpy4(a1[j], s[j+kx], &wf[((iy-1)*3+kx)*4]);
            }
        }
        #pragma unroll
        for (int rr = 0; rr < 2; ++rr) {
            float4* a = rr ? a1 : a0;
            int base = ((y0+rr)*R + x0)*4;
            #pragma unroll
            for (int j = 0; j < 4; ++j) {
                float4 u4 = *reinterpret_cast<const float4*>(upre + base + j*4);
                a[j].x *= swish_d(u4.x); a[j].y *= swish_d(u4.y);
                a[j].z *= swish_d(u4.z); a[j].w *= swish_d(u4.w);
                *reinterpret_cast<float4*>(din + base + j*4) = a[j];
            }
        }
    }
}

// ============================================================================
// dgrad 4->4 NHWC (encoder; no fuse), 2-row blocked
// ============================================================================
template<int R>
__device__ __noinline__ void dgrad4(const float* __restrict__ dout, const float* __restrict__ w,
                                    float* __restrict__ din)
{
    constexpr int NX = R/4;
    const int c = threadIdx.x & 3;
    float wf[36];
    #pragma unroll
    for (int k = 0; k < 9; ++k)
        #pragma unroll
        for (int o = 0; o < 4; ++o) wf[k*4+o] = w[(o*4+c)*9 + 8-k];
    for (int t = threadIdx.x; t < 4*(R/2)*NX; t += NT) {
        int r2 = t >> 2;
        int xv = r2 % NX, yp = r2 / NX, x0 = xv*4, y0 = 2*yp;
        float a0[4] = {};
        float a1[4] = {};
        #pragma unroll
        for (int iy = 0; iy < 4; ++iy) {
            int yy = y0 - 1 + iy; if ((unsigned)yy >= (unsigned)R) continue;
            const float* row = dout + yy*R*4;
            float4 p[6];
            #pragma unroll
            for (int k = 0; k < 6; ++k) {
                int xx = x0 - 1 + k;
                p[k] = ldz4(row + xx*4, (unsigned)xx < (unsigned)R);
            }
            if (iy <= 2) {
                #pragma unroll
                for (int j = 0; j < 4; ++j)
                    #pragma unroll
                    for (int kx = 0; kx < 3; ++kx)
                        a0[j] = dot4a(a0[j], &wf[(iy*3+kx)*4], p[j+kx]);
            }
            if (iy >= 1) {
                #pragma unroll
                for (int j = 0; j < 4; ++j)
                    #pragma unroll
                    for (int kx = 0; kx < 3; ++kx)
                        a1[j] = dot4a(a1[j], &wf[((iy-1)*3+kx)*4], p[j+kx]);
            }
        }
        int base0 = (y0*R + x0)*4 + c, base1 = base0 + R*4;
        #pragma unroll
        for (int j = 0; j < 4; ++j) { din[base0 + j*4] = a0[j]; din[base1 + j*4] = a1[j]; }
    }
}

// ============================================================================
// backward of (up -> conv): NHWC dout at R -> NHWC din at H, effective 4x4
// kernel wE = flip(w) * box2x2; fused swish'(upre).
// ============================================================================
template<int R>
__device__ __noinline__ void dupv(const float* __restrict__ dout, const float* __restrict__ w,
                                  const float* __restrict__ upre, float* __restrict__ din)
{
    constexpr int H = R/2, NXH = H/4;
    const int c = threadIdx.x & 3;
    float wE[64];   // [i*4+kk][o]
    #pragma unroll
    for (int o = 0; o < 4; ++o) {
        const float* wb = w + (o*4 + c)*9;
        #pragma unroll
        for (int i = 0; i < 4; ++i)
            #pragma unroll
            for (int j = 0; j < 4; ++j) {
                float s = 0.f;
                #pragma unroll
                for (int sy = 0; sy < 2; ++sy) {
                    int a = sy + 2 - i; if (a < 0 || a > 2) continue;
                    #pragma unroll
                    for (int sx = 0; sx < 2; ++sx) {
                        int bc = sx + 2 - j; if (bc < 0 || bc > 2) continue;
                        s += wb[a*3 + bc];
                    }
                }
                wE[(i*4+j)*4 + o] = s;
            }
    }
    for (int t = threadIdx.x; t < 4*H*NXH; t += NT) {
        int r2 = t >> 2;
        int vv = r2 % NXH, u = r2 / NXH, v0 = vv*4;
        int r0 = 2*u - 1;
        float a[4] = {};
        #pragma unroll
        for (int i = 0; i < 4; ++i) {
            int rr = r0 + i; if ((unsigned)rr >= (unsigned)R) continue;
            const float* row = dout + rr*R*4;
            float4 q[10];
            #pragma unroll
            for (int m = 0; m < 10; ++m) {
                int px = 2*v0 - 1 + m;
                q[m] = ldz4(row + px*4, (unsigned)px < (unsigned)R);
            }
            #pragma unroll
            for (int j = 0; j < 4; ++j)
                #pragma unroll
                for (int kk = 0; kk < 4; ++kk)
                    a[j] = dot4a(a[j], &wE[(i*4+kk)*4], q[2*j+kk]);
        }
        int base = (u*H + v0)*4 + c;
        #pragma unroll
        for (int j = 0; j < 4; ++j) {
            float up = upre[base + j*4];
            din[base + j*4] = a[j] * swish_d(up);
        }
    }
}

// ============================================================================
// wgrad 4->4 (NHWC dout; in NHWC at R or, UP, at H); in-place smem update
// ============================================================================
template<int R,bool UP>
__device__ __noinline__ void wgrad4(const float* __restrict__ dout, const float* __restrict__ in,
                                    float* wDst, float* bDst, float* sRed)
{
    constexpr int NX = R/4, H = R/2;
    for (int i = threadIdx.x; i < 148; i += NT) sRed[i] = 0.f;
    __syncthreads();
    const int o = threadIdx.x & 3;
    float acc[36]; float accb = 0.f;
    #pragma unroll
    for (int i = 0; i < 36; ++i) acc[i] = 0.f;

    for (int pv = threadIdx.x >> 2; pv < R*NX; pv += NT >> 2) {
        int y = pv / NX, x0 = (pv % NX)*4;
        const float* db = dout + (y*R + x0)*4 + o;
        float g0 = db[0], g1 = db[4], g2 = db[8], g3 = db[12];
        accb += g0+g1+g2+g3;
        float g01 = g0+g1, g12 = g1+g2, g23 = g2+g3;
        #pragma unroll
        for (int ky = 0; ky < 3; ++ky) {
            int yy = y + ky - 1; if ((unsigned)yy >= (unsigned)R) continue;
            if constexpr (UP) {
                const float* srow = in + (yy>>1)*H*4;
                int hx = x0 >> 1;
                float4 s0 = ldz4(srow + (hx-1)*4, hx > 0);
                float4 s1 = *reinterpret_cast<const float4*>(srow + hx*4);
                float4 s2 = *reinterpret_cast<const float4*>(srow + (hx+1)*4);
                float4 s3 = ldz4(srow + (hx+2)*4, hx+2 < H);
                accum4(&acc[ky*3+0], g0, s0); accum4(&acc[ky*3+0], g12, s1); accum4(&acc[ky*3+0], g3, s2);
                accum4(&acc[ky*3+1], g01, s1); accum4(&acc[ky*3+1], g23, s2);
                accum4(&acc[ky*3+2], g0, s1); accum4(&acc[ky*3+2], g12, s2); accum4(&acc[ky*3+2], g3, s3);
            } else {
                const float* row = in + yy*R*4;
                float4 p[6];
                #pragma unroll
                for (int k = 0; k < 6; ++k) {
                    int xx = x0 - 1 + k;
                    p[k] = ldz4(row + xx*4, (unsigned)xx < (unsigned)R);
                }
                float g[4] = {g0,g1,g2,g3};
                #pragma unroll
                for (int kx = 0; kx < 3; ++kx)
                    #pragma unroll
                    for (int j = 0; j < 4; ++j)
                        accum4(&acc[ky*3+kx], g[j], p[j+kx]);
            }
        }
    }
    unsigned lane = threadIdx.x & 31;
    #pragma unroll
    for (int off = 16; off >= 4; off >>= 1) {
        #pragma unroll
        for (int i = 0; i < 36; ++i) acc[i] += __shfl_xor_sync(0xffffffffu, acc[i], off);
        accb += __shfl_xor_sync(0xffffffffu, accb, off);
    }
    if (lane < 4) {
        #pragma unroll
        for (int i = 0; i < 36; ++i) atomicAdd(&sRed[o*36 + i], acc[i]);
        atomicAdd(&sRed[144 + o], accb);
    }
    __syncthreads();
    for (int i = threadIdx.x; i < 144; i += NT) wDst[i] -= LRATE * sRed[i];
    if (threadIdx.x < 4) bDst[threadIdx.x] -= LRATE * sRed[144 + threadIdx.x];
}

// ---- wgrad of final conv (planar dout, NHWC in, COUT=1) ----
template<int R>
__device__ __noinline__ void wgrad_fin(const float* __restrict__ dout, const float* __restrict__ in,
                                       float* wDst, float* bDst, float* sRed)
{
    constexpr int NX = R/4;
    for (int i = threadIdx.x; i < 37; i += NT) sRed[i] = 0.f;
    __syncthreads();
    float acc[36]; float accb = 0.f;
    #pragma unroll
    for (int i = 0; i < 36; ++i) acc[i] = 0.f;
    for (int pv = threadIdx.x; pv < R*NX; pv += NT) {
        int y = pv / NX, x0 = (pv % NX)*4;
        float4 g = *reinterpret_cast<const float4*>(dout + y*R + x0);
        float gv[4] = {g.x,g.y,g.z,g.w};
        accb += g.x+g.y+g.z+g.w;
        #pragma unroll
        for (int ky = 0; ky < 3; ++ky) {
            int yy = y + ky - 1; if ((unsigned)yy >= (unsigned)R) continue;
            const float* row = in + yy*R*4;
            float4 p[6];
            #pragma unroll
            for (int k = 0; k < 6; ++k) {
                int xx = x0 - 1 + k;
                p[k] = ldz4(row + xx*4, (unsigned)xx < (unsigned)R);
            }
            #pragma unroll
            for (int kx = 0; kx < 3; ++kx)
                #pragma unroll
                for (int j = 0; j < 4; ++j)
                    accum4(&acc[ky*3+kx], gv[j], p[j+kx]);
        }
    }
    unsigned lane = threadIdx.x & 31;
    #pragma unroll
    for (int off = 16; off >= 1; off >>= 1) {
        #pragma unroll
        for (int i = 0; i < 36; ++i) acc[i] += __shfl_xor_sync(0xffffffffu, acc[i], off);
        accb += __shfl_xor_sync(0xffffffffu, accb, off);
    }
    if (lane == 0) {
        #pragma unroll
        for (int i = 0; i < 36; ++i) atomicAdd(&sRed[i], acc[i]);
        atomicAdd(&sRed[36], accb);
    }
    __syncthreads();
    for (int i = threadIdx.x; i < 36; i += NT) wDst[i] -= LRATE * sRed[i];
    if (threadIdx.x == 0) bDst[0] -= LRATE * sRed[36];
}

// ---- wgrad of first conv (NHWC dout, planar in, CIN=1) ----
template<int R>
__device__ __noinline__ void wgrad_first(const float* __restrict__ dout, const float* __restrict__ in,
                                         float* wDst, float* bDst, float* sRed)
{
    constexpr int NX = R/4;
    for (int i = threadIdx.x; i < 40; i += NT) sRed[i] = 0.f;
    __syncthreads();
    const int o = threadIdx.x & 3;
    float acc[9]; float accb = 0.f;
    #pragma unroll
    for (int i = 0; i < 9; ++i) acc[i] = 0.f;
    for (int pv = threadIdx.x >> 2; pv < R*NX; pv += NT >> 2) {
        int y = pv / NX, x0 = (pv % NX)*4;
        const float* db = dout + (y*R + x0)*4 + o;
        float g[4] = {db[0], db[4], db[8], db[12]};
        accb += g[0]+g[1]+g[2]+g[3];
        #pragma unroll
        for (int ky = 0; ky < 3; ++ky) {
            int yy = y + ky - 1; if ((unsigned)yy >= (unsigned)R) continue;
            const float* row = in + yy*R;
            float4 v = *reinterpret_cast<const float4*>(row + x0);
            float s[6];
            s[0] = (x0 > 0)   ? row[x0-1] : 0.f;
            s[1]=v.x; s[2]=v.y; s[3]=v.z; s[4]=v.w;
            s[5] = (x0+4 < R) ? row[x0+4] : 0.f;
            #pragma unroll
            for (int kx = 0; kx < 3; ++kx) {
                float t = 0.f;
                #pragma unroll
                for (int j = 0; j < 4; ++j) t = fmaf(g[j], s[j+kx], t);
                acc[ky*3+kx] += t;
            }
        }
    }
    unsigned lane = threadIdx.x & 31;
    #pragma unroll
    for (int off = 16; off >= 4; off >>= 1) {
        #pragma unroll
        for (int i = 0; i < 9; ++i) acc[i] += __shfl_xor_sync(0xffffffffu, acc[i], off);
        accb += __shfl_xor_sync(0xffffffffu, accb, off);
    }
    if (lane < 4) {
        #pragma unroll
        for (int i = 0; i < 9; ++i) atomicAdd(&sRed[o*9 + i], acc[i]);
        atomicAdd(&sRed[36 + o], accb);
    }
    __syncthreads();
    for (int i = threadIdx.x; i < 36; i += NT) wDst[i] -= LRATE * sRed[i];
    if (threadIdx.x < 4) bDst[threadIdx.x] -= LRATE * sRed[36 + threadIdx.x];
}

// ---- full forward pass; FIRST: store pre-activations/argmax for backward ----
template<bool FIRST>
__device__ __noinline__ void forward_pass(const float* __restrict__ x, const float* sP,
                                          float* S, unsigned char* I,
                                          float* __restrict__ ydst)
{
    conv0<128>(x, sP+PW0, sP+PEB, S+OFF_U0);                                      __syncthreads();
    pool_swishv<128,FIRST>(S+OFF_U0, S+OFF_P0, I+IX0);                            __syncthreads();
    conv4<64,0,FIRST>(S+OFF_P0, sP+PEW,     sP+PEB+4,  S+OFF_U1, nullptr);        __syncthreads();
    pool_swishv<64,FIRST>(S+OFF_U1, S+OFF_P1, I+IX1);                             __syncthreads();
    conv4<32,0,FIRST>(S+OFF_P1, sP+PEW+144, sP+PEB+8,  S+OFF_U2, nullptr);        __syncthreads();
    pool_swishv<32,FIRST>(S+OFF_U2, S+OFF_P2, I+IX2);                             __syncthreads();
    conv4<16,0,FIRST>(S+OFF_P2, sP+PEW+288, sP+PEB+12, S+OFF_U3, nullptr);        __syncthreads();
    pool_swishv<16,FIRST>(S+OFF_U3, S+OFF_P3, I+IX3);                             __syncthreads();
    conv4<8,0,FIRST> (S+OFF_P3, sP+PEW+432, sP+PEB+16, S+OFF_U4, nullptr);        __syncthreads();
    pool_swishv<8,FIRST>(S+OFF_U4, S+OFF_P4, I+IX4);                              __syncthreads();
    conv4<4,1,FIRST> (S+OFF_P4, sP+PEW+576, sP+PEB+20, S+OFF_U5, S+OFF_F);        __syncthreads();

    if (threadIdx.x < 32) {
        float acc = sP[PLEB + threadIdx.x];
        for (int j = 0; j < 64; ++j) acc += sP[PLEW + threadIdx.x*64 + j] * S[OFF_F + nh(j)];
        if (FIRST) S[OFF_ZU + threadIdx.x] = acc;
        S[OFF_Z  + threadIdx.x] = swish_f(acc);
    }
    __syncthreads();
    if (threadIdx.x < 64) {
        float acc = sP[PLDB + threadIdx.x];
        for (int j = 0; j < 32; ++j) acc += sP[PLDW + threadIdx.x*32 + j] * S[OFF_Z + j];
        if (FIRST) S[OFF_DU + nh(threadIdx.x)] = acc;
        S[OFF_DD + nh(threadIdx.x)] = swish_f(acc);
    }
    __syncthreads();

    convup<8,FIRST>  (S+OFF_DD, sP+PDW,     sP+PDB,    S+OFF_V0, S+OFF_Q0);       __syncthreads();
    convup<16,FIRST> (S+OFF_Q0, sP+PDW+144, sP+PDB+4,  S+OFF_V1, S+OFF_Q1);       __syncthreads();
    convup<32,FIRST> (S+OFF_Q1, sP+PDW+288, sP+PDB+8,  S+OFF_V2, S+OFF_Q2);       __syncthreads();
    convup<64,FIRST> (S+OFF_Q2, sP+PDW+432, sP+PDB+12, S+OFF_V3, S+OFF_Q3);       __syncthreads();
    convup<128,FIRST>(S+OFF_Q3, sP+PDW+576, sP+PDB+16, S+OFF_V4, S+OFF_Q4);       __syncthreads();

    if (FIRST) convfin<128,2>(S+OFF_Q4, sP+PWO, sP[PBO], ydst, x);
    else       convfin<128,0>(S+OFF_Q4, sP+PWO, sP[PBO], ydst, nullptr);
    __syncthreads();
}

__global__ __launch_bounds__(NT, 1)
void maml_kernel(const float* __restrict__ x_all,
                 const float* __restrict__ enc_w0,   const float* __restrict__ enc_w,
                 const float* __restrict__ enc_b,    const float* __restrict__ enc_lin_w,
                 const float* __restrict__ enc_lin_b,const float* __restrict__ dec_lin_w,
                 const float* __restrict__ dec_lin_b,const float* __restrict__ dec_w,
                 const float* __restrict__ dec_b,    const float* __restrict__ dec_w_out,
                 const float* __restrict__ dec_b_out,float* __restrict__ out)
{
    __shared__ float sP[NPARAM];
    __shared__ float sRed[160];
    const int s = blockIdx.x;
    float* S = g_scratch + (size_t)s * SSC;
    unsigned char* I = g_idxbuf + s * SIDX;
    const float* x = x_all + (size_t)s * 16384;

    for (int i = threadIdx.x; i < 36;   i += NT) sP[PW0 +i] = enc_w0[i];
    for (int i = threadIdx.x; i < 24;   i += NT) sP[PEB +i] = enc_b[i];
    for (int i = threadIdx.x; i < 720;  i += NT) sP[PEW +i] = enc_w[i];
    for (int i = threadIdx.x; i < 2048; i += NT) sP[PLEW+i] = enc_lin_w[i];
    for (int i = threadIdx.x; i < 32;   i += NT) sP[PLEB+i] = enc_lin_b[i];
    for (int i = threadIdx.x; i < 2048; i += NT) sP[PLDW+i] = dec_lin_w[i];
    for (int i = threadIdx.x; i < 64;   i += NT) sP[PLDB+i] = dec_lin_b[i];
    for (int i = threadIdx.x; i < 720;  i += NT) sP[PDW +i] = dec_w[i];
    for (int i = threadIdx.x; i < 20;   i += NT) sP[PDB +i] = dec_b[i];
    for (int i = threadIdx.x; i < 36;   i += NT) sP[PWO +i] = dec_w_out[i];
    if (threadIdx.x == 0) sP[PBO] = dec_b_out[0];
    __syncthreads();

    // ===== forward #1 =====
    forward_pass<true>(x, sP, S, I, S + OFF_DY);

    float* GA = S + OFF_GA;
    float* GB = S + OFF_GB;

    // ===== backward =====
    dgrad_fin<128>(S+OFF_DY, sP+PWO, S+OFF_V4, GA);                         __syncthreads();
    wgrad_fin<128>(S+OFF_DY, S+OFF_Q4, sP+PWO, sP+PBO, sRed);               __syncthreads();

    dupv<128>(GA, sP+PDW+576, S+OFF_V3, GB);                                __syncthreads();
    wgrad4<128,true>(GA, S+OFF_Q3, sP+PDW+576, sP+PDB+16, sRed);            __syncthreads();
    dupv<64>(GB, sP+PDW+432, S+OFF_V2, GA);                                 __syncthreads();
    wgrad4<64,true>(GB, S+OFF_Q2, sP+PDW+432, sP+PDB+12, sRed);             __syncthreads();
    dupv<32>(GA, sP+PDW+288, S+OFF_V1, GB);                                 __syncthreads();
    wgrad4<32,true>(GA, S+OFF_Q1, sP+PDW+288, sP+PDB+8, sRed);              __syncthreads();
    dupv<16>(GB, sP+PDW+144, S+OFF_V0, GA);                                 __syncthreads();
    wgrad4<16,true>(GB, S+OFF_Q0, sP+PDW+144, sP+PDB+4, sRed);              __syncthreads();
    dupv<8>(GA, sP+PDW, S+OFF_DU, GB);                                      __syncthreads();  // GB = ddu (NHWC, 64)
    wgrad4<8,true>(GA, S+OFF_DD, sP+PDW, sP+PDB, sRed);                     __syncthreads();

    // dec_lin backward (ddu NHWC in GB)
    if (threadIdx.x < 32) {
        float acc = 0.f;
        for (int i = 0; i < 64; ++i) acc += sP[PLDW + i*32 + threadIdx.x] * GB[nh(i)];
        GA[threadIdx.x] = acc;                       // dz (plain)
    }
    __syncthreads();
    for (int t = threadIdx.x; t < 2048; t += NT) {
        int i = t >> 5, j = t & 31;
        sP[PLDW + t] -= LRATE * GB[nh(i)] * S[OFF_Z + j];
    }
    if (threadIdx.x < 64) sP[PLDB + threadIdx.x] -= LRATE * GB[nh(threadIdx.x)];
    __syncthreads();
    if (threadIdx.x < 32) GB[threadIdx.x] = GA[threadIdx.x] * swish_d(S[OFF_ZU + threadIdx.x]); // dzu (plain)
    __syncthreads();
    if (threadIdx.x < 64) {
        float acc = 0.f;
        for (int i = 0; i < 32; ++i) acc += sP[PLEW + i*64 + threadIdx.x] * GB[i];
        int ni = nh(threadIdx.x);
        GA[ni] = acc * swish_d(S[OFF_U5 + ni]);      // du5 (NHWC)
    }
    __syncthreads();
    for (int t = threadIdx.x; t < 2048; t += NT) {
        int i = t >> 6, j = t & 63;
        sP[PLEW + t] -= LRATE * GB[i] * S[OFF_F + nh(j)];
    }
    if (threadIdx.x < 32) sP[PLEB + threadIdx.x] -= LRATE * GB[threadIdx.x];
    __syncthreads();

    // encoder backward (du5 in GA)
    dgrad4<4>(GA, sP+PEW+576, GB);                                          __syncthreads();
    wgrad4<4,false>(GA, S+OFF_P4, sP+PEW+576, sP+PEB+20, sRed);             __syncthreads();
    pool_bwdv<8>(GB, I+IX4, S+OFF_U4, GA);                                  __syncthreads();
    dgrad4<8>(GA, sP+PEW+432, GB);                                          __syncthreads();
    wgrad4<8,false>(GA, S+OFF_P3, sP+PEW+432, sP+PEB+16, sRed);             __syncthreads();
    pool_bwdv<16>(GB, I+IX3, S+OFF_U3, GA);                                 __syncthreads();
    dgrad4<16>(GA, sP+PEW+288, GB);                                         __syncthreads();
    wgrad4<16,false>(GA, S+OFF_P2, sP+PEW+288, sP+PEB+12, sRed);            __syncthreads();
    pool_bwdv<32>(GB, I+IX2, S+OFF_U2, GA);                                 __syncthreads();
    dgrad4<32>(GA, sP+PEW+144, GB);                                         __syncthreads();
    wgrad4<32,false>(GA, S+OFF_P1, sP+PEW+144, sP+PEB+8, sRed);             __syncthreads();
    pool_bwdv<64>(GB, I+IX1, S+OFF_U1, GA);                                 __syncthreads();
    dgrad4<64>(GA, sP+PEW, GB);                                             __syncthreads();
    wgrad4<64,false>(GA, S+OFF_P0, sP+PEW, sP+PEB+4, sRed);                 __syncthreads();
    pool_bwdv<128>(GB, I+IX0, S+OFF_U0, GA);                                __syncthreads();
    wgrad_first<128>(GA, x, sP+PW0, sP+PEB, sRed);                          __syncthreads();

    // ===== forward #2 with updated per-sample params =====
    forward_pass<false>(x, sP, S, I, out + (size_t)s * 16384);
}

extern "C" void kernel_launch(void* const* d_in, const int* in_sizes, int n_in,
                              void* d_out, int out_size)
{
    (void)in_sizes; (void)n_in; (void)out_size;
    maml_kernel<<<128, NT>>>(
        (const float*)d_in[0],  (const float*)d_in[1],  (const float*)d_in[2],
        (const float*)d_in[3],  (const float*)d_in[4],  (const float*)d_in[5],
        (const float*)d_in[6],  (const float*)d_in[7],  (const float*)d_in[8],
        (const float*)d_in[9],  (const float*)d_in[10], (const float*)d_in[11],
        (float*)d_out);
}

// round 6
// speedup vs baseline: 3.7217x; 1.0026x over previous
#include <cuda_runtime.h>
#include <cuda_bf16.h>

typedef __nv_bfloat16 bf16;

#define NT 512
constexpr float LRATE = 0.01f;
constexpr float DYSCALE = 2.0f / 2097152.0f;   // 2 / (B * 128*128)

// ---- fp32 arena offsets (floats): forward-path tensors ----
constexpr int OFF_P0=0,     OFF_P1=16384, OFF_P2=20480, OFF_P3=21504, OFF_P4=21760,
              OFF_F=21824,  OFF_Z=21888,  OFF_DD=21920, OFF_Q0=21984, OFF_Q1=22240,
              OFF_Q2=23264, OFF_Q3=27360, OFF_Q4=43744;
constexpr int SSCF = 109280;

// ---- bf16 arena offsets (halfs): gradient-path tensors ----
constexpr int HU0=0,      HU1=65536,  HU2=81920,  HU3=86016,  HU4=87040,  HU5=87296,
              HV0=87360,  HV1=87616,  HV2=88640,  HV3=92736,  HV4=109120,
              HZU=174656, HDU=174688, HDY=174752, HGA=191136, HGB=256672;
constexpr int SSCH = 273056;

constexpr int IX0=0, IX1=16384, IX2=20480, IX3=21504, IX4=21760, SIDX=21824;

__device__ float          g_scratch [128ull * SSCF];   // ~56 MB
__device__ bf16           g_scratchh[128ull * SSCH];   // ~70 MB
__device__ unsigned char  g_idxbuf[128 * SIDX];

// ---- smem param layout (floats) ----
constexpr int PW0=0, PEB=36, PEW=60, PLEW=780, PLEB=2828, PLDW=2860, PLDB=4908,
              PDW=4972, PDB=5692, PWO=5712, PBO=5748, NPARAM=5749;

__device__ __forceinline__ float tanhap(float x){ float y; asm("tanh.approx.f32 %0, %1;" : "=f"(y) : "f"(x)); return y; }
__device__ __forceinline__ float sigm(float u){ return fmaf(tanhap(0.5f*u), 0.5f, 0.5f); }
__device__ __forceinline__ float swish_f(float u){ return u * sigm(u); }
__device__ __forceinline__ float swish_d(float u){ float s = sigm(u); return s * fmaf(u, 1.0f - s, 1.0f); }

__device__ __forceinline__ float bf2f(bf16 v){ return __bfloat162float(v); }
__device__ __forceinline__ bf16  f2bf(float v){ return __float2bfloat16(v); }
__device__ __forceinline__ float4 ld4h(const bf16* p){
    __nv_bfloat162 a = reinterpret_cast<const __nv_bfloat162*>(p)[0];
    __nv_bfloat162 b = reinterpret_cast<const __nv_bfloat162*>(p)[1];
    return make_float4(__bfloat162float(a.x), __bfloat162float(a.y),
                       __bfloat162float(b.x), __bfloat162float(b.y));
}
__device__ __forceinline__ float4 ldz4h(const bf16* p, bool v){
    return v ? ld4h(p) : make_float4(0.f,0.f,0.f,0.f);
}
__device__ __forceinline__ void st4h(bf16* p, float4 v){
    reinterpret_cast<__nv_bfloat162*>(p)[0] = __floats2bfloat162_rn(v.x, v.y);
    reinterpret_cast<__nv_bfloat162*>(p)[1] = __floats2bfloat162_rn(v.z, v.w);
}

__device__ __forceinline__ float4 ldz4(const float* p, bool v){
    return v ? *reinterpret_cast<const float4*>(p) : make_float4(0.f,0.f,0.f,0.f);
}
__device__ __forceinline__ float dot4a(float a, const float* w, float4 p){
    return fmaf(w[0],p.x, fmaf(w[1],p.y, fmaf(w[2],p.z, fmaf(w[3],p.w, a))));
}
__device__ __forceinline__ void axpy4(float4& a, float s, const float* w){
    a.x = fmaf(s,w[0],a.x); a.y = fmaf(s,w[1],a.y); a.z = fmaf(s,w[2],a.z); a.w = fmaf(s,w[3],a.w);
}
__device__ __forceinline__ void accum4(float* accK, float g, float4 p){  // stride 9 over c
    accK[0]  = fmaf(g,p.x,accK[0]);  accK[9]  = fmaf(g,p.y,accK[9]);
    accK[18] = fmaf(g,p.z,accK[18]); accK[27] = fmaf(g,p.w,accK[27]);
}
__device__ __forceinline__ int nh(int i){ return ((i & 15) << 2) + (i >> 4); }  // chw(4x4) -> nhwc

__device__ __forceinline__ void pool1(float v0,float v1,float v2,float v3,
                                      float& m, unsigned char& id){
    v0 = swish_f(v0); v1 = swish_f(v1); v2 = swish_f(v2); v3 = swish_f(v3);
    m = v0; id = 0;
    if (v1 > m) { m = v1; id = 1; }
    if (v2 > m) { m = v2; id = 2; }
    if (v3 > m) { m = v3; id = 3; }
}

// ============================================================================
// conv0pool: 1->4 conv (planar in) fused with swish+2x2 maxpool.
// Writes U0h (bf16, FIRST only), pooled act P0 (fp32 NHWC), argmax (FIRST).
// ============================================================================
template<int R,bool FIRST>
__device__ __noinline__ void conv0pool(const float* __restrict__ in, const float* __restrict__ w,
                                       const float* __restrict__ b, bf16* __restrict__ uh,
                                       float* __restrict__ pOut, unsigned char* __restrict__ idx)
{
    constexpr int NX = R/4, Ro = R/2;
    float wr[36];
    #pragma unroll
    for (int k = 0; k < 9; ++k)
        #pragma unroll
        for (int o = 0; o < 4; ++o) wr[k*4+o] = w[o*9+k];
    const float4 bb = make_float4(b[0],b[1],b[2],b[3]);
    for (int t = threadIdx.x; t < (R/2)*NX; t += NT) {
        int xv = t % NX, yp = t / NX, x0 = xv*4, y0 = 2*yp;
        float4 a0[4] = {bb,bb,bb,bb};
        float4 a1[4] = {bb,bb,bb,bb};
        #pragma unroll
        for (int iy = 0; iy < 4; ++iy) {
            int yy = y0 - 1 + iy; if ((unsigned)yy >= (unsigned)R) continue;
            const float* row = in + yy*R;
            float4 v = *reinterpret_cast<const float4*>(row + x0);
            float s[6];
            s[0] = (x0 > 0)   ? row[x0-1] : 0.f;
            s[1]=v.x; s[2]=v.y; s[3]=v.z; s[4]=v.w;
            s[5] = (x0+4 < R) ? row[x0+4] : 0.f;
            if (iy <= 2) {
                #pragma unroll
                for (int j = 0; j < 4; ++j)
                    #pragma unroll
                    for (int kx = 0; kx < 3; ++kx)
                        axpy4(a0[j], s[j+kx], &wr[(iy*3+kx)*4]);
            }
            if (iy >= 1) {
                #pragma unroll
                for (int j = 0; j < 4; ++j)
                    #pragma unroll
                    for (int kx = 0; kx < 3; ++kx)
                        axpy4(a1[j], s[j+kx], &wr[((iy-1)*3+kx)*4]);
            }
        }
        if (FIRST) {
            int ub0 = (y0*R + x0)*4, ub1 = ub0 + R*4;
            #pragma unroll
            for (int j = 0; j < 4; ++j) { st4h(uh + ub0 + j*4, a0[j]); st4h(uh + ub1 + j*4, a1[j]); }
        }
        int xo = x0 >> 1;
        #pragma unroll
        for (int jj = 0; jj < 2; ++jj) {
            int j = 2*jj;
            float4 q00 = a0[j], q01 = a0[j+1], q10 = a1[j], q11 = a1[j+1];
            float pm[4]; unsigned char im[4];
            pool1(q00.x, q01.x, q10.x, q11.x, pm[0], im[0]);
            pool1(q00.y, q01.y, q10.y, q11.y, pm[1], im[1]);
            pool1(q00.z, q01.z, q10.z, q11.z, pm[2], im[2]);
            pool1(q00.w, q01.w, q10.w, q11.w, pm[3], im[3]);
            int ob = (yp*Ro + xo + jj)*4;
            *reinterpret_cast<float4*>(pOut + ob) = make_float4(pm[0],pm[1],pm[2],pm[3]);
            if (FIRST) *reinterpret_cast<uchar4*>(idx + ob) = make_uchar4(im[0],im[1],im[2],im[3]);
        }
    }
}

// ============================================================================
// conv4pool: 4->4 conv NHWC fused with swish+2x2 maxpool; thread owns o.
// ============================================================================
template<int R,bool FIRST>
__device__ __noinline__ void conv4pool(const float* __restrict__ in, const float* __restrict__ w,
                                       const float* __restrict__ b, bf16* __restrict__ uh,
                                       float* __restrict__ pOut, unsigned char* __restrict__ idx)
{
    constexpr int NX = R/4, Ro = R/2;
    const int o = threadIdx.x & 3;
    float wr[36];
    #pragma unroll
    for (int k = 0; k < 9; ++k)
        #pragma unroll
        for (int c = 0; c < 4; ++c) wr[k*4+c] = w[(o*4+c)*9+k];
    const float bb = b[o];
    for (int t = threadIdx.x; t < 4*(R/2)*NX; t += NT) {
        int r2 = t >> 2;
        int xv = r2 % NX, yp = r2 / NX, x0 = xv*4, y0 = 2*yp;
        float a0[4] = {bb,bb,bb,bb};
        float a1[4] = {bb,bb,bb,bb};
        #pragma unroll
        for (int iy = 0; iy < 4; ++iy) {
            int yy = y0 - 1 + iy; if ((unsigned)yy >= (unsigned)R) continue;
            const float* row = in + yy*R*4;
            float4 p[6];
            #pragma unroll
            for (int k = 0; k < 6; ++k) {
                int xx = x0 - 1 + k;
                p[k] = ldz4(row + xx*4, (unsigned)xx < (unsigned)R);
            }
            if (iy <= 2) {
                #pragma unroll
                for (int j = 0; j < 4; ++j)
                    #pragma unroll
                    for (int kx = 0; kx < 3; ++kx)
                        a0[j] = dot4a(a0[j], &wr[(iy*3+kx)*4], p[j+kx]);
            }
            if (iy >= 1) {
                #pragma unroll
                for (int j = 0; j < 4; ++j)
                    #pragma unroll
                    for (int kx = 0; kx < 3; ++kx)
                        a1[j] = dot4a(a1[j], &wr[((iy-1)*3+kx)*4], p[j+kx]);
            }
        }
        if (FIRST) {
            int ub0 = (y0*R + x0)*4 + o, ub1 = ub0 + R*4;
            #pragma unroll
            for (int j = 0; j < 4; ++j) { uh[ub0 + j*4] = f2bf(a0[j]); uh[ub1 + j*4] = f2bf(a1[j]); }
        }
        int xo = x0 >> 1;
        #pragma unroll
        for (int jj = 0; jj < 2; ++jj) {
            int j = 2*jj;
            float m; unsigned char id;
            pool1(a0[j], a0[j+1], a1[j], a1[j+1], m, id);
            int ob = (yp*Ro + xo + jj)*4 + o;
            pOut[ob] = m;
            if (FIRST) idx[ob] = id;
        }
    }
}

// ============================================================================
// conv4b: 4->4 NHWC (last encoder conv, R small): pre bf16 (FIRST), act fp32
// ============================================================================
template<int R,bool FIRST>
__device__ __noinline__ void conv4b(const float* __restrict__ in, const float* __restrict__ w,
                                    const float* __restrict__ b, bf16* __restrict__ outPre,
                                    float* __restrict__ outAct)
{
    constexpr int NX = R/4;
    const int o = threadIdx.x & 3;
    float wr[36];
    #pragma unroll
    for (int k = 0; k < 9; ++k)
        #pragma unroll
        for (int c = 0; c < 4; ++c) wr[k*4+c] = w[(o*4+c)*9+k];
    const float bb = b[o];
    for (int t = threadIdx.x; t < 4*(R/2)*NX; t += NT) {
        int r2 = t >> 2;
        int xv = r2 % NX, yp = r2 / NX, x0 = xv*4, y0 = 2*yp;
        float a0[4] = {bb,bb,bb,bb};
        float a1[4] = {bb,bb,bb,bb};
        #pragma unroll
        for (int iy = 0; iy < 4; ++iy) {
            int yy = y0 - 1 + iy; if ((unsigned)yy >= (unsigned)R) continue;
            const float* row = in + yy*R*4;
            float4 p[6];
            #pragma unroll
            for (int k = 0; k < 6; ++k) {
                int xx = x0 - 1 + k;
                p[k] = ldz4(row + xx*4, (unsigned)xx < (unsigned)R);
            }
            if (iy <= 2) {
                #pragma unroll
                for (int j = 0; j < 4; ++j)
                    #pragma unroll
                    for (int kx = 0; kx < 3; ++kx)
                        a0[j] = dot4a(a0[j], &wr[(iy*3+kx)*4], p[j+kx]);
            }
            if (iy >= 1) {
                #pragma unroll
                for (int j = 0; j < 4; ++j)
                    #pragma unroll
                    for (int kx = 0; kx < 3; ++kx)
                        a1[j] = dot4a(a1[j], &wr[((iy-1)*3+kx)*4], p[j+kx]);
            }
        }
        int base0 = (y0*R + x0)*4 + o, base1 = base0 + R*4;
        #pragma unroll
        for (int j = 0; j < 4; ++j) {
            if (FIRST) { outPre[base0 + j*4] = f2bf(a0[j]); outPre[base1 + j*4] = f2bf(a1[j]); }
            outAct[base0 + j*4] = swish_f(a0[j]);
            outAct[base1 + j*4] = swish_f(a1[j]);
        }
    }
}

// ============================================================================
// convup: 4->4 NHWC, fused 2x nearest upsample; act fp32 always, pre bf16 if ST
// ============================================================================
template<int R,bool ST>
__device__ __noinline__ void convup(const float* __restrict__ in, const float* __restrict__ w,
                                    const float* __restrict__ b, bf16* __restrict__ outPre,
                                    float* __restrict__ outAct)
{
    constexpr int NX = R/4, H = R/2;
    const int o = threadIdx.x & 3;
    const int parity = (threadIdx.x >> 2) & 1;
    float FU[32];
    #pragma unroll
    for (int c = 0; c < 4; ++c) {
        const float* wb = w + (o*4 + c)*9;
        float A0,A1,A2,B0,B1,B2;
        if (!parity) { A0=wb[0];A1=wb[1];A2=wb[2]; B0=wb[3]+wb[6];B1=wb[4]+wb[7];B2=wb[5]+wb[8]; }
        else         { A0=wb[0]+wb[3];A1=wb[1]+wb[4];A2=wb[2]+wb[5]; B0=wb[6];B1=wb[7];B2=wb[8]; }
        FU[0*4+c]=A0;  FU[1*4+c]=A2;  FU[2*4+c]=A0+A1; FU[3*4+c]=A1+A2;
        FU[16+0*4+c]=B0; FU[16+1*4+c]=B2; FU[16+2*4+c]=B0+B1; FU[16+3*4+c]=B1+B2;
    }
    const float bb = b[o];
    constexpr int ITEMS = 8*(H/2)*NX;
    for (int t = threadIdx.x; t < ITEMS; t += NT) {
        int q = t >> 3;
        int xv = q % NX, yhp = q / NX;
        int yh0 = 2*yhp, x0 = xv*4, hx = x0>>1;
        float a0[4] = {bb,bb,bb,bb};
        float a1[4] = {bb,bb,bb,bb};
        #pragma unroll
        for (int rr = 0; rr < 3; ++rr) {
            int srow_i = yh0 - 1 + parity + rr;
            if ((unsigned)srow_i >= (unsigned)H) continue;
            const float* srow = in + srow_i*H*4;
            float4 s0 = ldz4(srow + (hx-1)*4, hx > 0);
            float4 s1 = *reinterpret_cast<const float4*>(srow + hx*4);
            float4 s2 = *reinterpret_cast<const float4*>(srow + (hx+1)*4);
            float4 s3 = ldz4(srow + (hx+2)*4, hx+2 < H);
            if (rr <= 1) {
                const float* F = FU + rr*16;
                a0[0] = dot4a(dot4a(a0[0], F+0*4, s0), F+3*4, s1);
                a0[1] = dot4a(dot4a(a0[1], F+2*4, s1), F+1*4, s2);
                a0[2] = dot4a(dot4a(a0[2], F+0*4, s1), F+3*4, s2);
                a0[3] = dot4a(dot4a(a0[3], F+2*4, s2), F+1*4, s3);
            }
            if (rr >= 1) {
                const float* F = FU + (rr-1)*16;
                a1[0] = dot4a(dot4a(a1[0], F+0*4, s0), F+3*4, s1);
                a1[1] = dot4a(dot4a(a1[1], F+2*4, s1), F+1*4, s2);
                a1[2] = dot4a(dot4a(a1[2], F+0*4, s1), F+3*4, s2);
                a1[3] = dot4a(dot4a(a1[3], F+2*4, s2), F+1*4, s3);
            }
        }
        int y0 = 2*yh0 + parity;
        int base0 = (y0*R + x0)*4 + o, base1 = base0 + 2*R*4;
        #pragma unroll
        for (int j = 0; j < 4; ++j) {
            if (ST) { outPre[base0 + j*4] = f2bf(a0[j]); outPre[base1 + j*4] = f2bf(a1[j]); }
            outAct[base0 + j*4] = swish_f(a0[j]);
            outAct[base1 + j*4] = swish_f(a1[j]);
        }
    }
}

// ============================================================================
// convfin: 4->1, NHWC in. MODE 0: y -> fp32 planar. MODE 2: dy -> bf16 planar.
// ============================================================================
template<int R,int MODE>
__device__ __noinline__ void convfin(const float* __restrict__ in, const float* __restrict__ w,
                                     float b0, void* __restrict__ outp,
                                     const float* __restrict__ xref)
{
    constexpr int NX = R/4;
    float wr[36];
    #pragma unroll
    for (int k = 0; k < 9; ++k)
        #pragma unroll
        for (int c = 0; c < 4; ++c) wr[k*4+c] = w[c*9+k];
    for (int t = threadIdx.x; t < (R/2)*NX; t += NT) {
        int xv = t % NX, yp = t / NX, x0 = xv*4, y0 = 2*yp;
        float a0[4] = {b0,b0,b0,b0};
        float a1[4] = {b0,b0,b0,b0};
        #pragma unroll
        for (int iy = 0; iy < 4; ++iy) {
            int yy = y0 - 1 + iy; if ((unsigned)yy >= (unsigned)R) continue;
            const float* row = in + yy*R*4;
            float4 p[6];
            #pragma unroll
            for (int k = 0; k < 6; ++k) {
                int xx = x0 - 1 + k;
                p[k] = ldz4(row + xx*4, (unsigned)xx < (unsigned)R);
            }
            if (iy <= 2) {
                #pragma unroll
                for (int j = 0; j < 4; ++j)
                    #pragma unroll
                    for (int kx = 0; kx < 3; ++kx)
                        a0[j] = dot4a(a0[j], &wr[(iy*3+kx)*4], p[j+kx]);
            }
            if (iy >= 1) {
                #pragma unroll
                for (int j = 0; j < 4; ++j)
                    #pragma unroll
                    for (int kx = 0; kx < 3; ++kx)
                        a1[j] = dot4a(a1[j], &wr[((iy-1)*3+kx)*4], p[j+kx]);
            }
        }
        #pragma unroll
        for (int rr = 0; rr < 2; ++rr) {
            float* a = rr ? a1 : a0;
            int y = y0 + rr;
            if constexpr (MODE == 2) {
                float4 xr = *reinterpret_cast<const float4*>(xref + y*R + x0);
                float4 ov = make_float4((a[0]-xr.x)*DYSCALE,(a[1]-xr.y)*DYSCALE,
                                        (a[2]-xr.z)*DYSCALE,(a[3]-xr.w)*DYSCALE);
                st4h(reinterpret_cast<bf16*>(outp) + y*R + x0, ov);
            } else {
                *reinterpret_cast<float4*>(reinterpret_cast<float*>(outp) + y*R + x0) =
                    make_float4(a[0],a[1],a[2],a[3]);
            }
        }
    }
}

// ---- pool backward scatter fused with swish', all bf16 ----
template<int R>
__device__ __noinline__ void pool_bwdv(const bf16* __restrict__ dp, const unsigned char* __restrict__ idx,
                                       const bf16* __restrict__ u, bf16* __restrict__ du)
{
    constexpr int H = R/2;
    for (int t = threadIdx.x; t < R*H; t += NT) {
        int xh = t % H, y = t / H;
        int cell = ((y>>1)*H + xh)*4;
        float4 d4 = ld4h(dp + cell);
        uchar4 i4 = *reinterpret_cast<const uchar4*>(idx + cell);
        float dv[4]={d4.x,d4.y,d4.z,d4.w};
        unsigned char iv[4]={i4.x,i4.y,i4.z,i4.w};
        int sb = (y & 1) << 1;
        #pragma unroll
        for (int s = 0; s < 2; ++s) {
            int x = 2*xh + s;
            float4 u4 = ld4h(u + (y*R + x)*4);
            float uv[4]={u4.x,u4.y,u4.z,u4.w};
            float ov[4];
            #pragma unroll
            for (int c = 0; c < 4; ++c) {
                float g = (iv[c] == (unsigned char)(sb+s)) ? dv[c] : 0.f;
                ov[c] = g * swish_d(uv[c]);
            }
            st4h(du + (y*R + x)*4, make_float4(ov[0],ov[1],ov[2],ov[3]));
        }
    }
}

// ============================================================================
// dgrad of final conv: planar bf16 dout -> NHWC bf16 din, fused swish'(V4h)
// ============================================================================
template<int R>
__device__ __noinline__ void dgrad_fin(const bf16* __restrict__ dout, const float* __restrict__ w,
                                       const bf16* __restrict__ upre, bf16* __restrict__ din)
{
    constexpr int NX = R/4;
    float wf[36];
    #pragma unroll
    for (int k = 0; k < 9; ++k)
        #pragma unroll
        for (int c = 0; c < 4; ++c) wf[k*4+c] = w[c*9 + 8-k];
    for (int t = threadIdx.x; t < (R/2)*NX; t += NT) {
        int xv = t % NX, yp = t / NX, x0 = xv*4, y0 = 2*yp;
        float4 a0[4] = {};
        float4 a1[4] = {};
        #pragma unroll
        for (int iy = 0; iy < 4; ++iy) {
            int yy = y0 - 1 + iy; if ((unsigned)yy >= (unsigned)R) continue;
            const bf16* row = dout + yy*R;
            float4 v = ld4h(row + x0);
            float s[6];
            s[0] = (x0 > 0)   ? bf2f(row[x0-1]) : 0.f;
            s[1]=v.x; s[2]=v.y; s[3]=v.z; s[4]=v.w;
            s[5] = (x0+4 < R) ? bf2f(row[x0+4]) : 0.f;
            if (iy <= 2) {
                #pragma unroll
                for (int j = 0; j < 4; ++j)
                    #pragma unroll
                    for (int kx = 0; kx < 3; ++kx)
                        axpy4(a0[j], s[j+kx], &wf[(iy*3+kx)*4]);
            }
            if (iy >= 1) {
                #pragma unroll
                for (int j = 0; j < 4; ++j)
                    #pragma unroll
                    for (int kx = 0; kx < 3; ++kx)
                        axpy4(a1[j], s[j+kx], &wf[((iy-1)*3+kx)*4]);
            }
        }
        #pragma unroll
        for (int rr = 0; rr < 2; ++rr) {
            float4* a = rr ? a1 : a0;
            int base = ((y0+rr)*R + x0)*4;
            #pragma unroll
            for (int j = 0; j < 4; ++j) {
                float4 u4 = ld4h(upre + base + j*4);
                a[j].x *= swish_d(u4.x); a[j].y *= swish_d(u4.y);
                a[j].z *= swish_d(u4.z); a[j].w *= swish_d(u4.w);
                st4h(din + base + j*4, a[j]);
            }
        }
    }
}

// ============================================================================
// dgrad4: 4->4 NHWC bf16 (encoder; no fuse), 2-row blocked
// ============================================================================
template<int R>
__device__ __noinline__ void dgrad4(const bf16* __restrict__ dout, const float* __restrict__ w,
                                    bf16* __restrict__ din)
{
    constexpr int NX = R/4;
    const int c = threadIdx.x & 3;
    float wf[36];
    #pragma unroll
    for (int k = 0; k < 9; ++k)
        #pragma unroll
        for (int o = 0; o < 4; ++o) wf[k*4+o] = w[(o*4+c)*9 + 8-k];
    for (int t = threadIdx.x; t < 4*(R/2)*NX; t += NT) {
        int r2 = t >> 2;
        int xv = r2 % NX, yp = r2 / NX, x0 = xv*4, y0 = 2*yp;
        float a0[4] = {};
        float a1[4] = {};
        #pragma unroll
        for (int iy = 0; iy < 4; ++iy) {
            int yy = y0 - 1 + iy; if ((unsigned)yy >= (unsigned)R) continue;
            const bf16* row = dout + yy*R*4;
            float4 p[6];
            #pragma unroll
            for (int k = 0; k < 6; ++k) {
                int xx = x0 - 1 + k;
                p[k] = ldz4h(row + xx*4, (unsigned)xx < (unsigned)R);
            }
            if (iy <= 2) {
                #pragma unroll
                for (int j = 0; j < 4; ++j)
                    #pragma unroll
                    for (int kx = 0; kx < 3; ++kx)
                        a0[j] = dot4a(a0[j], &wf[(iy*3+kx)*4], p[j+kx]);
            }
            if (iy >= 1) {
                #pragma unroll
                for (int j = 0; j < 4; ++j)
                    #pragma unroll
                    for (int kx = 0; kx < 3; ++kx)
                        a1[j] = dot4a(a1[j], &wf[((iy-1)*3+kx)*4], p[j+kx]);
            }
        }
        int base0 = (y0*R + x0)*4 + c, base1 = base0 + R*4;
        #pragma unroll
        for (int j = 0; j < 4; ++j) { din[base0 + j*4] = f2bf(a0[j]); din[base1 + j*4] = f2bf(a1[j]); }
    }
}

// ============================================================================
// dupv: backward of (up->conv), bf16 dout@R -> bf16 din@H, wE 4x4, swish'(upre)
// ============================================================================
template<int R>
__device__ __noinline__ void dupv(const bf16* __restrict__ dout, const float* __restrict__ w,
                                  const bf16* __restrict__ upre, bf16* __restrict__ din)
{
    constexpr int H = R/2, NXH = H/4;
    const int c = threadIdx.x & 3;
    float wE[64];
    #pragma unroll
    for (int o = 0; o < 4; ++o) {
        const float* wb = w + (o*4 + c)*9;
        #pragma unroll
        for (int i = 0; i < 4; ++i)
            #pragma unroll
            for (int j = 0; j < 4; ++j) {
                float s = 0.f;
                #pragma unroll
                for (int sy = 0; sy < 2; ++sy) {
                    int a = sy + 2 - i; if (a < 0 || a > 2) continue;
                    #pragma unroll
                    for (int sx = 0; sx < 2; ++sx) {
                        int bc = sx + 2 - j; if (bc < 0 || bc > 2) continue;
                        s += wb[a*3 + bc];
                    }
                }
                wE[(i*4+j)*4 + o] = s;
            }
    }
    for (int t = threadIdx.x; t < 4*H*NXH; t += NT) {
        int r2 = t >> 2;
        int vv = r2 % NXH, u = r2 / NXH, v0 = vv*4;
        int r0 = 2*u - 1;
        float a[4] = {};
        #pragma unroll
        for (int i = 0; i < 4; ++i) {
            int rr = r0 + i; if ((unsigned)rr >= (unsigned)R) continue;
            const bf16* row = dout + rr*R*4;
            float4 q[10];
            #pragma unroll
            for (int m = 0; m < 10; ++m) {
                int px = 2*v0 - 1 + m;
                q[m] = ldz4h(row + px*4, (unsigned)px < (unsigned)R);
            }
            #pragma unroll
            for (int j = 0; j < 4; ++j)
                #pragma unroll
                for (int kk = 0; kk < 4; ++kk)
                    a[j] = dot4a(a[j], &wE[(i*4+kk)*4], q[2*j+kk]);
        }
        int base = (u*H + v0)*4 + c;
        #pragma unroll
        for (int j = 0; j < 4; ++j) {
            float up = bf2f(upre[base + j*4]);
            din[base + j*4] = f2bf(a[j] * swish_d(up));
        }
    }
}

// ============================================================================
// wgrad4: dout bf16 NHWC; in fp32 NHWC at R or (UP) at H; in-place smem update
// ============================================================================
template<int R,bool UP>
__device__ __noinline__ void wgrad4(const bf16* __restrict__ dout, const float* __restrict__ in,
                                    float* wDst, float* bDst, float* sRed)
{
    constexpr int NX = R/4, H = R/2;
    for (int i = threadIdx.x; i < 148; i += NT) sRed[i] = 0.f;
    __syncthreads();
    const int o = threadIdx.x & 3;
    float acc[36]; float accb = 0.f;
    #pragma unroll
    for (int i = 0; i < 36; ++i) acc[i] = 0.f;

    for (int pv = threadIdx.x >> 2; pv < R*NX; pv += NT >> 2) {
        int y = pv / NX, x0 = (pv % NX)*4;
        const bf16* db = dout + (y*R + x0)*4 + o;
        float g0 = bf2f(db[0]), g1 = bf2f(db[4]), g2 = bf2f(db[8]), g3 = bf2f(db[12]);
        accb += g0+g1+g2+g3;
        float g01 = g0+g1, g12 = g1+g2, g23 = g2+g3;
        #pragma unroll
        for (int ky = 0; ky < 3; ++ky) {
            int yy = y + ky - 1; if ((unsigned)yy >= (unsigned)R) continue;
            if constexpr (UP) {
                const float* srow = in + (yy>>1)*H*4;
                int hx = x0 >> 1;
                float4 s0 = ldz4(srow + (hx-1)*4, hx > 0);
                float4 s1 = *reinterpret_cast<const float4*>(srow + hx*4);
                float4 s2 = *reinterpret_cast<const float4*>(srow + (hx+1)*4);
                float4 s3 = ldz4(srow + (hx+2)*4, hx+2 < H);
                accum4(&acc[ky*3+0], g0, s0); accum4(&acc[ky*3+0], g12, s1); accum4(&acc[ky*3+0], g3, s2);
                accum4(&acc[ky*3+1], g01, s1); accum4(&acc[ky*3+1], g23, s2);
                accum4(&acc[ky*3+2], g0, s1); accum4(&acc[ky*3+2], g12, s2); accum4(&acc[ky*3+2], g3, s3);
            } else {
                const float* row = in + yy*R*4;
                float4 p[6];
                #pragma unroll
                for (int k = 0; k < 6; ++k) {
                    int xx = x0 - 1 + k;
                    p[k] = ldz4(row + xx*4, (unsigned)xx < (unsigned)R);
                }
                float g[4] = {g0,g1,g2,g3};
                #pragma unroll
                for (int kx = 0; kx < 3; ++kx)
                    #pragma unroll
                    for (int j = 0; j < 4; ++j)
                        accum4(&acc[ky*3+kx], g[j], p[j+kx]);
            }
        }
    }
    unsigned lane = threadIdx.x & 31;
    #pragma unroll
    for (int off = 16; off >= 4; off >>= 1) {
        #pragma unroll
        for (int i = 0; i < 36; ++i) acc[i] += __shfl_xor_sync(0xffffffffu, acc[i], off);
        accb += __shfl_xor_sync(0xffffffffu, accb, off);
    }
    if (lane < 4) {
        #pragma unroll
        for (int i = 0; i < 36; ++i) atomicAdd(&sRed[o*36 + i], acc[i]);
        atomicAdd(&sRed[144 + o], accb);
    }
    __syncthreads();
    for (int i = threadIdx.x; i < 144; i += NT) wDst[i] -= LRATE * sRed[i];
    if (threadIdx.x < 4) bDst[threadIdx.x] -= LRATE * sRed[144 + threadIdx.x];
}

// ---- wgrad of final conv (planar bf16 dout, NHWC fp32 in, COUT=1) ----
template<int R>
__device__ __noinline__ void wgrad_fin(const bf16* __restrict__ dout, const float* __restrict__ in,
                                       float* wDst, float* bDst, float* sRed)
{
    constexpr int NX = R/4;
    for (int i = threadIdx.x; i < 37; i += NT) sRed[i] = 0.f;
    __syncthreads();
    float acc[36]; float accb = 0.f;
    #pragma unroll
    for (int i = 0; i < 36; ++i) acc[i] = 0.f;
    for (int pv = threadIdx.x; pv < R*NX; pv += NT) {
        int y = pv / NX, x0 = (pv % NX)*4;
        float4 g = ld4h(dout + y*R + x0);
        float gv[4] = {g.x,g.y,g.z,g.w};
        accb += g.x+g.y+g.z+g.w;
        #pragma unroll
        for (int ky = 0; ky < 3; ++ky) {
            int yy = y + ky - 1; if ((unsigned)yy >= (unsigned)R) continue;
            const float* row = in + yy*R*4;
            float4 p[6];
            #pragma unroll
            for (int k = 0; k < 6; ++k) {
                int xx = x0 - 1 + k;
                p[k] = ldz4(row + xx*4, (unsigned)xx < (unsigned)R);
            }
            #pragma unroll
            for (int kx = 0; kx < 3; ++kx)
                #pragma unroll
                for (int j = 0; j < 4; ++j)
                    accum4(&acc[ky*3+kx], gv[j], p[j+kx]);
        }
    }
    unsigned lane = threadIdx.x & 31;
    #pragma unroll
    for (int off = 16; off >= 1; off >>= 1) {
        #pragma unroll
        for (int i = 0; i < 36; ++i) acc[i] += __shfl_xor_sync(0xffffffffu, acc[i], off);
        accb += __shfl_xor_sync(0xffffffffu, accb, off);
    }
    if (lane == 0) {
        #pragma unroll
        for (int i = 0; i < 36; ++i) atomicAdd(&sRed[i], acc[i]);
        atomicAdd(&sRed[36], accb);
    }
    __syncthreads();
    for (int i = threadIdx.x; i < 36; i += NT) wDst[i] -= LRATE * sRed[i];
    if (threadIdx.x == 0) bDst[0] -= LRATE * sRed[36];
}

// ---- wgrad of first conv (NHWC bf16 dout, planar fp32 in, CIN=1) ----
template<int R>
__device__ __noinline__ void wgrad_first(const bf16* __restrict__ dout, const float* __restrict__ in,
                                         float* wDst, float* bDst, float* sRed)
{
    constexpr int NX = R/4;
    for (int i = threadIdx.x; i < 40; i += NT) sRed[i] = 0.f;
    __syncthreads();
    const int o = threadIdx.x & 3;
    float acc[9]; float accb = 0.f;
    #pragma unroll
    for (int i = 0; i < 9; ++i) acc[i] = 0.f;
    for (int pv = threadIdx.x >> 2; pv < R*NX; pv += NT >> 2) {
        int y = pv / NX, x0 = (pv % NX)*4;
        const bf16* db = dout + (y*R + x0)*4 + o;
        float g[4] = {bf2f(db[0]), bf2f(db[4]), bf2f(db[8]), bf2f(db[12])};
        accb += g[0]+g[1]+g[2]+g[3];
        #pragma unroll
        for (int ky = 0; ky < 3; ++ky) {
            int yy = y + ky - 1; if ((unsigned)yy >= (unsigned)R) continue;
            const float* row = in + yy*R;
            float4 v = *reinterpret_cast<const float4*>(row + x0);
            float s[6];
            s[0] = (x0 > 0)   ? row[x0-1] : 0.f;
            s[1]=v.x; s[2]=v.y; s[3]=v.z; s[4]=v.w;
            s[5] = (x0+4 < R) ? row[x0+4] : 0.f;
            #pragma unroll
            for (int kx = 0; kx < 3; ++kx) {
                float t = 0.f;
                #pragma unroll
                for (int j = 0; j < 4; ++j) t = fmaf(g[j], s[j+kx], t);
                acc[ky*3+kx] += t;
            }
        }
    }
    unsigned lane = threadIdx.x & 31;
    #pragma unroll
    for (int off = 16; off >= 4; off >>= 1) {
        #pragma unroll
        for (int i = 0; i < 9; ++i) acc[i] += __shfl_xor_sync(0xffffffffu, acc[i], off);
        accb += __shfl_xor_sync(0xffffffffu, accb, off);
    }
    if (lane < 4) {
        #pragma unroll
        for (int i = 0; i < 9; ++i) atomicAdd(&sRed[o*9 + i], acc[i]);
        atomicAdd(&sRed[36 + o], accb);
    }
    __syncthreads();
    for (int i = threadIdx.x; i < 36; i += NT) wDst[i] -= LRATE * sRed[i];
    if (threadIdx.x < 4) bDst[threadIdx.x] -= LRATE * sRed[36 + threadIdx.x];
}

// ---- full forward pass; FIRST: store gradient-path tensors (bf16) ----
template<bool FIRST>
__device__ __noinline__ void forward_pass(const float* __restrict__ x, const float* sP,
                                          float* S, bf16* Sh, unsigned char* I,
                                          float* __restrict__ ydst)
{
    conv0pool<128,FIRST>(x, sP+PW0, sP+PEB, Sh+HU0, S+OFF_P0, I+IX0);             __syncthreads();
    conv4pool<64,FIRST>(S+OFF_P0, sP+PEW,     sP+PEB+4,  Sh+HU1, S+OFF_P1, I+IX1); __syncthreads();
    conv4pool<32,FIRST>(S+OFF_P1, sP+PEW+144, sP+PEB+8,  Sh+HU2, S+OFF_P2, I+IX2); __syncthreads();
    conv4pool<16,FIRST>(S+OFF_P2, sP+PEW+288, sP+PEB+12, Sh+HU3, S+OFF_P3, I+IX3); __syncthreads();
    conv4pool<8,FIRST> (S+OFF_P3, sP+PEW+432, sP+PEB+16, Sh+HU4, S+OFF_P4, I+IX4); __syncthreads();
    conv4b<4,FIRST>    (S+OFF_P4, sP+PEW+576, sP+PEB+20, Sh+HU5, S+OFF_F);         __syncthreads();

    if (threadIdx.x < 32) {
        float acc = sP[PLEB + threadIdx.x];
        for (int j = 0; j < 64; ++j) acc += sP[PLEW + threadIdx.x*64 + j] * S[OFF_F + nh(j)];
        if (FIRST) Sh[HZU + threadIdx.x] = f2bf(acc);
        S[OFF_Z + threadIdx.x] = swish_f(acc);
    }
    __syncthreads();
    if (threadIdx.x < 64) {
        float acc = sP[PLDB + threadIdx.x];
        for (int j = 0; j < 32; ++j) acc += sP[PLDW + threadIdx.x*32 + j] * S[OFF_Z + j];
        int ni = nh(threadIdx.x);
        if (FIRST) Sh[HDU + ni] = f2bf(acc);
        S[OFF_DD + ni] = swish_f(acc);
    }
    __syncthreads();

    convup<8,FIRST>  (S+OFF_DD, sP+PDW,     sP+PDB,    Sh+HV0, S+OFF_Q0);         __syncthreads();
    convup<16,FIRST> (S+OFF_Q0, sP+PDW+144, sP+PDB+4,  Sh+HV1, S+OFF_Q1);         __syncthreads();
    convup<32,FIRST> (S+OFF_Q1, sP+PDW+288, sP+PDB+8,  Sh+HV2, S+OFF_Q2);         __syncthreads();
    convup<64,FIRST> (S+OFF_Q2, sP+PDW+432, sP+PDB+12, Sh+HV3, S+OFF_Q3);         __syncthreads();
    convup<128,FIRST>(S+OFF_Q3, sP+PDW+576, sP+PDB+16, Sh+HV4, S+OFF_Q4);         __syncthreads();

    if (FIRST) convfin<128,2>(S+OFF_Q4, sP+PWO, sP[PBO], Sh+HDY, x);
    else       convfin<128,0>(S+OFF_Q4, sP+PWO, sP[PBO], ydst, nullptr);
    __syncthreads();
}

__global__ __launch_bounds__(NT, 1)
void maml_kernel(const float* __restrict__ x_all,
                 const float* __restrict__ enc_w0,   const float* __restrict__ enc_w,
                 const float* __restrict__ enc_b,    const float* __restrict__ enc_lin_w,
                 const float* __restrict__ enc_lin_b,const float* __restrict__ dec_lin_w,
                 const float* __restrict__ dec_lin_b,const float* __restrict__ dec_w,
                 const float* __restrict__ dec_b,    const float* __restrict__ dec_w_out,
                 const float* __restrict__ dec_b_out,float* __restrict__ out)
{
    __shared__ float sP[NPARAM];
    __shared__ float sRed[160];
    const int s = blockIdx.x;
    float* S  = g_scratch  + (size_t)s * SSCF;
    bf16*  Sh = g_scratchh + (size_t)s * SSCH;
    unsigned char* I = g_idxbuf + s * SIDX;
    const float* x = x_all + (size_t)s * 16384;

    for (int i = threadIdx.x; i < 36;   i += NT) sP[PW0 +i] = enc_w0[i];
    for (int i = threadIdx.x; i < 24;   i += NT) sP[PEB +i] = enc_b[i];
    for (int i = threadIdx.x; i < 720;  i += NT) sP[PEW +i] = enc_w[i];
    for (int i = threadIdx.x; i < 2048; i += NT) sP[PLEW+i] = enc_lin_w[i];
    for (int i = threadIdx.x; i < 32;   i += NT) sP[PLEB+i] = enc_lin_b[i];
    for (int i = threadIdx.x; i < 2048; i += NT) sP[PLDW+i] = dec_lin_w[i];
    for (int i = threadIdx.x; i < 64;   i += NT) sP[PLDB+i] = dec_lin_b[i];
    for (int i = threadIdx.x; i < 720;  i += NT) sP[PDW +i] = dec_w[i];
    for (int i = threadIdx.x; i < 20;   i += NT) sP[PDB +i] = dec_b[i];
    for (int i = threadIdx.x; i < 36;   i += NT) sP[PWO +i] = dec_w_out[i];
    if (threadIdx.x == 0) sP[PBO] = dec_b_out[0];
    __syncthreads();

    // ===== forward #1 (stores gradient-path tensors as bf16) =====
    forward_pass<true>(x, sP, S, Sh, I, nullptr);

    bf16* GA = Sh + HGA;
    bf16* GB = Sh + HGB;

    // ===== backward (all gradient tensors bf16; accumulation fp32) =====
    dgrad_fin<128>(Sh+HDY, sP+PWO, Sh+HV4, GA);                             __syncthreads();
    wgrad_fin<128>(Sh+HDY, S+OFF_Q4, sP+PWO, sP+PBO, sRed);                 __syncthreads();

    dupv<128>(GA, sP+PDW+576, Sh+HV3, GB);                                  __syncthreads();
    wgrad4<128,true>(GA, S+OFF_Q3, sP+PDW+576, sP+PDB+16, sRed);            __syncthreads();
    dupv<64>(GB, sP+PDW+432, Sh+HV2, GA);                                   __syncthreads();
    wgrad4<64,true>(GB, S+OFF_Q2, sP+PDW+432, sP+PDB+12, sRed);             __syncthreads();
    dupv<32>(GA, sP+PDW+288, Sh+HV1, GB);                                   __syncthreads();
    wgrad4<32,true>(GA, S+OFF_Q1, sP+PDW+288, sP+PDB+8, sRed);              __syncthreads();
    dupv<16>(GB, sP+PDW+144, Sh+HV0, GA);                                   __syncthreads();
    wgrad4<16,true>(GB, S+OFF_Q0, sP+PDW+144, sP+PDB+4, sRed);              __syncthreads();
    dupv<8>(GA, sP+PDW, Sh+HDU, GB);                                        __syncthreads();  // GB = ddu (NHWC, 64)
    wgrad4<8,true>(GA, S+OFF_DD, sP+PDW, sP+PDB, sRed);                     __syncthreads();

    // dec_lin backward (ddu bf16 NHWC in GB)
    if (threadIdx.x < 32) {
        float acc = 0.f;
        for (int i = 0; i < 64; ++i) acc += sP[PLDW + i*32 + threadIdx.x] * bf2f(GB[nh(i)]);
        GA[threadIdx.x] = f2bf(acc);                 // dz
    }
    __syncthreads();
    for (int t = threadIdx.x; t < 2048; t += NT) {
        int i = t >> 5, j = t & 31;
        sP[PLDW + t] -= LRATE * bf2f(GB[nh(i)]) * S[OFF_Z + j];
    }
    if (threadIdx.x < 64) sP[PLDB + threadIdx.x] -= LRATE * bf2f(GB[nh(threadIdx.x)]);
    __syncthreads();
    if (threadIdx.x < 32)
        GB[threadIdx.x] = f2bf(bf2f(GA[threadIdx.x]) * swish_d(bf2f(Sh[HZU + threadIdx.x]))); // dzu
    __syncthreads();
    if (threadIdx.x < 64) {
        float acc = 0.f;
        for (int i = 0; i < 32; ++i) acc += sP[PLEW + i*64 + threadIdx.x] * bf2f(GB[i]);
        int ni = nh(threadIdx.x);
        GA[ni] = f2bf(acc * swish_d(bf2f(Sh[HU5 + ni])));   // du5 (NHWC)
    }
    __syncthreads();
    for (int t = threadIdx.x; t < 2048; t += NT) {
        int i = t >> 6, j = t & 63;
        sP[PLEW + t] -= LRATE * bf2f(GB[i]) * S[OFF_F + nh(j)];
    }
    if (threadIdx.x < 32) sP[PLEB + threadIdx.x] -= LRATE * bf2f(GB[threadIdx.x]);
    __syncthreads();

    // encoder backward (du5 in GA)
    dgrad4<4>(GA, sP+PEW+576, GB);                                          __syncthreads();
    wgrad4<4,false>(GA, S+OFF_P4, sP+PEW+576, sP+PEB+20, sRed);             __syncthreads();
    pool_bwdv<8>(GB, I+IX4, Sh+HU4, GA);                                    __syncthreads();
    dgrad4<8>(GA, sP+PEW+432, GB);                                          __syncthreads();
    wgrad4<8,false>(GA, S+OFF_P3, sP+PEW+432, sP+PEB+16, sRed);             __syncthreads();
    pool_bwdv<16>(GB, I+IX3, Sh+HU3, GA);                                   __syncthreads();
    dgrad4<16>(GA, sP+PEW+288, GB);                                         __syncthreads();
    wgrad4<16,false>(GA, S+OFF_P2, sP+PEW+288, sP+PEB+12, sRed);            __syncthreads();
    pool_bwdv<32>(GB, I+IX2, Sh+HU2, GA);                                   __syncthreads();
    dgrad4<32>(GA, sP+PEW+144, GB);                                         __syncthreads();
    wgrad4<32,false>(GA, S+OFF_P1, sP+PEW+144, sP+PEB+8, sRed);             __syncthreads();
    pool_bwdv<64>(GB, I+IX1, Sh+HU1, GA);                                   __syncthreads();
    dgrad4<64>(GA, sP+PEW, GB);                                             __syncthreads();
    wgrad4<64,false>(GA, S+OFF_P0, sP+PEW, sP+PEB+4, sRed);                 __syncthreads();
    pool_bwdv<128>(GB, I+IX0, Sh+HU0, GA);                                  __syncthreads();
    wgrad_first<128>(GA, x, sP+PW0, sP+PEB, sRed);                          __syncthreads();

    // ===== forward #2 with updated per-sample params (no gradient stores) =====
    forward_pass<false>(x, sP, S, Sh, I, out + (size_t)s * 16384);
}

extern "C" void kernel_launch(void* const* d_in, const int* in_sizes, int n_in,
                              void* d_out, int out_size)
{
    (void)in_sizes; (void)n_in; (void)out_size;
    maml_kernel<<<128, NT>>>(
        (const float*)d_in[0],  (const float*)d_in[1],  (const float*)d_in[2],
        (const float*)d_in[3],  (const float*)d_in[4],  (const float*)d_in[5],
        (const float*)d_in[6],  (const float*)d_in[7],  (const float*)d_in[8],
        (const float*)d_in[9],  (const float*)d_in[10], (const float*)d_in[11],
        (float*)d_out);
}

// round 7
// speedup vs baseline: 4.4235x; 1.1886x over previous
#include <cuda_runtime.h>
#include <cuda_bf16.h>

typedef __nv_bfloat16 bf16;

#define NT 512
constexpr float LRATE = 0.01f;
constexpr float DYSCALE = 2.0f / 2097152.0f;   // 2 / (B * 128*128)

// ---- smem tensor arena offsets (floats) ----
constexpr int T_P0=0,     T_P1=16384, T_P2=20480, T_P3=21504, T_P4=21760,
              T_F=21824,  T_Z=21888,  T_DD=21920, T_Q0=21984, T_Q1=22240,
              T_Q2=23264, T_Q3=27360, T_END=43744;
constexpr int NPARAM = 5749, NPARAM_PAD = 5752;
constexpr int SMEM_FLOATS = T_END + NPARAM_PAD + 320;      // + sRedA(160) + sRedB(160)
constexpr int SMEM_BYTES  = SMEM_FLOATS * 4;               // 199,264 B

// ---- bf16 arena offsets (halfs): gradient-path tensors ----
constexpr int HU0=0,      HU1=65536,  HU2=81920,  HU3=86016,  HU4=87040,  HU5=87296,
              HV0=87360,  HV1=87616,  HV2=88640,  HV3=92736,  HV4=109120,
              HZU=174656, HDU=174688, HDY=174752, HGA=191136, HGB=256672;
constexpr int SSCH = 273056;

constexpr int IX0=0, IX1=16384, IX2=20480, IX3=21504, IX4=21760, SIDX=21824;

__device__ float          g_q4[128ull * 65536];            // Q4 stays global (256 KB/sample)
__device__ bf16           g_scratchh[128ull * SSCH];       // ~70 MB
__device__ unsigned char  g_idxbuf[128 * SIDX];

// ---- smem param layout (floats) ----
constexpr int PW0=0, PEB=36, PEW=60, PLEW=780, PLEB=2828, PLDW=2860, PLDB=4908,
              PDW=4972, PDB=5692, PWO=5712, PBO=5748;

__device__ __forceinline__ float tanhap(float x){ float y; asm("tanh.approx.f32 %0, %1;" : "=f"(y) : "f"(x)); return y; }
__device__ __forceinline__ float sigm(float u){ return fmaf(tanhap(0.5f*u), 0.5f, 0.5f); }
__device__ __forceinline__ float swish_f(float u){ return u * sigm(u); }
__device__ __forceinline__ float swish_d(float u){ float s = sigm(u); return s * fmaf(u, 1.0f - s, 1.0f); }

__device__ __forceinline__ float bf2f(bf16 v){ return __bfloat162float(v); }
__device__ __forceinline__ bf16  f2bf(float v){ return __float2bfloat16(v); }
__device__ __forceinline__ float4 ld4h(const bf16* p){
    __nv_bfloat162 a = reinterpret_cast<const __nv_bfloat162*>(p)[0];
    __nv_bfloat162 b = reinterpret_cast<const __nv_bfloat162*>(p)[1];
    return make_float4(__bfloat162float(a.x), __bfloat162float(a.y),
                       __bfloat162float(b.x), __bfloat162float(b.y));
}
__device__ __forceinline__ float4 ldz4h(const bf16* p, bool v){
    return v ? ld4h(p) : make_float4(0.f,0.f,0.f,0.f);
}
__device__ __forceinline__ void st4h(bf16* p, float4 v){
    reinterpret_cast<__nv_bfloat162*>(p)[0] = __floats2bfloat162_rn(v.x, v.y);
    reinterpret_cast<__nv_bfloat162*>(p)[1] = __floats2bfloat162_rn(v.z, v.w);
}
__device__ __forceinline__ float4 ldz4(const float* p, bool v){
    return v ? *reinterpret_cast<const float4*>(p) : make_float4(0.f,0.f,0.f,0.f);
}
__device__ __forceinline__ float dot4a(float a, const float* w, float4 p){
    return fmaf(w[0],p.x, fmaf(w[1],p.y, fmaf(w[2],p.z, fmaf(w[3],p.w, a))));
}
__device__ __forceinline__ void axpy4(float4& a, float s, const float* w){
    a.x = fmaf(s,w[0],a.x); a.y = fmaf(s,w[1],a.y); a.z = fmaf(s,w[2],a.z); a.w = fmaf(s,w[3],a.w);
}
__device__ __forceinline__ void accum4(float* accK, float g, float4 p){  // stride 9 over c
    accK[0]  = fmaf(g,p.x,accK[0]);  accK[9]  = fmaf(g,p.y,accK[9]);
    accK[18] = fmaf(g,p.z,accK[18]); accK[27] = fmaf(g,p.w,accK[27]);
}
__device__ __forceinline__ int nh(int i){ return ((i & 15) << 2) + (i >> 4); }  // chw(4x4) -> nhwc

__device__ __forceinline__ void pool1(float v0,float v1,float v2,float v3,
                                      float& m, unsigned char& id){
    v0 = swish_f(v0); v1 = swish_f(v1); v2 = swish_f(v2); v3 = swish_f(v3);
    m = v0; id = 0;
    if (v1 > m) { m = v1; id = 1; }
    if (v2 > m) { m = v2; id = 2; }
    if (v3 > m) { m = v3; id = 3; }
}

// ============================================================================
// conv0pool: 1->4 conv (planar in) fused with swish+2x2 maxpool.
// ============================================================================
template<int R,bool FIRST>
__device__ __noinline__ void conv0pool(const float* __restrict__ in, const float* w,
                                       const float* b, bf16* __restrict__ uh,
                                       float* pOut, unsigned char* __restrict__ idx)
{
    constexpr int NX = R/4, Ro = R/2;
    float wr[36];
    #pragma unroll
    for (int k = 0; k < 9; ++k)
        #pragma unroll
        for (int o = 0; o < 4; ++o) wr[k*4+o] = w[o*9+k];
    const float4 bb = make_float4(b[0],b[1],b[2],b[3]);
    for (int t = threadIdx.x; t < (R/2)*NX; t += NT) {
        int xv = t % NX, yp = t / NX, x0 = xv*4, y0 = 2*yp;
        float4 a0[4] = {bb,bb,bb,bb};
        float4 a1[4] = {bb,bb,bb,bb};
        #pragma unroll
        for (int iy = 0; iy < 4; ++iy) {
            int yy = y0 - 1 + iy; if ((unsigned)yy >= (unsigned)R) continue;
            const float* row = in + yy*R;
            float4 v = *reinterpret_cast<const float4*>(row + x0);
            float s[6];
            s[0] = (x0 > 0)   ? row[x0-1] : 0.f;
            s[1]=v.x; s[2]=v.y; s[3]=v.z; s[4]=v.w;
            s[5] = (x0+4 < R) ? row[x0+4] : 0.f;
            if (iy <= 2) {
                #pragma unroll
                for (int j = 0; j < 4; ++j)
                    #pragma unroll
                    for (int kx = 0; kx < 3; ++kx)
                        axpy4(a0[j], s[j+kx], &wr[(iy*3+kx)*4]);
            }
            if (iy >= 1) {
                #pragma unroll
                for (int j = 0; j < 4; ++j)
                    #pragma unroll
                    for (int kx = 0; kx < 3; ++kx)
                        axpy4(a1[j], s[j+kx], &wr[((iy-1)*3+kx)*4]);
            }
        }
        if (FIRST) {
            int ub0 = (y0*R + x0)*4, ub1 = ub0 + R*4;
            #pragma unroll
            for (int j = 0; j < 4; ++j) { st4h(uh + ub0 + j*4, a0[j]); st4h(uh + ub1 + j*4, a1[j]); }
        }
        int xo = x0 >> 1;
        #pragma unroll
        for (int jj = 0; jj < 2; ++jj) {
            int j = 2*jj;
            float4 q00 = a0[j], q01 = a0[j+1], q10 = a1[j], q11 = a1[j+1];
            float pm[4]; unsigned char im[4];
            pool1(q00.x, q01.x, q10.x, q11.x, pm[0], im[0]);
            pool1(q00.y, q01.y, q10.y, q11.y, pm[1], im[1]);
            pool1(q00.z, q01.z, q10.z, q11.z, pm[2], im[2]);
            pool1(q00.w, q01.w, q10.w, q11.w, pm[3], im[3]);
            int ob = (yp*Ro + xo + jj)*4;
            *reinterpret_cast<float4*>(pOut + ob) = make_float4(pm[0],pm[1],pm[2],pm[3]);
            if (FIRST) *reinterpret_cast<uchar4*>(idx + ob) = make_uchar4(im[0],im[1],im[2],im[3]);
        }
    }
}

// ============================================================================
// conv4pool: 4->4 conv NHWC fused with swish+2x2 maxpool; thread owns o.
// ============================================================================
template<int R,bool FIRST>
__device__ __noinline__ void conv4pool(const float* in, const float* w,
                                       const float* b, bf16* __restrict__ uh,
                                       float* pOut, unsigned char* __restrict__ idx)
{
    constexpr int NX = R/4, Ro = R/2;
    const int o = threadIdx.x & 3;
    float wr[36];
    #pragma unroll
    for (int k = 0; k < 9; ++k)
        #pragma unroll
        for (int c = 0; c < 4; ++c) wr[k*4+c] = w[(o*4+c)*9+k];
    const float bb = b[o];
    for (int t = threadIdx.x; t < 4*(R/2)*NX; t += NT) {
        int r2 = t >> 2;
        int xv = r2 % NX, yp = r2 / NX, x0 = xv*4, y0 = 2*yp;
        float a0[4] = {bb,bb,bb,bb};
        float a1[4] = {bb,bb,bb,bb};
        #pragma unroll
        for (int iy = 0; iy < 4; ++iy) {
            int yy = y0 - 1 + iy; if ((unsigned)yy >= (unsigned)R) continue;
            const float* row = in + yy*R*4;
            float4 p[6];
            #pragma unroll
            for (int k = 0; k < 6; ++k) {
                int xx = x0 - 1 + k;
                p[k] = ldz4(row + xx*4, (unsigned)xx < (unsigned)R);
            }
            if (iy <= 2) {
                #pragma unroll
                for (int j = 0; j < 4; ++j)
                    #pragma unroll
                    for (int kx = 0; kx < 3; ++kx)
                        a0[j] = dot4a(a0[j], &wr[(iy*3+kx)*4], p[j+kx]);
            }
            if (iy >= 1) {
                #pragma unroll
                for (int j = 0; j < 4; ++j)
                    #pragma unroll
                    for (int kx = 0; kx < 3; ++kx)
                        a1[j] = dot4a(a1[j], &wr[((iy-1)*3+kx)*4], p[j+kx]);
            }
        }
        if (FIRST) {
            int ub0 = (y0*R + x0)*4 + o, ub1 = ub0 + R*4;
            #pragma unroll
            for (int j = 0; j < 4; ++j) { uh[ub0 + j*4] = f2bf(a0[j]); uh[ub1 + j*4] = f2bf(a1[j]); }
        }
        int xo = x0 >> 1;
        #pragma unroll
        for (int jj = 0; jj < 2; ++jj) {
            int j = 2*jj;
            float m; unsigned char id;
            pool1(a0[j], a0[j+1], a1[j], a1[j+1], m, id);
            int ob = (yp*Ro + xo + jj)*4 + o;
            pOut[ob] = m;
            if (FIRST) idx[ob] = id;
        }
    }
}

// ============================================================================
// conv4b: 4->4 NHWC (last encoder conv): pre bf16 (FIRST), act fp32
// ============================================================================
template<int R,bool FIRST>
__device__ __noinline__ void conv4b(const float* in, const float* w,
                                    const float* b, bf16* __restrict__ outPre,
                                    float* outAct)
{
    constexpr int NX = R/4;
    const int o = threadIdx.x & 3;
    float wr[36];
    #pragma unroll
    for (int k = 0; k < 9; ++k)
        #pragma unroll
        for (int c = 0; c < 4; ++c) wr[k*4+c] = w[(o*4+c)*9+k];
    const float bb = b[o];
    for (int t = threadIdx.x; t < 4*(R/2)*NX; t += NT) {
        int r2 = t >> 2;
        int xv = r2 % NX, yp = r2 / NX, x0 = xv*4, y0 = 2*yp;
        float a0[4] = {bb,bb,bb,bb};
        float a1[4] = {bb,bb,bb,bb};
        #pragma unroll
        for (int iy = 0; iy < 4; ++iy) {
            int yy = y0 - 1 + iy; if ((unsigned)yy >= (unsigned)R) continue;
            const float* row = in + yy*R*4;
            float4 p[6];
            #pragma unroll
            for (int k = 0; k < 6; ++k) {
                int xx = x0 - 1 + k;
                p[k] = ldz4(row + xx*4, (unsigned)xx < (unsigned)R);
            }
            if (iy <= 2) {
                #pragma unroll
                for (int j = 0; j < 4; ++j)
                    #pragma unroll
                    for (int kx = 0; kx < 3; ++kx)
                        a0[j] = dot4a(a0[j], &wr[(iy*3+kx)*4], p[j+kx]);
            }
            if (iy >= 1) {
                #pragma unroll
                for (int j = 0; j < 4; ++j)
                    #pragma unroll
                    for (int kx = 0; kx < 3; ++kx)
                        a1[j] = dot4a(a1[j], &wr[((iy-1)*3+kx)*4], p[j+kx]);
            }
        }
        int base0 = (y0*R + x0)*4 + o, base1 = base0 + R*4;
        #pragma unroll
        for (int j = 0; j < 4; ++j) {
            if (FIRST) { outPre[base0 + j*4] = f2bf(a0[j]); outPre[base1 + j*4] = f2bf(a1[j]); }
            outAct[base0 + j*4] = swish_f(a0[j]);
            outAct[base1 + j*4] = swish_f(a1[j]);
        }
    }
}

// ============================================================================
// convup: 4->4 NHWC, fused 2x nearest upsample; act fp32 always, pre bf16 if ST
// ============================================================================
template<int R,bool ST>
__device__ __noinline__ void convup(const float* in, const float* w,
                                    const float* b, bf16* __restrict__ outPre,
                                    float* outAct)
{
    constexpr int NX = R/4, H = R/2;
    const int o = threadIdx.x & 3;
    const int parity = (threadIdx.x >> 2) & 1;
    float FU[32];
    #pragma unroll
    for (int c = 0; c < 4; ++c) {
        const float* wb = w + (o*4 + c)*9;
        float A0,A1,A2,B0,B1,B2;
        if (!parity) { A0=wb[0];A1=wb[1];A2=wb[2]; B0=wb[3]+wb[6];B1=wb[4]+wb[7];B2=wb[5]+wb[8]; }
        else         { A0=wb[0]+wb[3];A1=wb[1]+wb[4];A2=wb[2]+wb[5]; B0=wb[6];B1=wb[7];B2=wb[8]; }
        FU[0*4+c]=A0;  FU[1*4+c]=A2;  FU[2*4+c]=A0+A1; FU[3*4+c]=A1+A2;
        FU[16+0*4+c]=B0; FU[16+1*4+c]=B2; FU[16+2*4+c]=B0+B1; FU[16+3*4+c]=B1+B2;
    }
    const float bb = b[o];
    constexpr int ITEMS = 8*(H/2)*NX;
    for (int t = threadIdx.x; t < ITEMS; t += NT) {
        int q = t >> 3;
        int xv = q % NX, yhp = q / NX;
        int yh0 = 2*yhp, x0 = xv*4, hx = x0>>1;
        float a0[4] = {bb,bb,bb,bb};
        float a1[4] = {bb,bb,bb,bb};
        #pragma unroll
        for (int rr = 0; rr < 3; ++rr) {
            int srow_i = yh0 - 1 + parity + rr;
            if ((unsigned)srow_i >= (unsigned)H) continue;
            const float* srow = in + srow_i*H*4;
            float4 s0 = ldz4(srow + (hx-1)*4, hx > 0);
            float4 s1 = *reinterpret_cast<const float4*>(srow + hx*4);
            float4 s2 = *reinterpret_cast<const float4*>(srow + (hx+1)*4);
            float4 s3 = ldz4(srow + (hx+2)*4, hx+2 < H);
            if (rr <= 1) {
                const float* F = FU + rr*16;
                a0[0] = dot4a(dot4a(a0[0], F+0*4, s0), F+3*4, s1);
                a0[1] = dot4a(dot4a(a0[1], F+2*4, s1), F+1*4, s2);
                a0[2] = dot4a(dot4a(a0[2], F+0*4, s1), F+3*4, s2);
                a0[3] = dot4a(dot4a(a0[3], F+2*4, s2), F+1*4, s3);
            }
            if (rr >= 1) {
                const float* F = FU + (rr-1)*16;
                a1[0] = dot4a(dot4a(a1[0], F+0*4, s0), F+3*4, s1);
                a1[1] = dot4a(dot4a(a1[1], F+2*4, s1), F+1*4, s2);
                a1[2] = dot4a(dot4a(a1[2], F+0*4, s1), F+3*4, s2);
                a1[3] = dot4a(dot4a(a1[3], F+2*4, s2), F+1*4, s3);
            }
        }
        int y0 = 2*yh0 + parity;
        int base0 = (y0*R + x0)*4 + o, base1 = base0 + 2*R*4;
        #pragma unroll
        for (int j = 0; j < 4; ++j) {
            if (ST) { outPre[base0 + j*4] = f2bf(a0[j]); outPre[base1 + j*4] = f2bf(a1[j]); }
            outAct[base0 + j*4] = swish_f(a0[j]);
            outAct[base1 + j*4] = swish_f(a1[j]);
        }
    }
}

// ============================================================================
// convfin: 4->1, NHWC in. MODE 0: y -> fp32 planar. MODE 2: dy -> bf16 planar.
// ============================================================================
template<int R,int MODE>
__device__ __noinline__ void convfin(const float* in, const float* w,
                                     float b0, void* __restrict__ outp,
                                     const float* __restrict__ xref)
{
    constexpr int NX = R/4;
    float wr[36];
    #pragma unroll
    for (int k = 0; k < 9; ++k)
        #pragma unroll
        for (int c = 0; c < 4; ++c) wr[k*4+c] = w[c*9+k];
    for (int t = threadIdx.x; t < (R/2)*NX; t += NT) {
        int xv = t % NX, yp = t / NX, x0 = xv*4, y0 = 2*yp;
        float a0[4] = {b0,b0,b0,b0};
        float a1[4] = {b0,b0,b0,b0};
        #pragma unroll
        for (int iy = 0; iy < 4; ++iy) {
            int yy = y0 - 1 + iy; if ((unsigned)yy >= (unsigned)R) continue;
            const float* row = in + yy*R*4;
            float4 p[6];
            #pragma unroll
            for (int k = 0; k < 6; ++k) {
                int xx = x0 - 1 + k;
                p[k] = ldz4(row + xx*4, (unsigned)xx < (unsigned)R);
            }
            if (iy <= 2) {
                #pragma unroll
                for (int j = 0; j < 4; ++j)
                    #pragma unroll
                    for (int kx = 0; kx < 3; ++kx)
                        a0[j] = dot4a(a0[j], &wr[(iy*3+kx)*4], p[j+kx]);
            }
            if (iy >= 1) {
                #pragma unroll
                for (int j = 0; j < 4; ++j)
                    #pragma unroll
                    for (int kx = 0; kx < 3; ++kx)
                        a1[j] = dot4a(a1[j], &wr[((iy-1)*3+kx)*4], p[j+kx]);
            }
        }
        #pragma unroll
        for (int rr = 0; rr < 2; ++rr) {
            float* a = rr ? a1 : a0;
            int y = y0 + rr;
            if constexpr (MODE == 2) {
                float4 xr = *reinterpret_cast<const float4*>(xref + y*R + x0);
                float4 ov = make_float4((a[0]-xr.x)*DYSCALE,(a[1]-xr.y)*DYSCALE,
                                        (a[2]-xr.z)*DYSCALE,(a[3]-xr.w)*DYSCALE);
                st4h(reinterpret_cast<bf16*>(outp) + y*R + x0, ov);
            } else {
                *reinterpret_cast<float4*>(reinterpret_cast<float*>(outp) + y*R + x0) =
                    make_float4(a[0],a[1],a[2],a[3]);
            }
        }
    }
}

// ---- pool backward scatter fused with swish', all bf16 (full-width) ----
template<int R>
__device__ __noinline__ void pool_bwdv(const bf16* __restrict__ dp, const unsigned char* __restrict__ idx,
                                       const bf16* __restrict__ u, bf16* __restrict__ du)
{
    constexpr int H = R/2;
    for (int t = threadIdx.x; t < R*H; t += NT) {
        int xh = t % H, y = t / H;
        int cell = ((y>>1)*H + xh)*4;
        float4 d4 = ld4h(dp + cell);
        uchar4 i4 = *reinterpret_cast<const uchar4*>(idx + cell);
        float dv[4]={d4.x,d4.y,d4.z,d4.w};
        unsigned char iv[4]={i4.x,i4.y,i4.z,i4.w};
        int sb = (y & 1) << 1;
        #pragma unroll
        for (int s = 0; s < 2; ++s) {
            int x = 2*xh + s;
            float4 u4 = ld4h(u + (y*R + x)*4);
            float uv[4]={u4.x,u4.y,u4.z,u4.w};
            float ov[4];
            #pragma unroll
            for (int c = 0; c < 4; ++c) {
                float g = (iv[c] == (unsigned char)(sb+s)) ? dv[c] : 0.f;
                ov[c] = g * swish_d(uv[c]);
            }
            st4h(du + (y*R + x)*4, make_float4(ov[0],ov[1],ov[2],ov[3]));
        }
    }
}

// ============================================================================
// dgrad of final conv (tid/nth parametrized for warp-split phases)
// ============================================================================
template<int R>
__device__ __noinline__ void dgrad_fin(const bf16* __restrict__ dout, const float* w,
                                       const bf16* __restrict__ upre, bf16* __restrict__ din,
                                       int tid, int nth)
{
    constexpr int NX = R/4;
    float wf[36];
    #pragma unroll
    for (int k = 0; k < 9; ++k)
        #pragma unroll
        for (int c = 0; c < 4; ++c) wf[k*4+c] = w[c*9 + 8-k];
    for (int t = tid; t < (R/2)*NX; t += nth) {
        int xv = t % NX, yp = t / NX, x0 = xv*4, y0 = 2*yp;
        float4 a0[4] = {};
        float4 a1[4] = {};
        #pragma unroll
        for (int iy = 0; iy < 4; ++iy) {
            int yy = y0 - 1 + iy; if ((unsigned)yy >= (unsigned)R) continue;
            const bf16* row = dout + yy*R;
            float4 v = ld4h(row + x0);
            float s[6];
            s[0] = (x0 > 0)   ? bf2f(row[x0-1]) : 0.f;
            s[1]=v.x; s[2]=v.y; s[3]=v.z; s[4]=v.w;
            s[5] = (x0+4 < R) ? bf2f(row[x0+4]) : 0.f;
            if (iy <= 2) {
                #pragma unroll
                for (int j = 0; j < 4; ++j)
                    #pragma unroll
                    for (int kx = 0; kx < 3; ++kx)
                        axpy4(a0[j], s[j+kx], &wf[(iy*3+kx)*4]);
            }
            if (iy >= 1) {
                #pragma unroll
                for (int j = 0; j < 4; ++j)
                    #pragma unroll
                    for (int kx = 0; kx < 3; ++kx)
                        axpy4(a1[j], s[j+kx], &wf[((iy-1)*3+kx)*4]);
            }
        }
        #pragma unroll
        for (int rr = 0; rr < 2; ++rr) {
            float4* a = rr ? a1 : a0;
            int base = ((y0+rr)*R + x0)*4;
            #pragma unroll
            for (int j = 0; j < 4; ++j) {
                float4 u4 = ld4h(upre + base + j*4);
                a[j].x *= swish_d(u4.x); a[j].y *= swish_d(u4.y);
                a[j].z *= swish_d(u4.z); a[j].w *= swish_d(u4.w);
                st4h(din + base + j*4, a[j]);
            }
        }
    }
}

// ============================================================================
// dgrad4: 4->4 NHWC bf16 (encoder; no fuse), tid/nth parametrized
// ============================================================================
template<int R>
__device__ __noinline__ void dgrad4(const bf16* __restrict__ dout, const float* w,
                                    bf16* __restrict__ din, int tid, int nth)
{
    constexpr int NX = R/4;
    const int c = tid & 3;
    float wf[36];
    #pragma unroll
    for (int k = 0; k < 9; ++k)
        #pragma unroll
        for (int o = 0; o < 4; ++o) wf[k*4+o] = w[(o*4+c)*9 + 8-k];
    for (int t = tid; t < 4*(R/2)*NX; t += nth) {
        int r2 = t >> 2;
        int xv = r2 % NX, yp = r2 / NX, x0 = xv*4, y0 = 2*yp;
        float a0[4] = {};
        float a1[4] = {};
        #pragma unroll
        for (int iy = 0; iy < 4; ++iy) {
            int yy = y0 - 1 + iy; if ((unsigned)yy >= (unsigned)R) continue;
            const bf16* row = dout + yy*R*4;
            float4 p[6];
            #pragma unroll
            for (int k = 0; k < 6; ++k) {
                int xx = x0 - 1 + k;
                p[k] = ldz4h(row + xx*4, (unsigned)xx < (unsigned)R);
            }
            if (iy <= 2) {
                #pragma unroll
                for (int j = 0; j < 4; ++j)
                    #pragma unroll
                    for (int kx = 0; kx < 3; ++kx)
                        a0[j] = dot4a(a0[j], &wf[(iy*3+kx)*4], p[j+kx]);
            }
            if (iy >= 1) {
                #pragma unroll
                for (int j = 0; j < 4; ++j)
                    #pragma unroll
                    for (int kx = 0; kx < 3; ++kx)
                        a1[j] = dot4a(a1[j], &wf[((iy-1)*3+kx)*4], p[j+kx]);
            }
        }
        int base0 = (y0*R + x0)*4 + c, base1 = base0 + R*4;
        #pragma unroll
        for (int j = 0; j < 4; ++j) { din[base0 + j*4] = f2bf(a0[j]); din[base1 + j*4] = f2bf(a1[j]); }
    }
}

// ============================================================================
// dupv: backward of (up->conv), tid/nth parametrized
// ============================================================================
template<int R>
__device__ __noinline__ void dupv(const bf16* __restrict__ dout, const float* w,
                                  const bf16* __restrict__ upre, bf16* __restrict__ din,
                                  int tid, int nth)
{
    constexpr int H = R/2, NXH = H/4;
    const int c = tid & 3;
    float wE[64];
    #pragma unroll
    for (int o = 0; o < 4; ++o) {
        const float* wb = w + (o*4 + c)*9;
        #pragma unroll
        for (int i = 0; i < 4; ++i)
            #pragma unroll
            for (int j = 0; j < 4; ++j) {
                float s = 0.f;
                #pragma unroll
                for (int sy = 0; sy < 2; ++sy) {
                    int a = sy + 2 - i; if (a < 0 || a > 2) continue;
                    #pragma unroll
                    for (int sx = 0; sx < 2; ++sx) {
                        int bc = sx + 2 - j; if (bc < 0 || bc > 2) continue;
                        s += wb[a*3 + bc];
                    }
                }
                wE[(i*4+j)*4 + o] = s;
            }
    }
    for (int t = tid; t < 4*H*NXH; t += nth) {
        int r2 = t >> 2;
        int vv = r2 % NXH, u = r2 / NXH, v0 = vv*4;
        int r0 = 2*u - 1;
        float a[4] = {};
        #pragma unroll
        for (int i = 0; i < 4; ++i) {
            int rr = r0 + i; if ((unsigned)rr >= (unsigned)R) continue;
            const bf16* row = dout + rr*R*4;
            float4 q[10];
            #pragma unroll
            for (int m = 0; m < 10; ++m) {
                int px = 2*v0 - 1 + m;
                q[m] = ldz4h(row + px*4, (unsigned)px < (unsigned)R);
            }
            #pragma unroll
            for (int j = 0; j < 4; ++j)
                #pragma unroll
                for (int kk = 0; kk < 4; ++kk)
                    a[j] = dot4a(a[j], &wE[(i*4+kk)*4], q[2*j+kk]);
        }
        int base = (u*H + v0)*4 + c;
        #pragma unroll
        for (int j = 0; j < 4; ++j) {
            float up = bf2f(upre[base + j*4]);
            din[base + j*4] = f2bf(a[j] * swish_d(up));
        }
    }
}

// ============================================================================
// wgrad accumulators — NO internal barriers; sRed pre-zeroed; update deferred
// ============================================================================
template<int R,bool UP>
__device__ __noinline__ void wgrad4_acc(const bf16* __restrict__ dout, const float* in,
                                        float* sRed, int tid, int nth)
{
    constexpr int NX = R/4, H = R/2;
    const int o = tid & 3;
    float acc[36]; float accb = 0.f;
    #pragma unroll
    for (int i = 0; i < 36; ++i) acc[i] = 0.f;

    for (int pv = tid >> 2; pv < R*NX; pv += nth >> 2) {
        int y = pv / NX, x0 = (pv % NX)*4;
        const bf16* db = dout + (y*R + x0)*4 + o;
        float g0 = bf2f(db[0]), g1 = bf2f(db[4]), g2 = bf2f(db[8]), g3 = bf2f(db[12]);
        accb += g0+g1+g2+g3;
        float g01 = g0+g1, g12 = g1+g2, g23 = g2+g3;
        #pragma unroll
        for (int ky = 0; ky < 3; ++ky) {
            int yy = y + ky - 1; if ((unsigned)yy >= (unsigned)R) continue;
            if constexpr (UP) {
                const float* srow = in + (yy>>1)*H*4;
                int hx = x0 >> 1;
                float4 s0 = ldz4(srow + (hx-1)*4, hx > 0);
                float4 s1 = *reinterpret_cast<const float4*>(srow + hx*4);
                float4 s2 = *reinterpret_cast<const float4*>(srow + (hx+1)*4);
                float4 s3 = ldz4(srow + (hx+2)*4, hx+2 < H);
                accum4(&acc[ky*3+0], g0, s0); accum4(&acc[ky*3+0], g12, s1); accum4(&acc[ky*3+0], g3, s2);
                accum4(&acc[ky*3+1], g01, s1); accum4(&acc[ky*3+1], g23, s2);
                accum4(&acc[ky*3+2], g0, s1); accum4(&acc[ky*3+2], g12, s2); accum4(&acc[ky*3+2], g3, s3);
            } else {
                const float* row = in + yy*R*4;
                float4 p[6];
                #pragma unroll
                for (int k = 0; k < 6; ++k) {
                    int xx = x0 - 1 + k;
                    p[k] = ldz4(row + xx*4, (unsigned)xx < (unsigned)R);
                }
                float g[4] = {g0,g1,g2,g3};
                #pragma unroll
                for (int kx = 0; kx < 3; ++kx)
                    #pragma unroll
                    for (int j = 0; j < 4; ++j)
                        accum4(&acc[ky*3+kx], g[j], p[j+kx]);
            }
        }
    }
    unsigned lane = tid & 31;
    #pragma unroll
    for (int off = 16; off >= 4; off >>= 1) {
        #pragma unroll
        for (int i = 0; i < 36; ++i) acc[i] += __shfl_xor_sync(0xffffffffu, acc[i], off);
        accb += __shfl_xor_sync(0xffffffffu, accb, off);
    }
    if (lane < 4) {
        #pragma unroll
        for (int i = 0; i < 36; ++i) atomicAdd(&sRed[o*36 + i], acc[i]);
        atomicAdd(&sRed[144 + o], accb);
    }
}

template<int R>
__device__ __noinline__ void wgradfin_acc(const bf16* __restrict__ dout, const float* in,
                                          float* sRed, int tid, int nth)
{
    constexpr int NX = R/4;
    float acc[36]; float accb = 0.f;
    #pragma unroll
    for (int i = 0; i < 36; ++i) acc[i] = 0.f;
    for (int pv = tid; pv < R*NX; pv += nth) {
        int y = pv / NX, x0 = (pv % NX)*4;
        float4 g = ld4h(dout + y*R + x0);
        float gv[4] = {g.x,g.y,g.z,g.w};
        accb += g.x+g.y+g.z+g.w;
        #pragma unroll
        for (int ky = 0; ky < 3; ++ky) {
            int yy = y + ky - 1; if ((unsigned)yy >= (unsigned)R) continue;
            const float* row = in + yy*R*4;
            float4 p[6];
            #pragma unroll
            for (int k = 0; k < 6; ++k) {
                int xx = x0 - 1 + k;
                p[k] = ldz4(row + xx*4, (unsigned)xx < (unsigned)R);
            }
            #pragma unroll
            for (int kx = 0; kx < 3; ++kx)
                #pragma unroll
                for (int j = 0; j < 4; ++j)
                    accum4(&acc[ky*3+kx], gv[j], p[j+kx]);
        }
    }
    unsigned lane = tid & 31;
    #pragma unroll
    for (int off = 16; off >= 1; off >>= 1) {
        #pragma unroll
        for (int i = 0; i < 36; ++i) acc[i] += __shfl_xor_sync(0xffffffffu, acc[i], off);
        accb += __shfl_xor_sync(0xffffffffu, accb, off);
    }
    if (lane == 0) {
        #pragma unroll
        for (int i = 0; i < 36; ++i) atomicAdd(&sRed[i], acc[i]);
        atomicAdd(&sRed[36], accb);
    }
}

template<int R>
__device__ __noinline__ void wgradfirst_acc(const bf16* __restrict__ dout, const float* __restrict__ in,
                                            float* sRed, int tid, int nth)
{
    constexpr int NX = R/4;
    const int o = tid & 3;
    float acc[9]; float accb = 0.f;
    #pragma unroll
    for (int i = 0; i < 9; ++i) acc[i] = 0.f;
    for (int pv = tid >> 2; pv < R*NX; pv += nth >> 2) {
        int y = pv / NX, x0 = (pv % NX)*4;
        const bf16* db = dout + (y*R + x0)*4 + o;
        float g[4] = {bf2f(db[0]), bf2f(db[4]), bf2f(db[8]), bf2f(db[12])};
        accb += g[0]+g[1]+g[2]+g[3];
        #pragma unroll
        for (int ky = 0; ky < 3; ++ky) {
            int yy = y + ky - 1; if ((unsigned)yy >= (unsigned)R) continue;
            const float* row = in + yy*R;
            float4 v = *reinterpret_cast<const float4*>(row + x0);
            float s[6];
            s[0] = (x0 > 0)   ? row[x0-1] : 0.f;
            s[1]=v.x; s[2]=v.y; s[3]=v.z; s[4]=v.w;
            s[5] = (x0+4 < R) ? row[x0+4] : 0.f;
            #pragma unroll
            for (int kx = 0; kx < 3; ++kx) {
                float t = 0.f;
                #pragma unroll
                for (int j = 0; j < 4; ++j) t = fmaf(g[j], s[j+kx], t);
                acc[ky*3+kx] += t;
            }
        }
    }
    unsigned lane = tid & 31;
    #pragma unroll
    for (int off = 16; off >= 4; off >>= 1) {
        #pragma unroll
        for (int i = 0; i < 9; ++i) acc[i] += __shfl_xor_sync(0xffffffffu, acc[i], off);
        accb += __shfl_xor_sync(0xffffffffu, accb, off);
    }
    if (lane < 4) {
        #pragma unroll
        for (int i = 0; i < 9; ++i) atomicAdd(&sRed[o*9 + i], acc[i]);
        atomicAdd(&sRed[36 + o], accb);
    }
}

// deferred weight update: reads sRed, applies SGD step, re-zeroes sRed
__device__ __forceinline__ void apply_update(float* w, float* b, float* sRed, int nw, int nb)
{
    for (int i = threadIdx.x; i < nw; i += NT) { w[i] -= LRATE * sRed[i]; sRed[i] = 0.f; }
    for (int i = threadIdx.x; i < nb; i += NT) { b[i] -= LRATE * sRed[nw+i]; sRed[nw+i] = 0.f; }
}

// ---- full forward pass ----
template<bool FIRST>
__device__ __noinline__ void forward_pass(const float* __restrict__ x, const float* sP,
                                          float* sT, bf16* Sh, float* gQ4,
                                          unsigned char* I, float* __restrict__ ydst)
{
    conv0pool<128,FIRST>(x, sP+PW0, sP+PEB, Sh+HU0, sT+T_P0, I+IX0);               __syncthreads();
    conv4pool<64,FIRST>(sT+T_P0, sP+PEW,     sP+PEB+4,  Sh+HU1, sT+T_P1, I+IX1);   __syncthreads();
    conv4pool<32,FIRST>(sT+T_P1, sP+PEW+144, sP+PEB+8,  Sh+HU2, sT+T_P2, I+IX2);   __syncthreads();
    conv4pool<16,FIRST>(sT+T_P2, sP+PEW+288, sP+PEB+12, Sh+HU3, sT+T_P3, I+IX3);   __syncthreads();
    conv4pool<8,FIRST> (sT+T_P3, sP+PEW+432, sP+PEB+16, Sh+HU4, sT+T_P4, I+IX4);   __syncthreads();
    conv4b<4,FIRST>    (sT+T_P4, sP+PEW+576, sP+PEB+20, Sh+HU5, sT+T_F);           __syncthreads();

    if (threadIdx.x < 32) {
        float acc = sP[PLEB + threadIdx.x];
        for (int j = 0; j < 64; ++j) acc += sP[PLEW + threadIdx.x*64 + j] * sT[T_F + nh(j)];
        if (FIRST) Sh[HZU + threadIdx.x] = f2bf(acc);
        sT[T_Z + threadIdx.x] = swish_f(acc);
    }
    __syncthreads();
    if (threadIdx.x < 64) {
        float acc = sP[PLDB + threadIdx.x];
        for (int j = 0; j < 32; ++j) acc += sP[PLDW + threadIdx.x*32 + j] * sT[T_Z + j];
        int ni = nh(threadIdx.x);
        if (FIRST) Sh[HDU + ni] = f2bf(acc);
        sT[T_DD + ni] = swish_f(acc);
    }
    __syncthreads();

    convup<8,FIRST>  (sT+T_DD, sP+PDW,     sP+PDB,    Sh+HV0, sT+T_Q0);            __syncthreads();
    convup<16,FIRST> (sT+T_Q0, sP+PDW+144, sP+PDB+4,  Sh+HV1, sT+T_Q1);            __syncthreads();
    convup<32,FIRST> (sT+T_Q1, sP+PDW+288, sP+PDB+8,  Sh+HV2, sT+T_Q2);            __syncthreads();
    convup<64,FIRST> (sT+T_Q2, sP+PDW+432, sP+PDB+12, Sh+HV3, sT+T_Q3);            __syncthreads();
    convup<128,FIRST>(sT+T_Q3, sP+PDW+576, sP+PDB+16, Sh+HV4, gQ4);                __syncthreads();

    if (FIRST) convfin<128,2>(gQ4, sP+PWO, sP[PBO], Sh+HDY, x);
    else       convfin<128,0>(gQ4, sP+PWO, sP[PBO], ydst, nullptr);
    __syncthreads();
}

__global__ __launch_bounds__(NT, 1)
void maml_kernel(const float* __restrict__ x_all,
                 const float* __restrict__ enc_w0,   const float* __restrict__ enc_w,
                 const float* __restrict__ enc_b,    const float* __restrict__ enc_lin_w,
                 const float* __restrict__ enc_lin_b,const float* __restrict__ dec_lin_w,
                 const float* __restrict__ dec_lin_b,const float* __restrict__ dec_w,
                 const float* __restrict__ dec_b,    const float* __restrict__ dec_w_out,
                 const float* __restrict__ dec_b_out,float* __restrict__ out)
{
    extern __shared__ __align__(16) float smem_f[];
    float* sT    = smem_f;
    float* sP    = smem_f + T_END;
    float* sRedA = smem_f + T_END + NPARAM_PAD;
    float* sRedB = sRedA + 160;

    const int s = blockIdx.x;
    bf16*  Sh  = g_scratchh + (size_t)s * SSCH;
    float* gQ4 = g_q4 + (size_t)s * 65536;
    unsigned char* I = g_idxbuf + s * SIDX;
    const float* x = x_all + (size_t)s * 16384;

    for (int i = threadIdx.x; i < 36;   i += NT) sP[PW0 +i] = enc_w0[i];
    for (int i = threadIdx.x; i < 24;   i += NT) sP[PEB +i] = enc_b[i];
    for (int i = threadIdx.x; i < 720;  i += NT) sP[PEW +i] = enc_w[i];
    for (int i = threadIdx.x; i < 2048; i += NT) sP[PLEW+i] = enc_lin_w[i];
    for (int i = threadIdx.x; i < 32;   i += NT) sP[PLEB+i] = enc_lin_b[i];
    for (int i = threadIdx.x; i < 2048; i += NT) sP[PLDW+i] = dec_lin_w[i];
    for (int i = threadIdx.x; i < 64;   i += NT) sP[PLDB+i] = dec_lin_b[i];
    for (int i = threadIdx.x; i < 720;  i += NT) sP[PDW +i] = dec_w[i];
    for (int i = threadIdx.x; i < 20;   i += NT) sP[PDB +i] = dec_b[i];
    for (int i = threadIdx.x; i < 36;   i += NT) sP[PWO +i] = dec_w_out[i];
    for (int i = threadIdx.x; i < 160;  i += NT) { sRedA[i] = 0.f; sRedB[i] = 0.f; }
    if (threadIdx.x == 0) sP[PBO] = dec_b_out[0];
    __syncthreads();

    // ===== forward #1 =====
    forward_pass<true>(x, sP, sT, Sh, gQ4, I, nullptr);

    bf16* GA = Sh + HGA;
    bf16* GB = Sh + HGB;
    const int tid = threadIdx.x;

    // ===== backward: warp-split merged (dgrad || wgrad) phases =====
    if (tid < 256) dgrad_fin<128>(Sh+HDY, sP+PWO, Sh+HV4, GA, tid, 256);
    else           wgradfin_acc<128>(Sh+HDY, gQ4, sRedA, tid-256, 256);
    __syncthreads();
    apply_update(sP+PWO, sP+PBO, sRedA, 36, 1);

    if (tid < 256) dupv<128>(GA, sP+PDW+576, Sh+HV3, GB, tid, 256);
    else           wgrad4_acc<128,true>(GA, sT+T_Q3, sRedB, tid-256, 256);
    __syncthreads();
    apply_update(sP+PDW+576, sP+PDB+16, sRedB, 144, 4);

    if (tid < 256) dupv<64>(GB, sP+PDW+432, Sh+HV2, GA, tid, 256);
    else           wgrad4_acc<64,true>(GB, sT+T_Q2, sRedA, tid-256, 256);
    __syncthreads();
    apply_update(sP+PDW+432, sP+PDB+12, sRedA, 144, 4);

    if (tid < 256) dupv<32>(GA, sP+PDW+288, Sh+HV1, GB, tid, 256);
    else           wgrad4_acc<32,true>(GA, sT+T_Q1, sRedB, tid-256, 256);
    __syncthreads();
    apply_update(sP+PDW+288, sP+PDB+8, sRedB, 144, 4);

    if (tid < 256) dupv<16>(GB, sP+PDW+144, Sh+HV0, GA, tid, 256);
    else           wgrad4_acc<16,true>(GB, sT+T_Q0, sRedA, tid-256, 256);
    __syncthreads();
    apply_update(sP+PDW+144, sP+PDB+4, sRedA, 144, 4);

    if (tid < 256) dupv<8>(GA, sP+PDW, Sh+HDU, GB, tid, 256);    // GB = ddu (NHWC, 64)
    else           wgrad4_acc<8,true>(GA, sT+T_DD, sRedB, tid-256, 256);
    __syncthreads();
    apply_update(sP+PDW, sP+PDB, sRedB, 144, 4);

    // dec_lin / enc_lin backward (sequential; small)
    if (tid < 32) {
        float acc = 0.f;
        for (int i = 0; i < 64; ++i) acc += sP[PLDW + i*32 + tid] * bf2f(GB[nh(i)]);
        GA[tid] = f2bf(acc);                 // dz
    }
    __syncthreads();
    for (int t = tid; t < 2048; t += NT) {
        int i = t >> 5, j = t & 31;
        sP[PLDW + t] -= LRATE * bf2f(GB[nh(i)]) * sT[T_Z + j];
    }
    if (tid < 64) sP[PLDB + tid] -= LRATE * bf2f(GB[nh(tid)]);
    __syncthreads();
    if (tid < 32)
        GB[tid] = f2bf(bf2f(GA[tid]) * swish_d(bf2f(Sh[HZU + tid]))); // dzu
    __syncthreads();
    if (tid < 64) {
        float acc = 0.f;
        for (int i = 0; i < 32; ++i) acc += sP[PLEW + i*64 + tid] * bf2f(GB[i]);
        int ni = nh(tid);
        GA[ni] = f2bf(acc * swish_d(bf2f(Sh[HU5 + ni])));   // du5 (NHWC)
    }
    __syncthreads();
    for (int t = tid; t < 2048; t += NT) {
        int i = t >> 6, j = t & 63;
        sP[PLEW + t] -= LRATE * bf2f(GB[i]) * sT[T_F + nh(j)];
    }
    if (tid < 32) sP[PLEB + tid] -= LRATE * bf2f(GB[tid]);
    __syncthreads();

    // encoder backward (du5 in GA)
    if (tid < 256) dgrad4<4>(GA, sP+PEW+576, GB, tid, 256);
    else           wgrad4_acc<4,false>(GA, sT+T_P4, sRedA, tid-256, 256);
    __syncthreads();
    apply_update(sP+PEW+576, sP+PEB+20, sRedA, 144, 4);
    pool_bwdv<8>(GB, I+IX4, Sh+HU4, GA);                                  __syncthreads();

    if (tid < 256) dgrad4<8>(GA, sP+PEW+432, GB, tid, 256);
    else           wgrad4_acc<8,false>(GA, sT+T_P3, sRedB, tid-256, 256);
    __syncthreads();
    apply_update(sP+PEW+432, sP+PEB+16, sRedB, 144, 4);
    pool_bwdv<16>(GB, I+IX3, Sh+HU3, GA);                                 __syncthreads();

    if (tid < 256) dgrad4<16>(GA, sP+PEW+288, GB, tid, 256);
    else           wgrad4_acc<16,false>(GA, sT+T_P2, sRedA, tid-256, 256);
    __syncthreads();
    apply_update(sP+PEW+288, sP+PEB+12, sRedA, 144, 4);
    pool_bwdv<32>(GB, I+IX2, Sh+HU2, GA);                                 __syncthreads();

    if (tid < 256) dgrad4<32>(GA, sP+PEW+144, GB, tid, 256);
    else           wgrad4_acc<32,false>(GA, sT+T_P1, sRedB, tid-256, 256);
    __syncthreads();
    apply_update(sP+PEW+144, sP+PEB+8, sRedB, 144, 4);
    pool_bwdv<64>(GB, I+IX1, Sh+HU1, GA);                                 __syncthreads();

    if (tid < 256) dgrad4<64>(GA, sP+PEW, GB, tid, 256);
    else           wgrad4_acc<64,false>(GA, sT+T_P0, sRedA, tid-256, 256);
    __syncthreads();
    apply_update(sP+PEW, sP+PEB+4, sRedA, 144, 4);
    pool_bwdv<128>(GB, I+IX0, Sh+HU0, GA);                                __syncthreads();

    wgradfirst_acc<128>(GA, x, sRedB, tid, NT);
    __syncthreads();
    apply_update(sP+PW0, sP+PEB, sRedB, 36, 4);
    __syncthreads();   // W0 update must be visible to fwd2's conv0pool

    // ===== forward #2 with updated per-sample params =====
    forward_pass<false>(x, sP, sT, Sh, gQ4, I, out + (size_t)s * 16384);
}

extern "C" void kernel_launch(void* const* d_in, const int* in_sizes, int n_in,
                              void* d_out, int out_size)
{
    (void)in_sizes; (void)n_in; (void)out_size;
    cudaFuncSetAttribute(maml_kernel, cudaFuncAttributeMaxDynamicSharedMemorySize, SMEM_BYTES);
    maml_kernel<<<128, NT, SMEM_BYTES>>>(
        (const float*)d_in[0],  (const float*)d_in[1],  (const float*)d_in[2],
        (const float*)d_in[3],  (const float*)d_in[4],  (const float*)d_in[5],
        (const float*)d_in[6],  (const float*)d_in[7],  (const float*)d_in[8],
        (const float*)d_in[9],  (const float*)d_in[10], (const float*)d_in[11],
        (float*)d_out);
}